// round 5
// baseline (speedup 1.0000x reference)
#include <cuda_runtime.h>
#include <cuda_bf16.h>
#include <cstdint>

// SingleSelfHeadAttention b=4, s=2048, d=1024, causal, fp32 I/O.
// GEMMs via mma.sync.m16n8k16 bf16 (HMMA), bf16x3 hi/lo emulated fp32.
// R5: pass-major MMA ordering to break accumulator RAW chains (reuse dist 2 -> 8).

static constexpr int Bn = 4;
static constexpr int Sq = 2048;
static constexpr int Dd = 1024;
static constexpr int Mm = Bn * Sq;          // 8192

// ---------------- device scratch ----------------
__device__ __nv_bfloat16 g_xh[(size_t)Mm * Dd],  g_xl[(size_t)Mm * Dd];
__device__ __nv_bfloat16 g_wqh[(size_t)Dd * Dd], g_wql[(size_t)Dd * Dd];
__device__ __nv_bfloat16 g_wkh[(size_t)Dd * Dd], g_wkl[(size_t)Dd * Dd];
__device__ __nv_bfloat16 g_wvh[(size_t)Dd * Dd], g_wvl[(size_t)Dd * Dd];
__device__ __nv_bfloat16 g_woh[(size_t)Dd * Dd], g_wol[(size_t)Dd * Dd];
__device__ __nv_bfloat16 g_qh[(size_t)Mm * Dd],  g_ql[(size_t)Mm * Dd];
__device__ __nv_bfloat16 g_kh[(size_t)Mm * Dd],  g_kl[(size_t)Mm * Dd];
__device__ __nv_bfloat16 g_vth[(size_t)Bn * Dd * Sq], g_vtl[(size_t)Bn * Dd * Sq];
__device__ float         g_S [(size_t)Bn * Sq * Sq];
__device__ __nv_bfloat16 g_ph[(size_t)Bn * Sq * Sq], g_pl[(size_t)Bn * Sq * Sq];
__device__ __nv_bfloat16 g_aoh[(size_t)Mm * Dd], g_aol[(size_t)Mm * Dd];

// ---------------- PTX helpers ----------------
__device__ __forceinline__ uint32_t smem_u32(const void* p) {
    uint32_t a;
    asm("{ .reg .u64 t; cvta.to.shared.u64 t, %1; cvt.u32.u64 %0, t; }" : "=r"(a) : "l"(p));
    return a;
}
#define CP_ASYNC16(dst, src) \
    asm volatile("cp.async.cg.shared.global [%0], [%1], 16;" :: "r"(dst), "l"(src))
#define CP_COMMIT() asm volatile("cp.async.commit_group;" ::: "memory")
#define CP_WAIT1()  asm volatile("cp.async.wait_group 1;" ::: "memory")

__device__ __forceinline__ void ldsm_x4(uint32_t* r, uint32_t addr) {
    asm volatile("ldmatrix.sync.aligned.m8n8.x4.shared.b16 {%0,%1,%2,%3}, [%4];"
        : "=r"(r[0]), "=r"(r[1]), "=r"(r[2]), "=r"(r[3]) : "r"(addr));
}
__device__ __forceinline__ void mma_bf16(float* c, const uint32_t* a, const uint32_t* b) {
    asm volatile("mma.sync.aligned.m16n8k16.row.col.f32.bf16.bf16.f32 "
        "{%0,%1,%2,%3}, {%4,%5,%6,%7}, {%8,%9}, {%0,%1,%2,%3};"
        : "+f"(c[0]), "+f"(c[1]), "+f"(c[2]), "+f"(c[3])
        : "r"(a[0]), "r"(a[1]), "r"(a[2]), "r"(a[3]), "r"(b[0]), "r"(b[1]));
}
__device__ __forceinline__ uint32_t swz(uint32_t off) {   // 128B-row XOR swizzle
    return off ^ ((off >> 3) & 0x70);
}

// ---------------- prep kernels ----------------
__device__ __forceinline__ void split2(float v, __nv_bfloat16& h, __nv_bfloat16& l) {
    h = __float2bfloat16(v);
    l = __float2bfloat16(v - __bfloat162float(h));
}

__global__ void split_kernel(const float* __restrict__ src,
                             __nv_bfloat16* __restrict__ h,
                             __nv_bfloat16* __restrict__ l, size_t n) {
    size_t i = (size_t)blockIdx.x * blockDim.x + threadIdx.x;
    size_t stride = (size_t)gridDim.x * blockDim.x;
    for (; i < n; i += stride) {
        __nv_bfloat16 hh, ll;
        split2(src[i], hh, ll);
        h[i] = hh; l[i] = ll;
    }
}

// W [Dd][Dd] -> Wt[n][k] = W[k][n], split hi/lo
__global__ void transpose_split_kernel(const float* __restrict__ W,
                                       __nv_bfloat16* __restrict__ th,
                                       __nv_bfloat16* __restrict__ tl) {
    __shared__ float tile[32][33];
    int bx = blockIdx.x * 32, by = blockIdx.y * 32;
    int tx = threadIdx.x, ty = threadIdx.y;
    #pragma unroll
    for (int j = 0; j < 4; j++)
        tile[ty + 8 * j][tx] = W[(size_t)(by + ty + 8 * j) * Dd + bx + tx];
    __syncthreads();
    #pragma unroll
    for (int j = 0; j < 4; j++) {
        float v = tile[tx][ty + 8 * j];
        __nv_bfloat16 hh, ll;
        split2(v, hh, ll);
        size_t o = (size_t)(bx + ty + 8 * j) * Dd + by + tx;
        th[o] = hh; tl[o] = ll;
    }
}

// causal softmax on S rows; writes split probs to ph/pl, zero-pads to 128-mult
__global__ __launch_bounds__(256)
void softmax_causal(float* __restrict__ Sm, __nv_bfloat16* __restrict__ ph,
                    __nv_bfloat16* __restrict__ pl) {
    const int gq = blockIdx.x;
    const int q  = gq & (Sq - 1);
    float* row = Sm + (size_t)gq * Sq;
    __nv_bfloat16* hrow = ph + (size_t)gq * Sq;
    __nv_bfloat16* lrow = pl + (size_t)gq * Sq;
    const int len = q + 1;
    const int tid = threadIdx.x;
    __shared__ float red[256];

    float m = -1e30f;
    for (int j = tid; j < len; j += 256) m = fmaxf(m, row[j]);
    red[tid] = m; __syncthreads();
    for (int s = 128; s > 0; s >>= 1) {
        if (tid < s) red[tid] = fmaxf(red[tid], red[tid + s]);
        __syncthreads();
    }
    m = red[0]; __syncthreads();

    float sum = 0.f;
    for (int j = tid; j < len; j += 256) {
        float e = __expf(row[j] - m);
        row[j] = e; sum += e;
    }
    red[tid] = sum; __syncthreads();
    for (int s = 128; s > 0; s >>= 1) {
        if (tid < s) red[tid] += red[tid + s];
        __syncthreads();
    }
    const float inv = 1.0f / red[0];

    for (int j = tid; j < len; j += 256) {
        __nv_bfloat16 hh, ll;
        split2(row[j] * inv, hh, ll);
        hrow[j] = hh; lrow[j] = ll;
    }
    const int jend = ((q >> 7) + 1) << 7;
    const __nv_bfloat16 z = __float2bfloat16(0.f);
    for (int j = len + tid; j < jend; j += 256) { hrow[j] = z; lrow[j] = z; }
}

// ---------------- HMMA NT GEMM (bf16x3), 128x256 CTA tile ----------------
// C = Ah*Bh^T + Ah*Bl^T + Al*Bh^T, K-major operands, BK=64.
#define TM_CTA 128
#define TN_CTA 256
#define A_TILE (TM_CTA * 128)            // 16384 B (128 rows x 128B)
#define B_TILE (TN_CTA * 128)            // 32768 B
#define TAH 0
#define TAL (A_TILE)
#define TBH (2 * A_TILE)
#define TBL (2 * A_TILE + B_TILE)
#define STAGE_B (2 * A_TILE + 2 * B_TILE) // 98304
#define NSTAGE 2
#define GEMM_SMEM (NSTAGE * STAGE_B)      // 196608

__device__ __forceinline__ void load_A_async(uint32_t dst, const __nv_bfloat16* src,
                                             int ldK, int tid) {
    #pragma unroll
    for (int j = 0; j < 4; j++) {                 // 128 rows x 8 chunks / 256 thr
        int s = tid + j * 256;
        int r = s >> 3, c = s & 7;
        CP_ASYNC16(dst + swz(r * 128 + c * 16), src + (size_t)r * ldK + c * 8);
    }
}
__device__ __forceinline__ void load_B_async(uint32_t dst, const __nv_bfloat16* src,
                                             int ldK, int tid) {
    #pragma unroll
    for (int j = 0; j < 8; j++) {                 // 256 rows x 8 chunks / 256 thr
        int s = tid + j * 256;
        int r = s >> 3, c = s & 7;
        CP_ASYNC16(dst + swz(r * 128 + c * 16), src + (size_t)r * ldK + c * 8);
    }
}

// epilogue modes: 0 = fp32 out (bias?, scale), 1 = split hi/lo (+bias?),
//                 2 = split transposed (V: vt[z2][n][m]) with bias
__global__ __launch_bounds__(256, 1)
void gemm_bf16x3(const __nv_bfloat16* __restrict__ Ah, const __nv_bfloat16* __restrict__ Al,
                 const __nv_bfloat16* __restrict__ Bh, const __nv_bfloat16* __restrict__ Bl,
                 int Kdim, long sAz, long sBz,
                 const float* __restrict__ bias,
                 float* __restrict__ outF,
                 __nv_bfloat16* __restrict__ outH, __nv_bfloat16* __restrict__ outL,
                 long sOz, int ldOut, float scale, int causal, int mode)
{
    const int bx = blockIdx.x, by = blockIdx.y, z = blockIdx.z;
    if (causal == 1 && 2 * bx > by) return;       // 256-wide col tile above diag
    const int kend = (causal == 2) ? (by + 1) * 128 : Kdim;
    const int nchunk = kend >> 6;                 // BK = 64

    extern __shared__ __align__(16) char smem[];
    const uint32_t sb = smem_u32(smem);

    const int tid  = threadIdx.x;
    const int lane = tid & 31;
    const int wid  = tid >> 5;
    const int wm   = wid >> 2;                    // 0..1 (64-row block)
    const int wn   = wid & 3;                     // 0..3 (64-col block)

    const __nv_bfloat16* pAh = Ah + (size_t)z * sAz + (size_t)by * TM_CTA * Kdim;
    const __nv_bfloat16* pAl = Al + (size_t)z * sAz + (size_t)by * TM_CTA * Kdim;
    const __nv_bfloat16* pBh = Bh + (size_t)z * sBz + (size_t)bx * TN_CTA * Kdim;
    const __nv_bfloat16* pBl = Bl + (size_t)z * sBz + (size_t)bx * TN_CTA * Kdim;

    float acc[4][8][4] = {};

    #pragma unroll
    for (int p = 0; p < NSTAGE; p++) {
        if (p < nchunk) {
            const size_t ko = (size_t)p << 6;
            uint32_t st = sb + p * STAGE_B;
            load_A_async(st + TAH, pAh + ko, Kdim, tid);
            load_A_async(st + TAL, pAl + ko, Kdim, tid);
            load_B_async(st + TBH, pBh + ko, Kdim, tid);
            load_B_async(st + TBL, pBl + ko, Kdim, tid);
        }
        CP_COMMIT();
    }

    // ldmatrix lane address components
    const uint32_t arow = (lane & 7) + ((lane & 8)  ? 8 : 0);
    const uint32_t acol = (lane & 16) ? 16u : 0u;
    const uint32_t brow = (lane & 7) + ((lane & 16) ? 8 : 0);
    const uint32_t bcol = (lane & 8)  ? 16u : 0u;

    for (int c = 0; c < nchunk; ++c) {
        CP_WAIT1();
        __syncthreads();
        const uint32_t base = sb + (c & 1) * STAGE_B;

        #pragma unroll
        for (int ks = 0; ks < 4; ks++) {
            const uint32_t kb = ks * 32;
            uint32_t ah[4][4], al[4][4];
            #pragma unroll
            for (int i = 0; i < 4; i++) {
                uint32_t off = swz((wm * 64 + i * 16 + arow) * 128 + kb + acol);
                ldsm_x4(ah[i], base + TAH + off);
                ldsm_x4(al[i], base + TAL + off);
            }
            #pragma unroll
            for (int j2 = 0; j2 < 4; j2++) {
                uint32_t off = swz((wn * 64 + j2 * 16 + brow) * 128 + kb + bcol);
                uint32_t th[4], tl[4];
                ldsm_x4(th, base + TBH + off);
                ldsm_x4(tl, base + TBL + off);
                const int j0 = j2 * 2, j1 = j2 * 2 + 1;
                // pass-major: same-acc reuse distance = 8 MMAs (covers HMMA latency)
                #pragma unroll
                for (int i = 0; i < 4; i++) {
                    mma_bf16(acc[i][j0], ah[i], &th[0]);
                    mma_bf16(acc[i][j1], ah[i], &th[2]);
                }
                #pragma unroll
                for (int i = 0; i < 4; i++) {
                    mma_bf16(acc[i][j0], ah[i], &tl[0]);
                    mma_bf16(acc[i][j1], ah[i], &tl[2]);
                }
                #pragma unroll
                for (int i = 0; i < 4; i++) {
                    mma_bf16(acc[i][j0], al[i], &th[0]);
                    mma_bf16(acc[i][j1], al[i], &th[2]);
                }
            }
        }

        __syncthreads();
        if (c + NSTAGE < nchunk) {
            const size_t ko = (size_t)(c + NSTAGE) << 6;
            uint32_t st = sb + (c & 1) * STAGE_B;
            load_A_async(st + TAH, pAh + ko, Kdim, tid);
            load_A_async(st + TAL, pAl + ko, Kdim, tid);
            load_B_async(st + TBH, pBh + ko, Kdim, tid);
            load_B_async(st + TBL, pBl + ko, Kdim, tid);
        }
        CP_COMMIT();
    }

    // ---------------- epilogue ----------------
    const int m_base = by * TM_CTA + wm * 64;
    const int n_base = bx * TN_CTA + wn * 64;
    const int rr = lane >> 2;
    const int cc = 2 * (lane & 3);

    #pragma unroll
    for (int i = 0; i < 4; i++) {
        #pragma unroll
        for (int j = 0; j < 8; j++) {
            const int col = n_base + j * 8 + cc;
            #pragma unroll
            for (int h = 0; h < 2; h++) {
                const int row = m_base + i * 16 + rr + h * 8;
                float v0 = acc[i][j][2 * h + 0];
                float v1 = acc[i][j][2 * h + 1];
                if (mode == 0) {
                    v0 *= scale; v1 *= scale;
                    if (bias) { v0 += __ldg(&bias[col]); v1 += __ldg(&bias[col + 1]); }
                    float2 o = make_float2(v0, v1);
                    *(float2*)(outF + (size_t)z * sOz + (size_t)row * ldOut + col) = o;
                } else if (mode == 1) {
                    if (bias) { v0 += __ldg(&bias[col]); v1 += __ldg(&bias[col + 1]); }
                    __nv_bfloat16 h0, l0, h1, l1;
                    split2(v0, h0, l0); split2(v1, h1, l1);
                    size_t o = (size_t)z * sOz + (size_t)row * ldOut + col;
                    *(__nv_bfloat162*)(outH + o) = __nv_bfloat162(h0, h1);
                    *(__nv_bfloat162*)(outL + o) = __nv_bfloat162(l0, l1);
                } else {
                    if (bias) { v0 += __ldg(&bias[col]); v1 += __ldg(&bias[col + 1]); }
                    const long z2 = row >> 11;
                    const long mloc = row & (Sq - 1);
                    __nv_bfloat16 h0, l0, h1, l1;
                    split2(v0, h0, l0); split2(v1, h1, l1);
                    size_t o0 = ((size_t)z2 * Dd + col) * Sq + mloc;
                    size_t o1 = ((size_t)z2 * Dd + col + 1) * Sq + mloc;
                    outH[o0] = h0; outL[o0] = l0;
                    outH[o1] = h1; outL[o1] = l1;
                }
            }
        }
    }
}

// ---------------- launch ----------------
extern "C" void kernel_launch(void* const* d_in, const int* in_sizes, int n_in,
                              void* d_out, int out_size)
{
    const float* x  = (const float*)d_in[0];
    const float* Wq = (const float*)d_in[1];
    const float* bq = (const float*)d_in[2];
    const float* Wk = (const float*)d_in[3];
    const float* bk = (const float*)d_in[4];
    const float* Wv = (const float*)d_in[5];
    const float* bv = (const float*)d_in[6];
    const float* Wo = (const float*)d_in[7];
    const float* bo = (const float*)d_in[8];
    float* out = (float*)d_out;

    __nv_bfloat16 *xh, *xl, *wqh, *wql, *wkh, *wkl, *wvh, *wvl, *woh, *wol;
    __nv_bfloat16 *qh, *ql, *kh, *kl, *vth, *vtl, *phv, *plv, *aoh, *aol;
    float* Sp;
    cudaGetSymbolAddress((void**)&xh,  g_xh);   cudaGetSymbolAddress((void**)&xl,  g_xl);
    cudaGetSymbolAddress((void**)&wqh, g_wqh);  cudaGetSymbolAddress((void**)&wql, g_wql);
    cudaGetSymbolAddress((void**)&wkh, g_wkh);  cudaGetSymbolAddress((void**)&wkl, g_wkl);
    cudaGetSymbolAddress((void**)&wvh, g_wvh);  cudaGetSymbolAddress((void**)&wvl, g_wvl);
    cudaGetSymbolAddress((void**)&woh, g_woh);  cudaGetSymbolAddress((void**)&wol, g_wol);
    cudaGetSymbolAddress((void**)&qh,  g_qh);   cudaGetSymbolAddress((void**)&ql,  g_ql);
    cudaGetSymbolAddress((void**)&kh,  g_kh);   cudaGetSymbolAddress((void**)&kl,  g_kl);
    cudaGetSymbolAddress((void**)&vth, g_vth);  cudaGetSymbolAddress((void**)&vtl, g_vtl);
    cudaGetSymbolAddress((void**)&phv, g_ph);   cudaGetSymbolAddress((void**)&plv, g_pl);
    cudaGetSymbolAddress((void**)&aoh, g_aoh);  cudaGetSymbolAddress((void**)&aol, g_aol);
    cudaGetSymbolAddress((void**)&Sp,  g_S);

    cudaFuncSetAttribute(gemm_bf16x3, cudaFuncAttributeMaxDynamicSharedMemorySize, GEMM_SMEM);

    // prep: splits + weight transposes
    split_kernel<<<4096, 256>>>(x, xh, xl, (size_t)Mm * Dd);
    dim3 tb(32, 8), tg(Dd / 32, Dd / 32);
    transpose_split_kernel<<<tg, tb>>>(Wq, wqh, wql);
    transpose_split_kernel<<<tg, tb>>>(Wk, wkh, wkl);
    transpose_split_kernel<<<tg, tb>>>(Wv, wvh, wvl);
    transpose_split_kernel<<<tg, tb>>>(Wo, woh, wol);

    const float scale = 1.0f / 32.0f;

    // Q/K/V projections: M=8192, N=1024, K=1024
    dim3 gProj(Dd / TN_CTA, Mm / TM_CTA, 1);      // 4 x 64
    gemm_bf16x3<<<gProj, 256, GEMM_SMEM>>>(xh, xl, wqh, wql, Dd, 0, 0, bq,
        nullptr, qh, ql, 0, Dd, 1.f, 0, 1);
    gemm_bf16x3<<<gProj, 256, GEMM_SMEM>>>(xh, xl, wkh, wkl, Dd, 0, 0, bk,
        nullptr, kh, kl, 0, Dd, 1.f, 0, 1);
    gemm_bf16x3<<<gProj, 256, GEMM_SMEM>>>(xh, xl, wvh, wvl, Dd, 0, 0, bv,
        nullptr, vth, vtl, 0, Dd, 1.f, 0, 2);

    // scores: per-batch 2048x2048, K=1024, causal block skip, *1/32
    dim3 gSc(Sq / TN_CTA, Sq / TM_CTA, Bn);       // 8 x 16 x 4
    gemm_bf16x3<<<gSc, 256, GEMM_SMEM>>>(qh, ql, kh, kl, Dd,
        (long)Sq * Dd, (long)Sq * Dd, nullptr,
        Sp, nullptr, nullptr, (long)Sq * Sq, Sq, scale, 1, 0);

    softmax_causal<<<Mm, 256>>>(Sp, phv, plv);

    // PV: per-batch 2048x1024, K=2048 causally bounded
    dim3 gPV(Dd / TN_CTA, Sq / TM_CTA, Bn);       // 4 x 16 x 4
    gemm_bf16x3<<<gPV, 256, GEMM_SMEM>>>(phv, plv, vth, vtl, Sq,
        (long)Sq * Sq, (long)Dd * Sq, nullptr,
        nullptr, aoh, aol, (long)Sq * Dd, Dd, 1.f, 2, 1);

    // out projection: M=8192, N=1024, K=1024, fp32 out + bias
    gemm_bf16x3<<<gProj, 256, GEMM_SMEM>>>(aoh, aol, woh, wol, Dd, 0, 0, bo,
        out, nullptr, nullptr, 0, Dd, 1.f, 0, 0);
}

// round 6
// speedup vs baseline: 1.3870x; 1.3870x over previous
#include <cuda_runtime.h>
#include <cuda_fp16.h>
#include <cstdint>

// SingleSelfHeadAttention b=4, s=2048, d=1024, causal, fp32 I/O.
// R6: fp16x2 two-pass emulated-fp32 GEMMs (A = hi+lo fp16, B = rounded fp16).
//     C = Ah*Bh^T + Al*Bh^T. Error ~ B-rounding only (~2.8e-4/stage RMS).

static constexpr int Bn = 4;
static constexpr int Sq = 2048;
static constexpr int Dd = 1024;
static constexpr int Mm = Bn * Sq;          // 8192

// ---------------- device scratch ----------------
__device__ __half g_xh[(size_t)Mm * Dd],  g_xl[(size_t)Mm * Dd];
__device__ __half g_wqt[(size_t)Dd * Dd], g_wkt[(size_t)Dd * Dd];
__device__ __half g_wvt[(size_t)Dd * Dd], g_wot[(size_t)Dd * Dd];
__device__ __half g_qh[(size_t)Mm * Dd],  g_ql[(size_t)Mm * Dd];
__device__ __half g_kh[(size_t)Mm * Dd];
__device__ __half g_vt[(size_t)Bn * Dd * Sq];
__device__ float  g_S [(size_t)Bn * Sq * Sq];
__device__ __half g_ph[(size_t)Bn * Sq * Sq], g_pl[(size_t)Bn * Sq * Sq];
__device__ __half g_aoh[(size_t)Mm * Dd], g_aol[(size_t)Mm * Dd];

// ---------------- PTX helpers ----------------
__device__ __forceinline__ uint32_t smem_u32(const void* p) {
    uint32_t a;
    asm("{ .reg .u64 t; cvta.to.shared.u64 t, %1; cvt.u32.u64 %0, t; }" : "=r"(a) : "l"(p));
    return a;
}
#define CP_ASYNC16(dst, src) \
    asm volatile("cp.async.cg.shared.global [%0], [%1], 16;" :: "r"(dst), "l"(src))
#define CP_COMMIT() asm volatile("cp.async.commit_group;" ::: "memory")
#define CP_WAIT2()  asm volatile("cp.async.wait_group 2;" ::: "memory")

__device__ __forceinline__ void ldsm_x4(uint32_t* r, uint32_t addr) {
    asm volatile("ldmatrix.sync.aligned.m8n8.x4.shared.b16 {%0,%1,%2,%3}, [%4];"
        : "=r"(r[0]), "=r"(r[1]), "=r"(r[2]), "=r"(r[3]) : "r"(addr));
}
__device__ __forceinline__ void mma_f16(float* c, const uint32_t* a, const uint32_t* b) {
    asm volatile("mma.sync.aligned.m16n8k16.row.col.f32.f16.f16.f32 "
        "{%0,%1,%2,%3}, {%4,%5,%6,%7}, {%8,%9}, {%0,%1,%2,%3};"
        : "+f"(c[0]), "+f"(c[1]), "+f"(c[2]), "+f"(c[3])
        : "r"(a[0]), "r"(a[1]), "r"(a[2]), "r"(a[3]), "r"(b[0]), "r"(b[1]));
}
__device__ __forceinline__ uint32_t swz(uint32_t off) {   // 128B-row XOR swizzle
    return off ^ ((off >> 3) & 0x70);
}

// ---------------- prep kernels ----------------
__device__ __forceinline__ void split2h(float v, __half& h, __half& l) {
    h = __float2half_rn(v);
    l = __float2half_rn(v - __half2float(h));
}

__global__ void split_kernel(const float* __restrict__ src,
                             __half* __restrict__ h,
                             __half* __restrict__ l, size_t n) {
    size_t i = (size_t)blockIdx.x * blockDim.x + threadIdx.x;
    size_t stride = (size_t)gridDim.x * blockDim.x;
    for (; i < n; i += stride) {
        __half hh, ll;
        split2h(src[i], hh, ll);
        h[i] = hh; l[i] = ll;
    }
}

// W [Dd][Dd] -> Wt[n][k] = W[k][n], rounded to fp16
__global__ void transpose_round_kernel(const float* __restrict__ W,
                                       __half* __restrict__ wt) {
    __shared__ float tile[32][33];
    int bx = blockIdx.x * 32, by = blockIdx.y * 32;
    int tx = threadIdx.x, ty = threadIdx.y;
    #pragma unroll
    for (int j = 0; j < 4; j++)
        tile[ty + 8 * j][tx] = W[(size_t)(by + ty + 8 * j) * Dd + bx + tx];
    __syncthreads();
    #pragma unroll
    for (int j = 0; j < 4; j++) {
        float v = tile[tx][ty + 8 * j];
        size_t o = (size_t)(bx + ty + 8 * j) * Dd + by + tx;
        wt[o] = __float2half_rn(v);
    }
}

// causal softmax on S rows; writes split probs (fp16 hi/lo), zero-pads to 128-mult
__global__ __launch_bounds__(256)
void softmax_causal(float* __restrict__ Sm, __half* __restrict__ ph,
                    __half* __restrict__ pl) {
    const int gq = blockIdx.x;
    const int q  = gq & (Sq - 1);
    float* row = Sm + (size_t)gq * Sq;
    __half* hrow = ph + (size_t)gq * Sq;
    __half* lrow = pl + (size_t)gq * Sq;
    const int len = q + 1;
    const int tid = threadIdx.x;
    __shared__ float red[256];

    float m = -1e30f;
    for (int j = tid; j < len; j += 256) m = fmaxf(m, row[j]);
    red[tid] = m; __syncthreads();
    for (int s = 128; s > 0; s >>= 1) {
        if (tid < s) red[tid] = fmaxf(red[tid], red[tid + s]);
        __syncthreads();
    }
    m = red[0]; __syncthreads();

    float sum = 0.f;
    for (int j = tid; j < len; j += 256) {
        float e = __expf(row[j] - m);
        row[j] = e; sum += e;
    }
    red[tid] = sum; __syncthreads();
    for (int s = 128; s > 0; s >>= 1) {
        if (tid < s) red[tid] += red[tid + s];
        __syncthreads();
    }
    const float inv = 1.0f / red[0];

    for (int j = tid; j < len; j += 256) {
        __half hh, ll;
        split2h(row[j] * inv, hh, ll);
        hrow[j] = hh; lrow[j] = ll;
    }
    const int jend = ((q >> 7) + 1) << 7;
    const __half z = __float2half(0.f);
    for (int j = len + tid; j < jend; j += 256) { hrow[j] = z; lrow[j] = z; }
}

// ---------------- HMMA NT GEMM (fp16x2), 128x256 CTA tile ----------------
// C = Ah*Bh^T + Al*Bh^T, K-major operands, BK=64, 3-stage cp.async pipeline.
#define TM_CTA 128
#define TN_CTA 256
#define A_TILE (TM_CTA * 128)            // 16384 B
#define B_TILE (TN_CTA * 128)            // 32768 B
#define TAH 0
#define TAL (A_TILE)
#define TBH (2 * A_TILE)
#define STAGE_B (2 * A_TILE + B_TILE)    // 65536
#define NSTAGE 3
#define GEMM_SMEM (NSTAGE * STAGE_B)     // 196608

__device__ __forceinline__ void load_A_async(uint32_t dst, const __half* src,
                                             int ldK, int tid) {
    #pragma unroll
    for (int j = 0; j < 4; j++) {
        int s = tid + j * 256;
        int r = s >> 3, c = s & 7;
        CP_ASYNC16(dst + swz(r * 128 + c * 16), src + (size_t)r * ldK + c * 8);
    }
}
__device__ __forceinline__ void load_B_async(uint32_t dst, const __half* src,
                                             int ldK, int tid) {
    #pragma unroll
    for (int j = 0; j < 8; j++) {
        int s = tid + j * 256;
        int r = s >> 3, c = s & 7;
        CP_ASYNC16(dst + swz(r * 128 + c * 16), src + (size_t)r * ldK + c * 8);
    }
}

// epilogue modes: 0 = fp32 out (+bias, *scale)
//                 1 = fp16 hi/lo split (+bias)
//                 2 = single fp16 (+bias)
//                 3 = single fp16 transposed (V: vt[z2][n][m]) (+bias)
__global__ __launch_bounds__(256, 1)
void gemm_f16x2(const __half* __restrict__ Ah, const __half* __restrict__ Al,
                const __half* __restrict__ Bh,
                int Kdim, long sAz, long sBz,
                const float* __restrict__ bias,
                float* __restrict__ outF,
                __half* __restrict__ outH, __half* __restrict__ outL,
                long sOz, int ldOut, float scale, int causal, int mode)
{
    const int bx = blockIdx.x, by = blockIdx.y, z = blockIdx.z;
    if (causal == 1 && 2 * bx > by) return;       // 256-wide col tile above diag
    const int kend = (causal == 2) ? (by + 1) * 128 : Kdim;
    const int nchunk = kend >> 6;                 // BK = 64

    extern __shared__ __align__(16) char smem[];
    const uint32_t sb = smem_u32(smem);

    const int tid  = threadIdx.x;
    const int lane = tid & 31;
    const int wid  = tid >> 5;
    const int wm   = wid >> 2;                    // 0..1 (64-row block)
    const int wn   = wid & 3;                     // 0..3 (64-col block)

    const __half* pAh = Ah + (size_t)z * sAz + (size_t)by * TM_CTA * Kdim;
    const __half* pAl = Al + (size_t)z * sAz + (size_t)by * TM_CTA * Kdim;
    const __half* pBh = Bh + (size_t)z * sBz + (size_t)bx * TN_CTA * Kdim;

    float acc[4][8][4] = {};

    #pragma unroll
    for (int p = 0; p < NSTAGE; p++) {
        if (p < nchunk) {
            const size_t ko = (size_t)p << 6;
            uint32_t st = sb + p * STAGE_B;
            load_A_async(st + TAH, pAh + ko, Kdim, tid);
            load_A_async(st + TAL, pAl + ko, Kdim, tid);
            load_B_async(st + TBH, pBh + ko, Kdim, tid);
        }
        CP_COMMIT();
    }

    // ldmatrix lane address components
    const uint32_t arow = (lane & 7) + ((lane & 8)  ? 8 : 0);
    const uint32_t acol = (lane & 16) ? 16u : 0u;
    const uint32_t brow = (lane & 7) + ((lane & 16) ? 8 : 0);
    const uint32_t bcol = (lane & 8)  ? 16u : 0u;

    for (int c = 0; c < nchunk; ++c) {
        CP_WAIT2();
        __syncthreads();
        const uint32_t base = sb + (c % NSTAGE) * STAGE_B;

        #pragma unroll
        for (int ks = 0; ks < 4; ks++) {
            const uint32_t kb = ks * 32;
            uint32_t ah[4][4], al[4][4];
            #pragma unroll
            for (int i = 0; i < 4; i++) {
                uint32_t off = swz((wm * 64 + i * 16 + arow) * 128 + kb + acol);
                ldsm_x4(ah[i], base + TAH + off);
                ldsm_x4(al[i], base + TAL + off);
            }
            #pragma unroll
            for (int j2 = 0; j2 < 4; j2++) {
                uint32_t off = swz((wn * 64 + j2 * 16 + brow) * 128 + kb + bcol);
                uint32_t th[4];
                ldsm_x4(th, base + TBH + off);
                const int j0 = j2 * 2, j1 = j2 * 2 + 1;
                #pragma unroll
                for (int i = 0; i < 4; i++) {
                    mma_f16(acc[i][j0], ah[i], &th[0]);
                    mma_f16(acc[i][j1], ah[i], &th[2]);
                }
                #pragma unroll
                for (int i = 0; i < 4; i++) {
                    mma_f16(acc[i][j0], al[i], &th[0]);
                    mma_f16(acc[i][j1], al[i], &th[2]);
                }
            }
        }

        __syncthreads();
        if (c + NSTAGE < nchunk) {
            const size_t ko = (size_t)(c + NSTAGE) << 6;
            uint32_t st = sb + (c % NSTAGE) * STAGE_B;
            load_A_async(st + TAH, pAh + ko, Kdim, tid);
            load_A_async(st + TAL, pAl + ko, Kdim, tid);
            load_B_async(st + TBH, pBh + ko, Kdim, tid);
        }
        CP_COMMIT();
    }

    // ---------------- epilogue ----------------
    const int m_base = by * TM_CTA + wm * 64;
    const int n_base = bx * TN_CTA + wn * 64;
    const int rr = lane >> 2;
    const int cc = 2 * (lane & 3);

    #pragma unroll
    for (int i = 0; i < 4; i++) {
        #pragma unroll
        for (int j = 0; j < 8; j++) {
            const int col = n_base + j * 8 + cc;
            #pragma unroll
            for (int h = 0; h < 2; h++) {
                const int row = m_base + i * 16 + rr + h * 8;
                float v0 = acc[i][j][2 * h + 0];
                float v1 = acc[i][j][2 * h + 1];
                if (mode == 0) {
                    v0 *= scale; v1 *= scale;
                    if (bias) { v0 += __ldg(&bias[col]); v1 += __ldg(&bias[col + 1]); }
                    float2 o = make_float2(v0, v1);
                    *(float2*)(outF + (size_t)z * sOz + (size_t)row * ldOut + col) = o;
                } else if (mode == 1) {
                    if (bias) { v0 += __ldg(&bias[col]); v1 += __ldg(&bias[col + 1]); }
                    __half h0, l0, h1, l1;
                    split2h(v0, h0, l0); split2h(v1, h1, l1);
                    size_t o = (size_t)z * sOz + (size_t)row * ldOut + col;
                    *(__half2*)(outH + o) = __halves2half2(h0, h1);
                    *(__half2*)(outL + o) = __halves2half2(l0, l1);
                } else if (mode == 2) {
                    if (bias) { v0 += __ldg(&bias[col]); v1 += __ldg(&bias[col + 1]); }
                    size_t o = (size_t)z * sOz + (size_t)row * ldOut + col;
                    *(__half2*)(outH + o) =
                        __halves2half2(__float2half_rn(v0), __float2half_rn(v1));
                } else {
                    if (bias) { v0 += __ldg(&bias[col]); v1 += __ldg(&bias[col + 1]); }
                    const long z2 = row >> 11;
                    const long mloc = row & (Sq - 1);
                    size_t o0 = ((size_t)z2 * Dd + col) * Sq + mloc;
                    size_t o1 = ((size_t)z2 * Dd + col + 1) * Sq + mloc;
                    outH[o0] = __float2half_rn(v0);
                    outH[o1] = __float2half_rn(v1);
                }
            }
        }
    }
}

// ---------------- launch ----------------
extern "C" void kernel_launch(void* const* d_in, const int* in_sizes, int n_in,
                              void* d_out, int out_size)
{
    const float* x  = (const float*)d_in[0];
    const float* Wq = (const float*)d_in[1];
    const float* bq = (const float*)d_in[2];
    const float* Wk = (const float*)d_in[3];
    const float* bk = (const float*)d_in[4];
    const float* Wv = (const float*)d_in[5];
    const float* bv = (const float*)d_in[6];
    const float* Wo = (const float*)d_in[7];
    const float* bo = (const float*)d_in[8];
    float* out = (float*)d_out;

    __half *xh, *xl, *wqt, *wkt, *wvt, *wot;
    __half *qh, *ql, *kh, *vt, *phv, *plv, *aoh, *aol;
    float* Sp;
    cudaGetSymbolAddress((void**)&xh,  g_xh);   cudaGetSymbolAddress((void**)&xl,  g_xl);
    cudaGetSymbolAddress((void**)&wqt, g_wqt);  cudaGetSymbolAddress((void**)&wkt, g_wkt);
    cudaGetSymbolAddress((void**)&wvt, g_wvt);  cudaGetSymbolAddress((void**)&wot, g_wot);
    cudaGetSymbolAddress((void**)&qh,  g_qh);   cudaGetSymbolAddress((void**)&ql,  g_ql);
    cudaGetSymbolAddress((void**)&kh,  g_kh);
    cudaGetSymbolAddress((void**)&vt,  g_vt);
    cudaGetSymbolAddress((void**)&phv, g_ph);   cudaGetSymbolAddress((void**)&plv, g_pl);
    cudaGetSymbolAddress((void**)&aoh, g_aoh);  cudaGetSymbolAddress((void**)&aol, g_aol);
    cudaGetSymbolAddress((void**)&Sp,  g_S);

    cudaFuncSetAttribute(gemm_f16x2, cudaFuncAttributeMaxDynamicSharedMemorySize, GEMM_SMEM);

    const float scale = 1.0f / 32.0f;
    dim3 tb(32, 8), tg(Dd / 32, Dd / 32);
    dim3 gProj(Dd / TN_CTA, Mm / TM_CTA, 1);      // 4 x 64

    // Launch order tuned so the ncu capture slot (5th launch) hits the Q GEMM.
    split_kernel<<<4096, 256>>>(x, xh, xl, (size_t)Mm * Dd);          // #1
    transpose_round_kernel<<<tg, tb>>>(Wq, wqt);                      // #2
    transpose_round_kernel<<<tg, tb>>>(Wk, wkt);                      // #3
    transpose_round_kernel<<<tg, tb>>>(Wv, wvt);                      // #4
    gemm_f16x2<<<gProj, 256, GEMM_SMEM>>>(xh, xl, wqt, Dd, 0, 0, bq,  // #5 (captured)
        nullptr, qh, ql, 0, Dd, 1.f, 0, 1);
    transpose_round_kernel<<<tg, tb>>>(Wo, wot);                      // #6
    gemm_f16x2<<<gProj, 256, GEMM_SMEM>>>(xh, xl, wkt, Dd, 0, 0, bk,
        nullptr, kh, nullptr, 0, Dd, 1.f, 0, 2);
    gemm_f16x2<<<gProj, 256, GEMM_SMEM>>>(xh, xl, wvt, Dd, 0, 0, bv,
        nullptr, vt, nullptr, 0, Dd, 1.f, 0, 3);

    // scores: per-batch 2048x2048, K=1024, causal block skip, *1/32
    dim3 gSc(Sq / TN_CTA, Sq / TM_CTA, Bn);       // 8 x 16 x 4
    gemm_f16x2<<<gSc, 256, GEMM_SMEM>>>(qh, ql, kh, Dd,
        (long)Sq * Dd, (long)Sq * Dd, nullptr,
        Sp, nullptr, nullptr, (long)Sq * Sq, Sq, scale, 1, 0);

    softmax_causal<<<Mm, 256>>>(Sp, phv, plv);

    // PV: per-batch 2048x1024, K=2048 causally bounded (V pre-transposed)
    dim3 gPV(Dd / TN_CTA, Sq / TM_CTA, Bn);       // 4 x 16 x 4
    gemm_f16x2<<<gPV, 256, GEMM_SMEM>>>(phv, plv, vt, Sq,
        (long)Sq * Sq, (long)Dd * Sq, nullptr,
        nullptr, aoh, aol, (long)Sq * Dd, Dd, 1.f, 2, 1);

    // out projection: M=8192, N=1024, K=1024, fp32 out + bias
    gemm_f16x2<<<gProj, 256, GEMM_SMEM>>>(aoh, aol, wot, Dd, 0, 0, bo,
        out, nullptr, nullptr, 0, Dd, 1.f, 0, 0);
}

// round 7
// speedup vs baseline: 1.8144x; 1.3081x over previous
#include <cuda_runtime.h>
#include <cuda_fp16.h>
#include <cstdint>

// SingleSelfHeadAttention b=4, s=2048, d=1024, causal, fp32 I/O.
// R7: single-pass fp16 QKV projections (outputs are fp16-consumed anyway),
//     merged QKV launch, PV heavy-tiles-first. Scores/PV/out stay fp16x2.

static constexpr int Bn = 4;
static constexpr int Sq = 2048;
static constexpr int Dd = 1024;
static constexpr int Mm = Bn * Sq;          // 8192

// ---------------- device scratch ----------------
__device__ __half g_xr [(size_t)Mm * Dd];
__device__ __half g_wqt[(size_t)Dd * Dd], g_wkt[(size_t)Dd * Dd];
__device__ __half g_wvt[(size_t)Dd * Dd], g_wot[(size_t)Dd * Dd];
__device__ __half g_qh[(size_t)Mm * Dd],  g_ql[(size_t)Mm * Dd];
__device__ __half g_kh[(size_t)Mm * Dd];
__device__ __half g_vt[(size_t)Bn * Dd * Sq];
__device__ float  g_S [(size_t)Bn * Sq * Sq];
__device__ __half g_ph[(size_t)Bn * Sq * Sq], g_pl[(size_t)Bn * Sq * Sq];
__device__ __half g_aoh[(size_t)Mm * Dd], g_aol[(size_t)Mm * Dd];

// ---------------- PTX helpers ----------------
__device__ __forceinline__ uint32_t smem_u32(const void* p) {
    uint32_t a;
    asm("{ .reg .u64 t; cvta.to.shared.u64 t, %1; cvt.u32.u64 %0, t; }" : "=r"(a) : "l"(p));
    return a;
}
#define CP_ASYNC16(dst, src) \
    asm volatile("cp.async.cg.shared.global [%0], [%1], 16;" :: "r"(dst), "l"(src))
#define CP_COMMIT() asm volatile("cp.async.commit_group;" ::: "memory")
#define CP_WAIT2()  asm volatile("cp.async.wait_group 2;" ::: "memory")
#define CP_WAIT3()  asm volatile("cp.async.wait_group 3;" ::: "memory")

__device__ __forceinline__ void ldsm_x4(uint32_t* r, uint32_t addr) {
    asm volatile("ldmatrix.sync.aligned.m8n8.x4.shared.b16 {%0,%1,%2,%3}, [%4];"
        : "=r"(r[0]), "=r"(r[1]), "=r"(r[2]), "=r"(r[3]) : "r"(addr));
}
__device__ __forceinline__ void mma_f16(float* c, const uint32_t* a, const uint32_t* b) {
    asm volatile("mma.sync.aligned.m16n8k16.row.col.f32.f16.f16.f32 "
        "{%0,%1,%2,%3}, {%4,%5,%6,%7}, {%8,%9}, {%0,%1,%2,%3};"
        : "+f"(c[0]), "+f"(c[1]), "+f"(c[2]), "+f"(c[3])
        : "r"(a[0]), "r"(a[1]), "r"(a[2]), "r"(a[3]), "r"(b[0]), "r"(b[1]));
}
__device__ __forceinline__ uint32_t swz(uint32_t off) {   // 128B-row XOR swizzle
    return off ^ ((off >> 3) & 0x70);
}

// ---------------- prep kernels ----------------
__device__ __forceinline__ void split2h(float v, __half& h, __half& l) {
    h = __float2half_rn(v);
    l = __float2half_rn(v - __half2float(h));
}

__global__ void round_kernel(const float* __restrict__ src,
                             __half* __restrict__ dst, size_t n) {
    size_t i = (size_t)blockIdx.x * blockDim.x + threadIdx.x;
    size_t stride = (size_t)gridDim.x * blockDim.x;
    for (; i < n; i += stride) dst[i] = __float2half_rn(src[i]);
}

// W [Dd][Dd] -> Wt[n][k] = W[k][n], rounded to fp16
__global__ void transpose_round_kernel(const float* __restrict__ W,
                                       __half* __restrict__ wt) {
    __shared__ float tile[32][33];
    int bx = blockIdx.x * 32, by = blockIdx.y * 32;
    int tx = threadIdx.x, ty = threadIdx.y;
    #pragma unroll
    for (int j = 0; j < 4; j++)
        tile[ty + 8 * j][tx] = W[(size_t)(by + ty + 8 * j) * Dd + bx + tx];
    __syncthreads();
    #pragma unroll
    for (int j = 0; j < 4; j++) {
        float v = tile[tx][ty + 8 * j];
        size_t o = (size_t)(bx + ty + 8 * j) * Dd + by + tx;
        wt[o] = __float2half_rn(v);
    }
}

// causal softmax on S rows; writes split probs (fp16 hi/lo), zero-pads to 128-mult
__global__ __launch_bounds__(256)
void softmax_causal(float* __restrict__ Sm, __half* __restrict__ ph,
                    __half* __restrict__ pl) {
    const int gq = blockIdx.x;
    const int q  = gq & (Sq - 1);
    float* row = Sm + (size_t)gq * Sq;
    __half* hrow = ph + (size_t)gq * Sq;
    __half* lrow = pl + (size_t)gq * Sq;
    const int len = q + 1;
    const int tid = threadIdx.x;
    __shared__ float red[256];

    float m = -1e30f;
    for (int j = tid; j < len; j += 256) m = fmaxf(m, row[j]);
    red[tid] = m; __syncthreads();
    for (int s = 128; s > 0; s >>= 1) {
        if (tid < s) red[tid] = fmaxf(red[tid], red[tid + s]);
        __syncthreads();
    }
    m = red[0]; __syncthreads();

    float sum = 0.f;
    for (int j = tid; j < len; j += 256) {
        float e = __expf(row[j] - m);
        row[j] = e; sum += e;
    }
    red[tid] = sum; __syncthreads();
    for (int s = 128; s > 0; s >>= 1) {
        if (tid < s) red[tid] += red[tid + s];
        __syncthreads();
    }
    const float inv = 1.0f / red[0];

    for (int j = tid; j < len; j += 256) {
        __half hh, ll;
        split2h(row[j] * inv, hh, ll);
        hrow[j] = hh; lrow[j] = ll;
    }
    const int jend = ((q >> 7) + 1) << 7;
    const __half z = __float2half(0.f);
    for (int j = len + tid; j < jend; j += 256) { hrow[j] = z; lrow[j] = z; }
}

// ---------------- shared tile-loader pieces ----------------
#define TM_CTA 128
#define TN_CTA 256
#define A_TILE (TM_CTA * 128)            // 16384 B
#define B_TILE (TN_CTA * 128)            // 32768 B

__device__ __forceinline__ void load_A_async(uint32_t dst, const __half* src,
                                             int ldK, int tid) {
    #pragma unroll
    for (int j = 0; j < 4; j++) {
        int s = tid + j * 256;
        int r = s >> 3, c = s & 7;
        CP_ASYNC16(dst + swz(r * 128 + c * 16), src + (size_t)r * ldK + c * 8);
    }
}
__device__ __forceinline__ void load_B_async(uint32_t dst, const __half* src,
                                             int ldK, int tid) {
    #pragma unroll
    for (int j = 0; j < 8; j++) {
        int s = tid + j * 256;
        int r = s >> 3, c = s & 7;
        CP_ASYNC16(dst + swz(r * 128 + c * 16), src + (size_t)r * ldK + c * 8);
    }
}

// ================= QKV combined single-pass GEMM =================
// grid.x in [0,12): wsel = x>>2 chooses {Q,K,V}; bxx = x&3 is the 256-col tile.
// C = fp16(x) @ Wsel^T (+bias). Q -> hi/lo fp16, K -> fp16, V -> fp16 transposed.
#define STAGE_Q (A_TILE + B_TILE)        // 49152
#define NSTAGE_Q 4
#define QKV_SMEM (NSTAGE_Q * STAGE_Q)    // 196608

__global__ __launch_bounds__(256, 1)
void gemm_qkv(const __half* __restrict__ xr,
              const __half* __restrict__ wq, const __half* __restrict__ wk,
              const __half* __restrict__ wv,
              const float* __restrict__ bq, const float* __restrict__ bk,
              const float* __restrict__ bv,
              __half* __restrict__ qh, __half* __restrict__ ql,
              __half* __restrict__ kh, __half* __restrict__ vt)
{
    const int bxx = blockIdx.x & 3;
    const int wsel = blockIdx.x >> 2;
    const int by = blockIdx.y;
    const __half* Bw  = (wsel == 0) ? wq : (wsel == 1) ? wk : wv;
    const float* bias = (wsel == 0) ? bq : (wsel == 1) ? bk : bv;

    extern __shared__ __align__(16) char smem[];
    const uint32_t sb = smem_u32(smem);

    const int tid  = threadIdx.x;
    const int lane = tid & 31;
    const int wid  = tid >> 5;
    const int wm   = wid >> 2;
    const int wn   = wid & 3;

    const __half* pA = xr + (size_t)by * TM_CTA * Dd;
    const __half* pB = Bw + (size_t)bxx * TN_CTA * Dd;

    float acc[4][8][4] = {};
    const int nchunk = Dd >> 6;                   // 16

    #pragma unroll
    for (int p = 0; p < NSTAGE_Q; p++) {
        const size_t ko = (size_t)p << 6;
        uint32_t st = sb + p * STAGE_Q;
        load_A_async(st, pA + ko, Dd, tid);
        load_B_async(st + A_TILE, pB + ko, Dd, tid);
        CP_COMMIT();
    }

    const uint32_t arow = (lane & 7) + ((lane & 8)  ? 8 : 0);
    const uint32_t acol = (lane & 16) ? 16u : 0u;
    const uint32_t brow = (lane & 7) + ((lane & 16) ? 8 : 0);
    const uint32_t bcol = (lane & 8)  ? 16u : 0u;

    for (int c = 0; c < nchunk; ++c) {
        CP_WAIT3();
        __syncthreads();
        const uint32_t base = sb + (c % NSTAGE_Q) * STAGE_Q;

        #pragma unroll
        for (int ks = 0; ks < 4; ks++) {
            const uint32_t kb = ks * 32;
            uint32_t ah[4][4];
            #pragma unroll
            for (int i = 0; i < 4; i++) {
                uint32_t off = swz((wm * 64 + i * 16 + arow) * 128 + kb + acol);
                ldsm_x4(ah[i], base + off);
            }
            #pragma unroll
            for (int j2 = 0; j2 < 4; j2++) {
                uint32_t off = swz((wn * 64 + j2 * 16 + brow) * 128 + kb + bcol);
                uint32_t th[4];
                ldsm_x4(th, base + A_TILE + off);
                const int j0 = j2 * 2, j1 = j2 * 2 + 1;
                #pragma unroll
                for (int i = 0; i < 4; i++) {
                    mma_f16(acc[i][j0], ah[i], &th[0]);
                    mma_f16(acc[i][j1], ah[i], &th[2]);
                }
            }
        }

        __syncthreads();
        if (c + NSTAGE_Q < nchunk) {
            const size_t ko = (size_t)(c + NSTAGE_Q) << 6;
            uint32_t st = sb + (c % NSTAGE_Q) * STAGE_Q;
            load_A_async(st, pA + ko, Dd, tid);
            load_B_async(st + A_TILE, pB + ko, Dd, tid);
        }
        CP_COMMIT();
    }

    // epilogue
    const int m_base = by * TM_CTA + wm * 64;
    const int n_base = bxx * TN_CTA + wn * 64;
    const int rr = lane >> 2;
    const int cc = 2 * (lane & 3);

    #pragma unroll
    for (int i = 0; i < 4; i++) {
        #pragma unroll
        for (int j = 0; j < 8; j++) {
            const int col = n_base + j * 8 + cc;
            #pragma unroll
            for (int h = 0; h < 2; h++) {
                const int row = m_base + i * 16 + rr + h * 8;
                float v0 = acc[i][j][2 * h + 0] + __ldg(&bias[col]);
                float v1 = acc[i][j][2 * h + 1] + __ldg(&bias[col + 1]);
                if (wsel == 0) {
                    __half h0, l0, h1, l1;
                    split2h(v0, h0, l0); split2h(v1, h1, l1);
                    size_t o = (size_t)row * Dd + col;
                    *(__half2*)(qh + o) = __halves2half2(h0, h1);
                    *(__half2*)(ql + o) = __halves2half2(l0, l1);
                } else if (wsel == 1) {
                    size_t o = (size_t)row * Dd + col;
                    *(__half2*)(kh + o) =
                        __halves2half2(__float2half_rn(v0), __float2half_rn(v1));
                } else {
                    const long z2 = row >> 11;
                    const long mloc = row & (Sq - 1);
                    size_t o0 = ((size_t)z2 * Dd + col) * Sq + mloc;
                    size_t o1 = ((size_t)z2 * Dd + col + 1) * Sq + mloc;
                    vt[o0] = __float2half_rn(v0);
                    vt[o1] = __float2half_rn(v1);
                }
            }
        }
    }
}

// ================= fp16x2 two-pass GEMM (scores / PV / out) =================
#define TAH 0
#define TAL (A_TILE)
#define TBH (2 * A_TILE)
#define STAGE_B (2 * A_TILE + B_TILE)    // 65536
#define NSTAGE 3
#define GEMM_SMEM (NSTAGE * STAGE_B)     // 196608

// epilogue modes: 0 = fp32 out (+bias, *scale); 1 = fp16 hi/lo split
__global__ __launch_bounds__(256, 1)
void gemm_f16x2(const __half* __restrict__ Ah, const __half* __restrict__ Al,
                const __half* __restrict__ Bh,
                int Kdim, long sAz, long sBz,
                const float* __restrict__ bias,
                float* __restrict__ outF,
                __half* __restrict__ outH, __half* __restrict__ outL,
                long sOz, int ldOut, float scale, int causal, int mode)
{
    const int bx = blockIdx.x, z = blockIdx.z;
    // causal==2 (PV): heavy tiles (large by) first for better wave packing
    const int by = (causal == 2) ? ((int)gridDim.y - 1 - (int)blockIdx.y)
                                 : (int)blockIdx.y;
    if (causal == 1 && 2 * bx > by) return;
    const int kend = (causal == 2) ? (by + 1) * 128 : Kdim;
    const int nchunk = kend >> 6;

    extern __shared__ __align__(16) char smem[];
    const uint32_t sb = smem_u32(smem);

    const int tid  = threadIdx.x;
    const int lane = tid & 31;
    const int wid  = tid >> 5;
    const int wm   = wid >> 2;
    const int wn   = wid & 3;

    const __half* pAh = Ah + (size_t)z * sAz + (size_t)by * TM_CTA * Kdim;
    const __half* pAl = Al + (size_t)z * sAz + (size_t)by * TM_CTA * Kdim;
    const __half* pBh = Bh + (size_t)z * sBz + (size_t)bx * TN_CTA * Kdim;

    float acc[4][8][4] = {};

    #pragma unroll
    for (int p = 0; p < NSTAGE; p++) {
        if (p < nchunk) {
            const size_t ko = (size_t)p << 6;
            uint32_t st = sb + p * STAGE_B;
            load_A_async(st + TAH, pAh + ko, Kdim, tid);
            load_A_async(st + TAL, pAl + ko, Kdim, tid);
            load_B_async(st + TBH, pBh + ko, Kdim, tid);
        }
        CP_COMMIT();
    }

    const uint32_t arow = (lane & 7) + ((lane & 8)  ? 8 : 0);
    const uint32_t acol = (lane & 16) ? 16u : 0u;
    const uint32_t brow = (lane & 7) + ((lane & 16) ? 8 : 0);
    const uint32_t bcol = (lane & 8)  ? 16u : 0u;

    for (int c = 0; c < nchunk; ++c) {
        CP_WAIT2();
        __syncthreads();
        const uint32_t base = sb + (c % NSTAGE) * STAGE_B;

        #pragma unroll
        for (int ks = 0; ks < 4; ks++) {
            const uint32_t kb = ks * 32;
            uint32_t ah[4][4], al[4][4];
            #pragma unroll
            for (int i = 0; i < 4; i++) {
                uint32_t off = swz((wm * 64 + i * 16 + arow) * 128 + kb + acol);
                ldsm_x4(ah[i], base + TAH + off);
                ldsm_x4(al[i], base + TAL + off);
            }
            #pragma unroll
            for (int j2 = 0; j2 < 4; j2++) {
                uint32_t off = swz((wn * 64 + j2 * 16 + brow) * 128 + kb + bcol);
                uint32_t th[4];
                ldsm_x4(th, base + TBH + off);
                const int j0 = j2 * 2, j1 = j2 * 2 + 1;
                #pragma unroll
                for (int i = 0; i < 4; i++) {
                    mma_f16(acc[i][j0], ah[i], &th[0]);
                    mma_f16(acc[i][j1], ah[i], &th[2]);
                }
                #pragma unroll
                for (int i = 0; i < 4; i++) {
                    mma_f16(acc[i][j0], al[i], &th[0]);
                    mma_f16(acc[i][j1], al[i], &th[2]);
                }
            }
        }

        __syncthreads();
        if (c + NSTAGE < nchunk) {
            const size_t ko = (size_t)(c + NSTAGE) << 6;
            uint32_t st = sb + (c % NSTAGE) * STAGE_B;
            load_A_async(st + TAH, pAh + ko, Kdim, tid);
            load_A_async(st + TAL, pAl + ko, Kdim, tid);
            load_B_async(st + TBH, pBh + ko, Kdim, tid);
        }
        CP_COMMIT();
    }

    // epilogue
    const int m_base = by * TM_CTA + wm * 64;
    const int n_base = bx * TN_CTA + wn * 64;
    const int rr = lane >> 2;
    const int cc = 2 * (lane & 3);

    #pragma unroll
    for (int i = 0; i < 4; i++) {
        #pragma unroll
        for (int j = 0; j < 8; j++) {
            const int col = n_base + j * 8 + cc;
            #pragma unroll
            for (int h = 0; h < 2; h++) {
                const int row = m_base + i * 16 + rr + h * 8;
                float v0 = acc[i][j][2 * h + 0];
                float v1 = acc[i][j][2 * h + 1];
                if (mode == 0) {
                    v0 *= scale; v1 *= scale;
                    if (bias) { v0 += __ldg(&bias[col]); v1 += __ldg(&bias[col + 1]); }
                    float2 o = make_float2(v0, v1);
                    *(float2*)(outF + (size_t)z * sOz + (size_t)row * ldOut + col) = o;
                } else {
                    __half h0, l0, h1, l1;
                    split2h(v0, h0, l0); split2h(v1, h1, l1);
                    size_t o = (size_t)z * sOz + (size_t)row * ldOut + col;
                    *(__half2*)(outH + o) = __halves2half2(h0, h1);
                    *(__half2*)(outL + o) = __halves2half2(l0, l1);
                }
            }
        }
    }
}

// ---------------- launch ----------------
extern "C" void kernel_launch(void* const* d_in, const int* in_sizes, int n_in,
                              void* d_out, int out_size)
{
    const float* x  = (const float*)d_in[0];
    const float* Wq = (const float*)d_in[1];
    const float* bq = (const float*)d_in[2];
    const float* Wk = (const float*)d_in[3];
    const float* bk = (const float*)d_in[4];
    const float* Wv = (const float*)d_in[5];
    const float* bv = (const float*)d_in[6];
    const float* Wo = (const float*)d_in[7];
    const float* bo = (const float*)d_in[8];
    float* out = (float*)d_out;

    __half *xr, *wqt, *wkt, *wvt, *wot;
    __half *qh, *ql, *kh, *vt, *phv, *plv, *aoh, *aol;
    float* Sp;
    cudaGetSymbolAddress((void**)&xr,  g_xr);
    cudaGetSymbolAddress((void**)&wqt, g_wqt);  cudaGetSymbolAddress((void**)&wkt, g_wkt);
    cudaGetSymbolAddress((void**)&wvt, g_wvt);  cudaGetSymbolAddress((void**)&wot, g_wot);
    cudaGetSymbolAddress((void**)&qh,  g_qh);   cudaGetSymbolAddress((void**)&ql,  g_ql);
    cudaGetSymbolAddress((void**)&kh,  g_kh);
    cudaGetSymbolAddress((void**)&vt,  g_vt);
    cudaGetSymbolAddress((void**)&phv, g_ph);   cudaGetSymbolAddress((void**)&plv, g_pl);
    cudaGetSymbolAddress((void**)&aoh, g_aoh);  cudaGetSymbolAddress((void**)&aol, g_aol);
    cudaGetSymbolAddress((void**)&Sp,  g_S);

    cudaFuncSetAttribute(gemm_qkv,  cudaFuncAttributeMaxDynamicSharedMemorySize, QKV_SMEM);
    cudaFuncSetAttribute(gemm_f16x2, cudaFuncAttributeMaxDynamicSharedMemorySize, GEMM_SMEM);

    const float scale = 1.0f / 32.0f;
    dim3 tb(32, 8), tg(Dd / 32, Dd / 32);

    round_kernel<<<2048, 256>>>(x, xr, (size_t)Mm * Dd);              // #1
    transpose_round_kernel<<<tg, tb>>>(Wq, wqt);                      // #2
    transpose_round_kernel<<<tg, tb>>>(Wk, wkt);                      // #3
    transpose_round_kernel<<<tg, tb>>>(Wv, wvt);                      // #4
    transpose_round_kernel<<<tg, tb>>>(Wo, wot);                      // #5

    // #6 (ncu capture slot): combined QKV projection, single-pass fp16
    dim3 gQKV(12, Mm / TM_CTA, 1);                // 12 x 64
    gemm_qkv<<<gQKV, 256, QKV_SMEM>>>(xr, wqt, wkt, wvt, bq, bk, bv,
                                      qh, ql, kh, vt);

    // scores: per-batch 2048x2048, K=1024, causal block skip, *1/32
    dim3 gSc(Sq / TN_CTA, Sq / TM_CTA, Bn);       // 8 x 16 x 4
    gemm_f16x2<<<gSc, 256, GEMM_SMEM>>>(qh, ql, kh, Dd,
        (long)Sq * Dd, (long)Sq * Dd, nullptr,
        Sp, nullptr, nullptr, (long)Sq * Sq, Sq, scale, 1, 0);

    softmax_causal<<<Mm, 256>>>(Sp, phv, plv);

    // PV: per-batch 2048x1024, K causally bounded, heavy tiles first
    dim3 gPV(Dd / TN_CTA, Sq / TM_CTA, Bn);       // 4 x 16 x 4
    gemm_f16x2<<<gPV, 256, GEMM_SMEM>>>(phv, plv, vt, Sq,
        (long)Sq * Sq, (long)Dd * Sq, nullptr,
        nullptr, aoh, aol, (long)Sq * Dd, Dd, 1.f, 2, 1);

    // out projection: M=8192, N=1024, K=1024, fp32 out + bias
    dim3 gProj(Dd / TN_CTA, Mm / TM_CTA, 1);      // 4 x 64
    gemm_f16x2<<<gProj, 256, GEMM_SMEM>>>(aoh, aol, wot, Dd, 0, 0, bo,
        out, nullptr, nullptr, 0, Dd, 1.f, 0, 0);
}

// round 8
// speedup vs baseline: 2.2065x; 1.2161x over previous
#include <cuda_runtime.h>
#include <cuda_fp16.h>
#include <cstdint>

// SingleSelfHeadAttention b=4, s=2048, d=1024, causal, fp32 I/O.
// R8: single-pass fp16 scores & PV (QKV already single-pass); out-proj stays
//     fp16x2. Merged weight-transpose launch; PV GEMM in ncu capture slot.

static constexpr int Bn = 4;
static constexpr int Sq = 2048;
static constexpr int Dd = 1024;
static constexpr int Mm = Bn * Sq;          // 8192

// ---------------- device scratch ----------------
__device__ __half g_xr [(size_t)Mm * Dd];
__device__ __half g_wqt[(size_t)Dd * Dd], g_wkt[(size_t)Dd * Dd];
__device__ __half g_wvt[(size_t)Dd * Dd], g_wot[(size_t)Dd * Dd];
__device__ __half g_qh[(size_t)Mm * Dd];
__device__ __half g_kh[(size_t)Mm * Dd];
__device__ __half g_vt[(size_t)Bn * Dd * Sq];
__device__ float  g_S [(size_t)Bn * Sq * Sq];
__device__ __half g_ph[(size_t)Bn * Sq * Sq];
__device__ __half g_aoh[(size_t)Mm * Dd], g_aol[(size_t)Mm * Dd];

// ---------------- PTX helpers ----------------
__device__ __forceinline__ uint32_t smem_u32(const void* p) {
    uint32_t a;
    asm("{ .reg .u64 t; cvta.to.shared.u64 t, %1; cvt.u32.u64 %0, t; }" : "=r"(a) : "l"(p));
    return a;
}
#define CP_ASYNC16(dst, src) \
    asm volatile("cp.async.cg.shared.global [%0], [%1], 16;" :: "r"(dst), "l"(src))
#define CP_COMMIT() asm volatile("cp.async.commit_group;" ::: "memory")
#define CP_WAIT2()  asm volatile("cp.async.wait_group 2;" ::: "memory")
#define CP_WAIT3()  asm volatile("cp.async.wait_group 3;" ::: "memory")

__device__ __forceinline__ void ldsm_x4(uint32_t* r, uint32_t addr) {
    asm volatile("ldmatrix.sync.aligned.m8n8.x4.shared.b16 {%0,%1,%2,%3}, [%4];"
        : "=r"(r[0]), "=r"(r[1]), "=r"(r[2]), "=r"(r[3]) : "r"(addr));
}
__device__ __forceinline__ void mma_f16(float* c, const uint32_t* a, const uint32_t* b) {
    asm volatile("mma.sync.aligned.m16n8k16.row.col.f32.f16.f16.f32 "
        "{%0,%1,%2,%3}, {%4,%5,%6,%7}, {%8,%9}, {%0,%1,%2,%3};"
        : "+f"(c[0]), "+f"(c[1]), "+f"(c[2]), "+f"(c[3])
        : "r"(a[0]), "r"(a[1]), "r"(a[2]), "r"(a[3]), "r"(b[0]), "r"(b[1]));
}
__device__ __forceinline__ uint32_t swz(uint32_t off) {   // 128B-row XOR swizzle
    return off ^ ((off >> 3) & 0x70);
}

// ---------------- prep kernels ----------------
__device__ __forceinline__ void split2h(float v, __half& h, __half& l) {
    h = __float2half_rn(v);
    l = __float2half_rn(v - __half2float(h));
}

__global__ void round_kernel(const float* __restrict__ src,
                             __half* __restrict__ dst, size_t n) {
    size_t i = (size_t)blockIdx.x * blockDim.x + threadIdx.x;
    size_t stride = (size_t)gridDim.x * blockDim.x;
    for (; i < n; i += stride) dst[i] = __float2half_rn(src[i]);
}

// All four W [Dd][Dd] -> Wt[n][k] = W[k][n], fp16; grid.z selects the pair.
__global__ void transpose4_kernel(const float* __restrict__ W0, __half* __restrict__ T0,
                                  const float* __restrict__ W1, __half* __restrict__ T1,
                                  const float* __restrict__ W2, __half* __restrict__ T2,
                                  const float* __restrict__ W3, __half* __restrict__ T3) {
    const float* W = (blockIdx.z == 0) ? W0 : (blockIdx.z == 1) ? W1
                   : (blockIdx.z == 2) ? W2 : W3;
    __half* T = (blockIdx.z == 0) ? T0 : (blockIdx.z == 1) ? T1
              : (blockIdx.z == 2) ? T2 : T3;
    __shared__ float tile[32][33];
    int bx = blockIdx.x * 32, by = blockIdx.y * 32;
    int tx = threadIdx.x, ty = threadIdx.y;
    #pragma unroll
    for (int j = 0; j < 4; j++)
        tile[ty + 8 * j][tx] = W[(size_t)(by + ty + 8 * j) * Dd + bx + tx];
    __syncthreads();
    #pragma unroll
    for (int j = 0; j < 4; j++) {
        float v = tile[tx][ty + 8 * j];
        size_t o = (size_t)(bx + ty + 8 * j) * Dd + by + tx;
        T[o] = __float2half_rn(v);
    }
}

// causal softmax on S rows; writes fp16 probs, zero-pads to 128-mult
__global__ __launch_bounds__(256)
void softmax_causal(float* __restrict__ Sm, __half* __restrict__ ph) {
    const int gq = blockIdx.x;
    const int q  = gq & (Sq - 1);
    float* row = Sm + (size_t)gq * Sq;
    __half* hrow = ph + (size_t)gq * Sq;
    const int len = q + 1;
    const int tid = threadIdx.x;
    __shared__ float red[256];

    float m = -1e30f;
    for (int j = tid; j < len; j += 256) m = fmaxf(m, row[j]);
    red[tid] = m; __syncthreads();
    for (int s = 128; s > 0; s >>= 1) {
        if (tid < s) red[tid] = fmaxf(red[tid], red[tid + s]);
        __syncthreads();
    }
    m = red[0]; __syncthreads();

    float sum = 0.f;
    for (int j = tid; j < len; j += 256) {
        float e = __expf(row[j] - m);
        row[j] = e; sum += e;
    }
    red[tid] = sum; __syncthreads();
    for (int s = 128; s > 0; s >>= 1) {
        if (tid < s) red[tid] += red[tid + s];
        __syncthreads();
    }
    const float inv = 1.0f / red[0];

    for (int j = tid; j < len; j += 256)
        hrow[j] = __float2half_rn(row[j] * inv);
    const int jend = ((q >> 7) + 1) << 7;
    const __half z = __float2half(0.f);
    for (int j = len + tid; j < jend; j += 256) hrow[j] = z;
}

// ---------------- shared tile-loader pieces ----------------
#define TM_CTA 128
#define TN_CTA 256
#define A_TILE (TM_CTA * 128)            // 16384 B
#define B_TILE (TN_CTA * 128)            // 32768 B

__device__ __forceinline__ void load_A_async(uint32_t dst, const __half* src,
                                             int ldK, int tid) {
    #pragma unroll
    for (int j = 0; j < 4; j++) {
        int s = tid + j * 256;
        int r = s >> 3, c = s & 7;
        CP_ASYNC16(dst + swz(r * 128 + c * 16), src + (size_t)r * ldK + c * 8);
    }
}
__device__ __forceinline__ void load_B_async(uint32_t dst, const __half* src,
                                             int ldK, int tid) {
    #pragma unroll
    for (int j = 0; j < 8; j++) {
        int s = tid + j * 256;
        int r = s >> 3, c = s & 7;
        CP_ASYNC16(dst + swz(r * 128 + c * 16), src + (size_t)r * ldK + c * 8);
    }
}

// ================= QKV combined single-pass GEMM =================
// grid.x in [0,12): wsel = x>>2 chooses {Q,K,V}; bxx = x&3 is the 256-col tile.
#define STAGE_Q (A_TILE + B_TILE)        // 49152
#define NSTAGE_Q 4
#define QKV_SMEM (NSTAGE_Q * STAGE_Q)    // 196608

__global__ __launch_bounds__(256, 1)
void gemm_qkv(const __half* __restrict__ xr,
              const __half* __restrict__ wq, const __half* __restrict__ wk,
              const __half* __restrict__ wv,
              const float* __restrict__ bq, const float* __restrict__ bk,
              const float* __restrict__ bv,
              __half* __restrict__ qh, __half* __restrict__ kh,
              __half* __restrict__ vt)
{
    const int bxx = blockIdx.x & 3;
    const int wsel = blockIdx.x >> 2;
    const int by = blockIdx.y;
    const __half* Bw  = (wsel == 0) ? wq : (wsel == 1) ? wk : wv;
    const float* bias = (wsel == 0) ? bq : (wsel == 1) ? bk : bv;

    extern __shared__ __align__(16) char smem[];
    const uint32_t sb = smem_u32(smem);

    const int tid  = threadIdx.x;
    const int lane = tid & 31;
    const int wid  = tid >> 5;
    const int wm   = wid >> 2;
    const int wn   = wid & 3;

    const __half* pA = xr + (size_t)by * TM_CTA * Dd;
    const __half* pB = Bw + (size_t)bxx * TN_CTA * Dd;

    float acc[4][8][4] = {};
    const int nchunk = Dd >> 6;                   // 16

    #pragma unroll
    for (int p = 0; p < NSTAGE_Q; p++) {
        const size_t ko = (size_t)p << 6;
        uint32_t st = sb + p * STAGE_Q;
        load_A_async(st, pA + ko, Dd, tid);
        load_B_async(st + A_TILE, pB + ko, Dd, tid);
        CP_COMMIT();
    }

    const uint32_t arow = (lane & 7) + ((lane & 8)  ? 8 : 0);
    const uint32_t acol = (lane & 16) ? 16u : 0u;
    const uint32_t brow = (lane & 7) + ((lane & 16) ? 8 : 0);
    const uint32_t bcol = (lane & 8)  ? 16u : 0u;

    for (int c = 0; c < nchunk; ++c) {
        CP_WAIT3();
        __syncthreads();
        const uint32_t base = sb + (c % NSTAGE_Q) * STAGE_Q;

        #pragma unroll
        for (int ks = 0; ks < 4; ks++) {
            const uint32_t kb = ks * 32;
            uint32_t ah[4][4];
            #pragma unroll
            for (int i = 0; i < 4; i++) {
                uint32_t off = swz((wm * 64 + i * 16 + arow) * 128 + kb + acol);
                ldsm_x4(ah[i], base + off);
            }
            #pragma unroll
            for (int j2 = 0; j2 < 4; j2++) {
                uint32_t off = swz((wn * 64 + j2 * 16 + brow) * 128 + kb + bcol);
                uint32_t th[4];
                ldsm_x4(th, base + A_TILE + off);
                const int j0 = j2 * 2, j1 = j2 * 2 + 1;
                #pragma unroll
                for (int i = 0; i < 4; i++) {
                    mma_f16(acc[i][j0], ah[i], &th[0]);
                    mma_f16(acc[i][j1], ah[i], &th[2]);
                }
            }
        }

        __syncthreads();
        if (c + NSTAGE_Q < nchunk) {
            const size_t ko = (size_t)(c + NSTAGE_Q) << 6;
            uint32_t st = sb + (c % NSTAGE_Q) * STAGE_Q;
            load_A_async(st, pA + ko, Dd, tid);
            load_B_async(st + A_TILE, pB + ko, Dd, tid);
        }
        CP_COMMIT();
    }

    const int m_base = by * TM_CTA + wm * 64;
    const int n_base = bxx * TN_CTA + wn * 64;
    const int rr = lane >> 2;
    const int cc = 2 * (lane & 3);

    #pragma unroll
    for (int i = 0; i < 4; i++) {
        #pragma unroll
        for (int j = 0; j < 8; j++) {
            const int col = n_base + j * 8 + cc;
            #pragma unroll
            for (int h = 0; h < 2; h++) {
                const int row = m_base + i * 16 + rr + h * 8;
                float v0 = acc[i][j][2 * h + 0] + __ldg(&bias[col]);
                float v1 = acc[i][j][2 * h + 1] + __ldg(&bias[col + 1]);
                if (wsel == 0) {
                    size_t o = (size_t)row * Dd + col;
                    *(__half2*)(qh + o) =
                        __halves2half2(__float2half_rn(v0), __float2half_rn(v1));
                } else if (wsel == 1) {
                    size_t o = (size_t)row * Dd + col;
                    *(__half2*)(kh + o) =
                        __halves2half2(__float2half_rn(v0), __float2half_rn(v1));
                } else {
                    const long z2 = row >> 11;
                    const long mloc = row & (Sq - 1);
                    size_t o0 = ((size_t)z2 * Dd + col) * Sq + mloc;
                    size_t o1 = ((size_t)z2 * Dd + col + 1) * Sq + mloc;
                    vt[o0] = __float2half_rn(v0);
                    vt[o1] = __float2half_rn(v1);
                }
            }
        }
    }
}

// ================= generic fp16 GEMM (1- or 2-pass) =================
// TWOPASS: C = Ah*B^T + Al*B^T ; else C = Ah*B^T.
// modes: 0 = fp32 out (+bias, *scale); 1 = fp16 hi/lo split out
template <bool TWOPASS>
__global__ __launch_bounds__(256, 1)
void gemm_f16(const __half* __restrict__ Ah, const __half* __restrict__ Al,
              const __half* __restrict__ Bh,
              int Kdim, long sAz, long sBz,
              const float* __restrict__ bias,
              float* __restrict__ outF,
              __half* __restrict__ outH, __half* __restrict__ outL,
              long sOz, int ldOut, float scale, int causal, int mode)
{
    constexpr int STG = TWOPASS ? (2 * A_TILE + B_TILE) : (A_TILE + B_TILE);
    constexpr int NST = TWOPASS ? 3 : 4;

    const int bx = blockIdx.x, z = blockIdx.z;
    const int by = (causal == 2) ? ((int)gridDim.y - 1 - (int)blockIdx.y)
                                 : (int)blockIdx.y;
    if (causal == 1 && 2 * bx > by) return;
    const int kend = (causal == 2) ? (by + 1) * 128 : Kdim;
    const int nchunk = kend >> 6;

    extern __shared__ __align__(16) char smem[];
    const uint32_t sb = smem_u32(smem);

    const int tid  = threadIdx.x;
    const int lane = tid & 31;
    const int wid  = tid >> 5;
    const int wm   = wid >> 2;
    const int wn   = wid & 3;

    const __half* pAh = Ah + (size_t)z * sAz + (size_t)by * TM_CTA * Kdim;
    const __half* pAl = TWOPASS ? Al + (size_t)z * sAz + (size_t)by * TM_CTA * Kdim
                                : nullptr;
    const __half* pBh = Bh + (size_t)z * sBz + (size_t)bx * TN_CTA * Kdim;

    float acc[4][8][4] = {};

    #pragma unroll
    for (int p = 0; p < NST; p++) {
        if (p < nchunk) {
            const size_t ko = (size_t)p << 6;
            uint32_t st = sb + p * STG;
            load_A_async(st, pAh + ko, Kdim, tid);
            if (TWOPASS) load_A_async(st + A_TILE, pAl + ko, Kdim, tid);
            load_B_async(st + (TWOPASS ? 2 : 1) * A_TILE, pBh + ko, Kdim, tid);
        }
        CP_COMMIT();
    }

    const uint32_t arow = (lane & 7) + ((lane & 8)  ? 8 : 0);
    const uint32_t acol = (lane & 16) ? 16u : 0u;
    const uint32_t brow = (lane & 7) + ((lane & 16) ? 8 : 0);
    const uint32_t bcol = (lane & 8)  ? 16u : 0u;

    for (int c = 0; c < nchunk; ++c) {
        if (TWOPASS) { CP_WAIT2(); } else { CP_WAIT3(); }
        __syncthreads();
        const uint32_t base = sb + (c % NST) * STG;
        const uint32_t bofs = base + (TWOPASS ? 2 : 1) * A_TILE;

        #pragma unroll
        for (int ks = 0; ks < 4; ks++) {
            const uint32_t kb = ks * 32;
            uint32_t ah[4][4], al[4][4];
            #pragma unroll
            for (int i = 0; i < 4; i++) {
                uint32_t off = swz((wm * 64 + i * 16 + arow) * 128 + kb + acol);
                ldsm_x4(ah[i], base + off);
                if (TWOPASS) ldsm_x4(al[i], base + A_TILE + off);
            }
            #pragma unroll
            for (int j2 = 0; j2 < 4; j2++) {
                uint32_t off = swz((wn * 64 + j2 * 16 + brow) * 128 + kb + bcol);
                uint32_t th[4];
                ldsm_x4(th, bofs + off);
                const int j0 = j2 * 2, j1 = j2 * 2 + 1;
                #pragma unroll
                for (int i = 0; i < 4; i++) {
                    mma_f16(acc[i][j0], ah[i], &th[0]);
                    mma_f16(acc[i][j1], ah[i], &th[2]);
                }
                if (TWOPASS) {
                    #pragma unroll
                    for (int i = 0; i < 4; i++) {
                        mma_f16(acc[i][j0], al[i], &th[0]);
                        mma_f16(acc[i][j1], al[i], &th[2]);
                    }
                }
            }
        }

        __syncthreads();
        if (c + NST < nchunk) {
            const size_t ko = (size_t)(c + NST) << 6;
            uint32_t st = sb + (c % NST) * STG;
            load_A_async(st, pAh + ko, Kdim, tid);
            if (TWOPASS) load_A_async(st + A_TILE, pAl + ko, Kdim, tid);
            load_B_async(st + (TWOPASS ? 2 : 1) * A_TILE, pBh + ko, Kdim, tid);
        }
        CP_COMMIT();
    }

    const int m_base = by * TM_CTA + wm * 64;
    const int n_base = bx * TN_CTA + wn * 64;
    const int rr = lane >> 2;
    const int cc = 2 * (lane & 3);

    #pragma unroll
    for (int i = 0; i < 4; i++) {
        #pragma unroll
        for (int j = 0; j < 8; j++) {
            const int col = n_base + j * 8 + cc;
            #pragma unroll
            for (int h = 0; h < 2; h++) {
                const int row = m_base + i * 16 + rr + h * 8;
                float v0 = acc[i][j][2 * h + 0];
                float v1 = acc[i][j][2 * h + 1];
                if (mode == 0) {
                    v0 *= scale; v1 *= scale;
                    if (bias) { v0 += __ldg(&bias[col]); v1 += __ldg(&bias[col + 1]); }
                    float2 o = make_float2(v0, v1);
                    *(float2*)(outF + (size_t)z * sOz + (size_t)row * ldOut + col) = o;
                } else {
                    __half h0, l0, h1, l1;
                    split2h(v0, h0, l0); split2h(v1, h1, l1);
                    size_t o = (size_t)z * sOz + (size_t)row * ldOut + col;
                    *(__half2*)(outH + o) = __halves2half2(h0, h1);
                    *(__half2*)(outL + o) = __halves2half2(l0, l1);
                }
            }
        }
    }
}

// ---------------- launch ----------------
extern "C" void kernel_launch(void* const* d_in, const int* in_sizes, int n_in,
                              void* d_out, int out_size)
{
    const float* x  = (const float*)d_in[0];
    const float* Wq = (const float*)d_in[1];
    const float* bq = (const float*)d_in[2];
    const float* Wk = (const float*)d_in[3];
    const float* bk = (const float*)d_in[4];
    const float* Wv = (const float*)d_in[5];
    const float* bv = (const float*)d_in[6];
    const float* Wo = (const float*)d_in[7];
    const float* bo = (const float*)d_in[8];
    float* out = (float*)d_out;

    __half *xr, *wqt, *wkt, *wvt, *wot, *qh, *kh, *vt, *phv, *aoh, *aol;
    float* Sp;
    cudaGetSymbolAddress((void**)&xr,  g_xr);
    cudaGetSymbolAddress((void**)&wqt, g_wqt);  cudaGetSymbolAddress((void**)&wkt, g_wkt);
    cudaGetSymbolAddress((void**)&wvt, g_wvt);  cudaGetSymbolAddress((void**)&wot, g_wot);
    cudaGetSymbolAddress((void**)&qh,  g_qh);
    cudaGetSymbolAddress((void**)&kh,  g_kh);
    cudaGetSymbolAddress((void**)&vt,  g_vt);
    cudaGetSymbolAddress((void**)&phv, g_ph);
    cudaGetSymbolAddress((void**)&aoh, g_aoh);  cudaGetSymbolAddress((void**)&aol, g_aol);
    cudaGetSymbolAddress((void**)&Sp,  g_S);

    cudaFuncSetAttribute(gemm_qkv, cudaFuncAttributeMaxDynamicSharedMemorySize, QKV_SMEM);
    cudaFuncSetAttribute(gemm_f16<false>, cudaFuncAttributeMaxDynamicSharedMemorySize, 196608);
    cudaFuncSetAttribute(gemm_f16<true>,  cudaFuncAttributeMaxDynamicSharedMemorySize, 196608);

    const float scale = 1.0f / 32.0f;

    // #1: round x to fp16
    round_kernel<<<2048, 256>>>(x, xr, (size_t)Mm * Dd);
    // #2: all four weight transposes in one launch
    dim3 tb(32, 8), tg4(Dd / 32, Dd / 32, 4);
    transpose4_kernel<<<tg4, tb>>>(Wq, wqt, Wk, wkt, Wv, wvt, Wo, wot);

    // #3: combined QKV projection (single-pass fp16)
    dim3 gQKV(12, Mm / TM_CTA, 1);
    gemm_qkv<<<gQKV, 256, QKV_SMEM>>>(xr, wqt, wkt, wvt, bq, bk, bv, qh, kh, vt);

    // #4: scores (single-pass), per-batch 2048x2048, K=1024, causal skip, *1/32
    dim3 gSc(Sq / TN_CTA, Sq / TM_CTA, Bn);
    gemm_f16<false><<<gSc, 256, 196608>>>(qh, nullptr, kh, Dd,
        (long)Sq * Dd, (long)Sq * Dd, nullptr,
        Sp, nullptr, nullptr, (long)Sq * Sq, Sq, scale, 1, 0);

    // #5: softmax
    softmax_causal<<<Mm, 256>>>(Sp, phv);

    // #6 (ncu capture slot): PV single-pass, K causally bounded, heavy first
    dim3 gPV(Dd / TN_CTA, Sq / TM_CTA, Bn);
    gemm_f16<false><<<gPV, 256, 196608>>>(phv, nullptr, vt, Sq,
        (long)Sq * Sq, (long)Dd * Sq, nullptr,
        nullptr, aoh, aol, (long)Sq * Dd, Dd, 1.f, 2, 1);

    // #7: out projection (two-pass), fp32 out + bias
    dim3 gProj(Dd / TN_CTA, Mm / TM_CTA, 1);
    gemm_f16<true><<<gProj, 256, 196608>>>(aoh, aol, wot, Dd, 0, 0, bo,
        out, nullptr, nullptr, 0, Dd, 1.f, 0, 0);
}

// round 9
// speedup vs baseline: 2.4451x; 1.1081x over previous
#include <cuda_runtime.h>
#include <cuda_fp16.h>
#include <cstdint>

// SingleSelfHeadAttention b=4, s=2048, d=1024, causal, fp32 I/O.
// R9: ALL GEMMs single-pass fp16 (HMMA, fp32 accum). Error budget ~4.3e-4.

static constexpr int Bn = 4;
static constexpr int Sq = 2048;
static constexpr int Dd = 1024;
static constexpr int Mm = Bn * Sq;          // 8192

// ---------------- device scratch ----------------
__device__ __half g_xr [(size_t)Mm * Dd];
__device__ __half g_wqt[(size_t)Dd * Dd], g_wkt[(size_t)Dd * Dd];
__device__ __half g_wvt[(size_t)Dd * Dd], g_wot[(size_t)Dd * Dd];
__device__ __half g_qh[(size_t)Mm * Dd];
__device__ __half g_kh[(size_t)Mm * Dd];
__device__ __half g_vt[(size_t)Bn * Dd * Sq];
__device__ float  g_S [(size_t)Bn * Sq * Sq];
__device__ __half g_ph[(size_t)Bn * Sq * Sq];
__device__ __half g_aoh[(size_t)Mm * Dd];

// ---------------- PTX helpers ----------------
__device__ __forceinline__ uint32_t smem_u32(const void* p) {
    uint32_t a;
    asm("{ .reg .u64 t; cvta.to.shared.u64 t, %1; cvt.u32.u64 %0, t; }" : "=r"(a) : "l"(p));
    return a;
}
#define CP_ASYNC16(dst, src) \
    asm volatile("cp.async.cg.shared.global [%0], [%1], 16;" :: "r"(dst), "l"(src))
#define CP_COMMIT() asm volatile("cp.async.commit_group;" ::: "memory")
#define CP_WAIT3()  asm volatile("cp.async.wait_group 3;" ::: "memory")

__device__ __forceinline__ void ldsm_x4(uint32_t* r, uint32_t addr) {
    asm volatile("ldmatrix.sync.aligned.m8n8.x4.shared.b16 {%0,%1,%2,%3}, [%4];"
        : "=r"(r[0]), "=r"(r[1]), "=r"(r[2]), "=r"(r[3]) : "r"(addr));
}
__device__ __forceinline__ void mma_f16(float* c, const uint32_t* a, const uint32_t* b) {
    asm volatile("mma.sync.aligned.m16n8k16.row.col.f32.f16.f16.f32 "
        "{%0,%1,%2,%3}, {%4,%5,%6,%7}, {%8,%9}, {%0,%1,%2,%3};"
        : "+f"(c[0]), "+f"(c[1]), "+f"(c[2]), "+f"(c[3])
        : "r"(a[0]), "r"(a[1]), "r"(a[2]), "r"(a[3]), "r"(b[0]), "r"(b[1]));
}
__device__ __forceinline__ uint32_t swz(uint32_t off) {   // 128B-row XOR swizzle
    return off ^ ((off >> 3) & 0x70);
}

// ---------------- prep kernels ----------------
__global__ void round_kernel(const float* __restrict__ src,
                             __half* __restrict__ dst, size_t n) {
    size_t i = (size_t)blockIdx.x * blockDim.x + threadIdx.x;
    size_t stride = (size_t)gridDim.x * blockDim.x;
    for (; i < n; i += stride) dst[i] = __float2half_rn(src[i]);
}

// All four W [Dd][Dd] -> Wt[n][k] = W[k][n], fp16; grid.z selects the pair.
__global__ void transpose4_kernel(const float* __restrict__ W0, __half* __restrict__ T0,
                                  const float* __restrict__ W1, __half* __restrict__ T1,
                                  const float* __restrict__ W2, __half* __restrict__ T2,
                                  const float* __restrict__ W3, __half* __restrict__ T3) {
    const float* W = (blockIdx.z == 0) ? W0 : (blockIdx.z == 1) ? W1
                   : (blockIdx.z == 2) ? W2 : W3;
    __half* T = (blockIdx.z == 0) ? T0 : (blockIdx.z == 1) ? T1
              : (blockIdx.z == 2) ? T2 : T3;
    __shared__ float tile[32][33];
    int bx = blockIdx.x * 32, by = blockIdx.y * 32;
    int tx = threadIdx.x, ty = threadIdx.y;
    #pragma unroll
    for (int j = 0; j < 4; j++)
        tile[ty + 8 * j][tx] = W[(size_t)(by + ty + 8 * j) * Dd + bx + tx];
    __syncthreads();
    #pragma unroll
    for (int j = 0; j < 4; j++) {
        float v = tile[tx][ty + 8 * j];
        size_t o = (size_t)(bx + ty + 8 * j) * Dd + by + tx;
        T[o] = __float2half_rn(v);
    }
}

// causal softmax on S rows; writes fp16 probs, zero-pads to 128-mult
__global__ __launch_bounds__(256)
void softmax_causal(float* __restrict__ Sm, __half* __restrict__ ph) {
    const int gq = blockIdx.x;
    const int q  = gq & (Sq - 1);
    float* row = Sm + (size_t)gq * Sq;
    __half* hrow = ph + (size_t)gq * Sq;
    const int len = q + 1;
    const int tid = threadIdx.x;
    __shared__ float red[256];

    float m = -1e30f;
    for (int j = tid; j < len; j += 256) m = fmaxf(m, row[j]);
    red[tid] = m; __syncthreads();
    for (int s = 128; s > 0; s >>= 1) {
        if (tid < s) red[tid] = fmaxf(red[tid], red[tid + s]);
        __syncthreads();
    }
    m = red[0]; __syncthreads();

    float sum = 0.f;
    for (int j = tid; j < len; j += 256) {
        float e = __expf(row[j] - m);
        row[j] = e; sum += e;
    }
    red[tid] = sum; __syncthreads();
    for (int s = 128; s > 0; s >>= 1) {
        if (tid < s) red[tid] += red[tid + s];
        __syncthreads();
    }
    const float inv = 1.0f / red[0];

    for (int j = tid; j < len; j += 256)
        hrow[j] = __float2half_rn(row[j] * inv);
    const int jend = ((q >> 7) + 1) << 7;
    const __half z = __float2half(0.f);
    for (int j = len + tid; j < jend; j += 256) hrow[j] = z;
}

// ---------------- shared tile-loader pieces ----------------
#define TM_CTA 128
#define TN_CTA 256
#define A_TILE (TM_CTA * 128)            // 16384 B
#define B_TILE (TN_CTA * 128)            // 32768 B
#define STAGE  (A_TILE + B_TILE)         // 49152
#define NSTAGE 4
#define GEMM_SMEM (NSTAGE * STAGE)       // 196608

__device__ __forceinline__ void load_A_async(uint32_t dst, const __half* src,
                                             int ldK, int tid) {
    #pragma unroll
    for (int j = 0; j < 4; j++) {
        int s = tid + j * 256;
        int r = s >> 3, c = s & 7;
        CP_ASYNC16(dst + swz(r * 128 + c * 16), src + (size_t)r * ldK + c * 8);
    }
}
__device__ __forceinline__ void load_B_async(uint32_t dst, const __half* src,
                                             int ldK, int tid) {
    #pragma unroll
    for (int j = 0; j < 8; j++) {
        int s = tid + j * 256;
        int r = s >> 3, c = s & 7;
        CP_ASYNC16(dst + swz(r * 128 + c * 16), src + (size_t)r * ldK + c * 8);
    }
}

// ================= QKV combined single-pass GEMM =================
__global__ __launch_bounds__(256, 1)
void gemm_qkv(const __half* __restrict__ xr,
              const __half* __restrict__ wq, const __half* __restrict__ wk,
              const __half* __restrict__ wv,
              const float* __restrict__ bq, const float* __restrict__ bk,
              const float* __restrict__ bv,
              __half* __restrict__ qh, __half* __restrict__ kh,
              __half* __restrict__ vt)
{
    const int bxx = blockIdx.x & 3;
    const int wsel = blockIdx.x >> 2;
    const int by = blockIdx.y;
    const __half* Bw  = (wsel == 0) ? wq : (wsel == 1) ? wk : wv;
    const float* bias = (wsel == 0) ? bq : (wsel == 1) ? bk : bv;

    extern __shared__ __align__(16) char smem[];
    const uint32_t sb = smem_u32(smem);

    const int tid  = threadIdx.x;
    const int lane = tid & 31;
    const int wid  = tid >> 5;
    const int wm   = wid >> 2;
    const int wn   = wid & 3;

    const __half* pA = xr + (size_t)by * TM_CTA * Dd;
    const __half* pB = Bw + (size_t)bxx * TN_CTA * Dd;

    float acc[4][8][4] = {};
    const int nchunk = Dd >> 6;                   // 16

    #pragma unroll
    for (int p = 0; p < NSTAGE; p++) {
        const size_t ko = (size_t)p << 6;
        uint32_t st = sb + p * STAGE;
        load_A_async(st, pA + ko, Dd, tid);
        load_B_async(st + A_TILE, pB + ko, Dd, tid);
        CP_COMMIT();
    }

    const uint32_t arow = (lane & 7) + ((lane & 8)  ? 8 : 0);
    const uint32_t acol = (lane & 16) ? 16u : 0u;
    const uint32_t brow = (lane & 7) + ((lane & 16) ? 8 : 0);
    const uint32_t bcol = (lane & 8)  ? 16u : 0u;

    for (int c = 0; c < nchunk; ++c) {
        CP_WAIT3();
        __syncthreads();
        const uint32_t base = sb + (c % NSTAGE) * STAGE;

        #pragma unroll
        for (int ks = 0; ks < 4; ks++) {
            const uint32_t kb = ks * 32;
            uint32_t ah[4][4];
            #pragma unroll
            for (int i = 0; i < 4; i++) {
                uint32_t off = swz((wm * 64 + i * 16 + arow) * 128 + kb + acol);
                ldsm_x4(ah[i], base + off);
            }
            #pragma unroll
            for (int j2 = 0; j2 < 4; j2++) {
                uint32_t off = swz((wn * 64 + j2 * 16 + brow) * 128 + kb + bcol);
                uint32_t th[4];
                ldsm_x4(th, base + A_TILE + off);
                const int j0 = j2 * 2, j1 = j2 * 2 + 1;
                #pragma unroll
                for (int i = 0; i < 4; i++) {
                    mma_f16(acc[i][j0], ah[i], &th[0]);
                    mma_f16(acc[i][j1], ah[i], &th[2]);
                }
            }
        }

        __syncthreads();
        if (c + NSTAGE < nchunk) {
            const size_t ko = (size_t)(c + NSTAGE) << 6;
            uint32_t st = sb + (c % NSTAGE) * STAGE;
            load_A_async(st, pA + ko, Dd, tid);
            load_B_async(st + A_TILE, pB + ko, Dd, tid);
        }
        CP_COMMIT();
    }

    const int m_base = by * TM_CTA + wm * 64;
    const int n_base = bxx * TN_CTA + wn * 64;
    const int rr = lane >> 2;
    const int cc = 2 * (lane & 3);

    #pragma unroll
    for (int i = 0; i < 4; i++) {
        #pragma unroll
        for (int j = 0; j < 8; j++) {
            const int col = n_base + j * 8 + cc;
            #pragma unroll
            for (int h = 0; h < 2; h++) {
                const int row = m_base + i * 16 + rr + h * 8;
                float v0 = acc[i][j][2 * h + 0] + __ldg(&bias[col]);
                float v1 = acc[i][j][2 * h + 1] + __ldg(&bias[col + 1]);
                if (wsel == 0) {
                    size_t o = (size_t)row * Dd + col;
                    *(__half2*)(qh + o) =
                        __halves2half2(__float2half_rn(v0), __float2half_rn(v1));
                } else if (wsel == 1) {
                    size_t o = (size_t)row * Dd + col;
                    *(__half2*)(kh + o) =
                        __halves2half2(__float2half_rn(v0), __float2half_rn(v1));
                } else {
                    const long z2 = row >> 11;
                    const long mloc = row & (Sq - 1);
                    size_t o0 = ((size_t)z2 * Dd + col) * Sq + mloc;
                    size_t o1 = ((size_t)z2 * Dd + col + 1) * Sq + mloc;
                    vt[o0] = __float2half_rn(v0);
                    vt[o1] = __float2half_rn(v1);
                }
            }
        }
    }
}

// ================= generic single-pass fp16 GEMM =================
// modes: 0 = fp32 out (+bias, *scale); 1 = fp16 out
__global__ __launch_bounds__(256, 1)
void gemm_f16(const __half* __restrict__ Ah, const __half* __restrict__ Bh,
              int Kdim, long sAz, long sBz,
              const float* __restrict__ bias,
              float* __restrict__ outF, __half* __restrict__ outH,
              long sOz, int ldOut, float scale, int causal, int mode)
{
    const int bx = blockIdx.x, z = blockIdx.z;
    const int by = (causal == 2) ? ((int)gridDim.y - 1 - (int)blockIdx.y)
                                 : (int)blockIdx.y;
    if (causal == 1 && 2 * bx > by) return;
    const int kend = (causal == 2) ? (by + 1) * 128 : Kdim;
    const int nchunk = kend >> 6;

    extern __shared__ __align__(16) char smem[];
    const uint32_t sb = smem_u32(smem);

    const int tid  = threadIdx.x;
    const int lane = tid & 31;
    const int wid  = tid >> 5;
    const int wm   = wid >> 2;
    const int wn   = wid & 3;

    const __half* pAh = Ah + (size_t)z * sAz + (size_t)by * TM_CTA * Kdim;
    const __half* pBh = Bh + (size_t)z * sBz + (size_t)bx * TN_CTA * Kdim;

    float acc[4][8][4] = {};

    #pragma unroll
    for (int p = 0; p < NSTAGE; p++) {
        if (p < nchunk) {
            const size_t ko = (size_t)p << 6;
            uint32_t st = sb + p * STAGE;
            load_A_async(st, pAh + ko, Kdim, tid);
            load_B_async(st + A_TILE, pBh + ko, Kdim, tid);
        }
        CP_COMMIT();
    }

    const uint32_t arow = (lane & 7) + ((lane & 8)  ? 8 : 0);
    const uint32_t acol = (lane & 16) ? 16u : 0u;
    const uint32_t brow = (lane & 7) + ((lane & 16) ? 8 : 0);
    const uint32_t bcol = (lane & 8)  ? 16u : 0u;

    for (int c = 0; c < nchunk; ++c) {
        CP_WAIT3();
        __syncthreads();
        const uint32_t base = sb + (c % NSTAGE) * STAGE;

        #pragma unroll
        for (int ks = 0; ks < 4; ks++) {
            const uint32_t kb = ks * 32;
            uint32_t ah[4][4];
            #pragma unroll
            for (int i = 0; i < 4; i++) {
                uint32_t off = swz((wm * 64 + i * 16 + arow) * 128 + kb + acol);
                ldsm_x4(ah[i], base + off);
            }
            #pragma unroll
            for (int j2 = 0; j2 < 4; j2++) {
                uint32_t off = swz((wn * 64 + j2 * 16 + brow) * 128 + kb + bcol);
                uint32_t th[4];
                ldsm_x4(th, base + A_TILE + off);
                const int j0 = j2 * 2, j1 = j2 * 2 + 1;
                #pragma unroll
                for (int i = 0; i < 4; i++) {
                    mma_f16(acc[i][j0], ah[i], &th[0]);
                    mma_f16(acc[i][j1], ah[i], &th[2]);
                }
            }
        }

        __syncthreads();
        if (c + NSTAGE < nchunk) {
            const size_t ko = (size_t)(c + NSTAGE) << 6;
            uint32_t st = sb + (c % NSTAGE) * STAGE;
            load_A_async(st, pAh + ko, Kdim, tid);
            load_B_async(st + A_TILE, pBh + ko, Kdim, tid);
        }
        CP_COMMIT();
    }

    const int m_base = by * TM_CTA + wm * 64;
    const int n_base = bx * TN_CTA + wn * 64;
    const int rr = lane >> 2;
    const int cc = 2 * (lane & 3);

    #pragma unroll
    for (int i = 0; i < 4; i++) {
        #pragma unroll
        for (int j = 0; j < 8; j++) {
            const int col = n_base + j * 8 + cc;
            #pragma unroll
            for (int h = 0; h < 2; h++) {
                const int row = m_base + i * 16 + rr + h * 8;
                float v0 = acc[i][j][2 * h + 0];
                float v1 = acc[i][j][2 * h + 1];
                if (mode == 0) {
                    v0 *= scale; v1 *= scale;
                    if (bias) { v0 += __ldg(&bias[col]); v1 += __ldg(&bias[col + 1]); }
                    float2 o = make_float2(v0, v1);
                    *(float2*)(outF + (size_t)z * sOz + (size_t)row * ldOut + col) = o;
                } else {
                    size_t o = (size_t)z * sOz + (size_t)row * ldOut + col;
                    *(__half2*)(outH + o) =
                        __halves2half2(__float2half_rn(v0), __float2half_rn(v1));
                }
            }
        }
    }
}

// ---------------- launch ----------------
extern "C" void kernel_launch(void* const* d_in, const int* in_sizes, int n_in,
                              void* d_out, int out_size)
{
    const float* x  = (const float*)d_in[0];
    const float* Wq = (const float*)d_in[1];
    const float* bq = (const float*)d_in[2];
    const float* Wk = (const float*)d_in[3];
    const float* bk = (const float*)d_in[4];
    const float* Wv = (const float*)d_in[5];
    const float* bv = (const float*)d_in[6];
    const float* Wo = (const float*)d_in[7];
    const float* bo = (const float*)d_in[8];
    float* out = (float*)d_out;

    __half *xr, *wqt, *wkt, *wvt, *wot, *qh, *kh, *vt, *phv, *aoh;
    float* Sp;
    cudaGetSymbolAddress((void**)&xr,  g_xr);
    cudaGetSymbolAddress((void**)&wqt, g_wqt);  cudaGetSymbolAddress((void**)&wkt, g_wkt);
    cudaGetSymbolAddress((void**)&wvt, g_wvt);  cudaGetSymbolAddress((void**)&wot, g_wot);
    cudaGetSymbolAddress((void**)&qh,  g_qh);
    cudaGetSymbolAddress((void**)&kh,  g_kh);
    cudaGetSymbolAddress((void**)&vt,  g_vt);
    cudaGetSymbolAddress((void**)&phv, g_ph);
    cudaGetSymbolAddress((void**)&aoh, g_aoh);
    cudaGetSymbolAddress((void**)&Sp,  g_S);

    cudaFuncSetAttribute(gemm_qkv, cudaFuncAttributeMaxDynamicSharedMemorySize, GEMM_SMEM);
    cudaFuncSetAttribute(gemm_f16, cudaFuncAttributeMaxDynamicSharedMemorySize, GEMM_SMEM);

    const float scale = 1.0f / 32.0f;

    // #1: round x to fp16
    round_kernel<<<2048, 256>>>(x, xr, (size_t)Mm * Dd);
    // #2: all four weight transposes in one launch
    dim3 tb(32, 8), tg4(Dd / 32, Dd / 32, 4);
    transpose4_kernel<<<tg4, tb>>>(Wq, wqt, Wk, wkt, Wv, wvt, Wo, wot);

    // #3: combined QKV projection (single-pass fp16)
    dim3 gQKV(12, Mm / TM_CTA, 1);
    gemm_qkv<<<gQKV, 256, GEMM_SMEM>>>(xr, wqt, wkt, wvt, bq, bk, bv, qh, kh, vt);

    // #4: scores (single-pass), per-batch 2048x2048, K=1024, causal skip, *1/32
    dim3 gSc(Sq / TN_CTA, Sq / TM_CTA, Bn);
    gemm_f16<<<gSc, 256, GEMM_SMEM>>>(qh, kh, Dd,
        (long)Sq * Dd, (long)Sq * Dd, nullptr,
        Sp, nullptr, (long)Sq * Sq, Sq, scale, 1, 0);

    // #5: softmax
    softmax_causal<<<Mm, 256>>>(Sp, phv);

    // #6 (ncu capture slot): PV single-pass, K causally bounded, heavy first
    dim3 gPV(Dd / TN_CTA, Sq / TM_CTA, Bn);
    gemm_f16<<<gPV, 256, GEMM_SMEM>>>(phv, vt, Sq,
        (long)Sq * Sq, (long)Dd * Sq, nullptr,
        nullptr, aoh, (long)Sq * Dd, Dd, 1.f, 2, 1);

    // #7: out projection (single-pass), fp32 out + bias
    dim3 gProj(Dd / TN_CTA, Mm / TM_CTA, 1);
    gemm_f16<<<gProj, 256, GEMM_SMEM>>>(aoh, wot, Dd, 0, 0, bo,
        out, nullptr, 0, Dd, 1.f, 0, 0);
}

// round 10
// speedup vs baseline: 2.7075x; 1.1073x over previous
#include <cuda_runtime.h>
#include <cuda_fp16.h>
#include <cstdint>

// SingleSelfHeadAttention b=4, s=2048, d=1024, causal, fp32 I/O.
// R10: 128x128 CTA tiles @ 128 threads (64x64 warp tiles), 2 CTAs/SM,
//      3-stage cp.async. All GEMMs single-pass fp16 HMMA, fp32 accum.

static constexpr int Bn = 4;
static constexpr int Sq = 2048;
static constexpr int Dd = 1024;
static constexpr int Mm = Bn * Sq;          // 8192

// ---------------- device scratch ----------------
__device__ __half g_xr [(size_t)Mm * Dd];
__device__ __half g_wqt[(size_t)Dd * Dd], g_wkt[(size_t)Dd * Dd];
__device__ __half g_wvt[(size_t)Dd * Dd], g_wot[(size_t)Dd * Dd];
__device__ __half g_qh[(size_t)Mm * Dd];
__device__ __half g_kh[(size_t)Mm * Dd];
__device__ __half g_vt[(size_t)Bn * Dd * Sq];
__device__ float  g_S [(size_t)Bn * Sq * Sq];
__device__ __half g_ph[(size_t)Bn * Sq * Sq];
__device__ __half g_aoh[(size_t)Mm * Dd];

// ---------------- PTX helpers ----------------
__device__ __forceinline__ uint32_t smem_u32(const void* p) {
    uint32_t a;
    asm("{ .reg .u64 t; cvta.to.shared.u64 t, %1; cvt.u32.u64 %0, t; }" : "=r"(a) : "l"(p));
    return a;
}
#define CP_ASYNC16(dst, src) \
    asm volatile("cp.async.cg.shared.global [%0], [%1], 16;" :: "r"(dst), "l"(src))
#define CP_COMMIT() asm volatile("cp.async.commit_group;" ::: "memory")
#define CP_WAIT2()  asm volatile("cp.async.wait_group 2;" ::: "memory")

__device__ __forceinline__ void ldsm_x4(uint32_t* r, uint32_t addr) {
    asm volatile("ldmatrix.sync.aligned.m8n8.x4.shared.b16 {%0,%1,%2,%3}, [%4];"
        : "=r"(r[0]), "=r"(r[1]), "=r"(r[2]), "=r"(r[3]) : "r"(addr));
}
__device__ __forceinline__ void mma_f16(float* c, const uint32_t* a, const uint32_t* b) {
    asm volatile("mma.sync.aligned.m16n8k16.row.col.f32.f16.f16.f32 "
        "{%0,%1,%2,%3}, {%4,%5,%6,%7}, {%8,%9}, {%0,%1,%2,%3};"
        : "+f"(c[0]), "+f"(c[1]), "+f"(c[2]), "+f"(c[3])
        : "r"(a[0]), "r"(a[1]), "r"(a[2]), "r"(a[3]), "r"(b[0]), "r"(b[1]));
}
__device__ __forceinline__ uint32_t swz(uint32_t off) {   // 128B-row XOR swizzle
    return off ^ ((off >> 3) & 0x70);
}

// ---------------- prep kernels ----------------
__global__ void round_kernel(const float* __restrict__ src,
                             __half* __restrict__ dst, size_t n) {
    size_t i = (size_t)blockIdx.x * blockDim.x + threadIdx.x;
    size_t stride = (size_t)gridDim.x * blockDim.x;
    for (; i < n; i += stride) dst[i] = __float2half_rn(src[i]);
}

// All four W [Dd][Dd] -> Wt[n][k] = W[k][n], fp16; grid.z selects the pair.
__global__ void transpose4_kernel(const float* __restrict__ W0, __half* __restrict__ T0,
                                  const float* __restrict__ W1, __half* __restrict__ T1,
                                  const float* __restrict__ W2, __half* __restrict__ T2,
                                  const float* __restrict__ W3, __half* __restrict__ T3) {
    const float* W = (blockIdx.z == 0) ? W0 : (blockIdx.z == 1) ? W1
                   : (blockIdx.z == 2) ? W2 : W3;
    __half* T = (blockIdx.z == 0) ? T0 : (blockIdx.z == 1) ? T1
              : (blockIdx.z == 2) ? T2 : T3;
    __shared__ float tile[32][33];
    int bx = blockIdx.x * 32, by = blockIdx.y * 32;
    int tx = threadIdx.x, ty = threadIdx.y;
    #pragma unroll
    for (int j = 0; j < 4; j++)
        tile[ty + 8 * j][tx] = W[(size_t)(by + ty + 8 * j) * Dd + bx + tx];
    __syncthreads();
    #pragma unroll
    for (int j = 0; j < 4; j++) {
        float v = tile[tx][ty + 8 * j];
        size_t o = (size_t)(bx + ty + 8 * j) * Dd + by + tx;
        T[o] = __float2half_rn(v);
    }
}

// causal softmax on S rows; writes fp16 probs, zero-pads to 128-mult
__global__ __launch_bounds__(256)
void softmax_causal(float* __restrict__ Sm, __half* __restrict__ ph) {
    const int gq = blockIdx.x;
    const int q  = gq & (Sq - 1);
    float* row = Sm + (size_t)gq * Sq;
    __half* hrow = ph + (size_t)gq * Sq;
    const int len = q + 1;
    const int tid = threadIdx.x;
    __shared__ float red[256];

    float m = -1e30f;
    for (int j = tid; j < len; j += 256) m = fmaxf(m, row[j]);
    red[tid] = m; __syncthreads();
    for (int s = 128; s > 0; s >>= 1) {
        if (tid < s) red[tid] = fmaxf(red[tid], red[tid + s]);
        __syncthreads();
    }
    m = red[0]; __syncthreads();

    float sum = 0.f;
    for (int j = tid; j < len; j += 256) {
        float e = __expf(row[j] - m);
        row[j] = e; sum += e;
    }
    red[tid] = sum; __syncthreads();
    for (int s = 128; s > 0; s >>= 1) {
        if (tid < s) red[tid] += red[tid + s];
        __syncthreads();
    }
    const float inv = 1.0f / red[0];

    for (int j = tid; j < len; j += 256)
        hrow[j] = __float2half_rn(row[j] * inv);
    const int jend = ((q >> 7) + 1) << 7;
    const __half z = __float2half(0.f);
    for (int j = len + tid; j < jend; j += 256) hrow[j] = z;
}

// ---------------- GEMM config: 128x128 tile, 128 threads ----------------
#define TM_CTA 128
#define TN_CTA 128
#define NTHR   128
#define A_TILE (TM_CTA * 128)            // 16384 B (128 rows x 64 fp16)
#define STAGE  (2 * A_TILE)              // 32768 (A + B)
#define NSTAGE 3
#define GEMM_SMEM (NSTAGE * STAGE)       // 98304 -> 2 CTAs/SM

// 128 rows x 8 16B-chunks, 128 threads -> 8 cp.async each
__device__ __forceinline__ void load_T_async(uint32_t dst, const __half* src,
                                             int ldK, int tid) {
    #pragma unroll
    for (int j = 0; j < 8; j++) {
        int s = tid + j * NTHR;
        int r = s >> 3, c = s & 7;
        CP_ASYNC16(dst + swz(r * 128 + c * 16), src + (size_t)r * ldK + c * 8);
    }
}

// ================= QKV combined single-pass GEMM =================
// grid.x in [0,24): wsel = x>>3 chooses {Q,K,V}; bxx = x&7 is the 128-col tile.
__global__ __launch_bounds__(NTHR, 2)
void gemm_qkv(const __half* __restrict__ xr,
              const __half* __restrict__ wq, const __half* __restrict__ wk,
              const __half* __restrict__ wv,
              const float* __restrict__ bq, const float* __restrict__ bk,
              const float* __restrict__ bv,
              __half* __restrict__ qh, __half* __restrict__ kh,
              __half* __restrict__ vt)
{
    const int bxx = blockIdx.x & 7;
    const int wsel = blockIdx.x >> 3;
    const int by = blockIdx.y;
    const __half* Bw  = (wsel == 0) ? wq : (wsel == 1) ? wk : wv;
    const float* bias = (wsel == 0) ? bq : (wsel == 1) ? bk : bv;

    extern __shared__ __align__(16) char smem[];
    const uint32_t sb = smem_u32(smem);

    const int tid  = threadIdx.x;
    const int lane = tid & 31;
    const int wid  = tid >> 5;
    const int wm   = wid >> 1;                    // 0..1
    const int wn   = wid & 1;                     // 0..1

    const __half* pA = xr + (size_t)by * TM_CTA * Dd;
    const __half* pB = Bw + (size_t)bxx * TN_CTA * Dd;

    float acc[4][8][4] = {};
    const int nchunk = Dd >> 6;                   // 16

    #pragma unroll
    for (int p = 0; p < NSTAGE; p++) {
        const size_t ko = (size_t)p << 6;
        uint32_t st = sb + p * STAGE;
        load_T_async(st, pA + ko, Dd, tid);
        load_T_async(st + A_TILE, pB + ko, Dd, tid);
        CP_COMMIT();
    }

    const uint32_t arow = (lane & 7) + ((lane & 8)  ? 8 : 0);
    const uint32_t acol = (lane & 16) ? 16u : 0u;
    const uint32_t brow = (lane & 7) + ((lane & 16) ? 8 : 0);
    const uint32_t bcol = (lane & 8)  ? 16u : 0u;

    for (int c = 0; c < nchunk; ++c) {
        CP_WAIT2();
        __syncthreads();
        const uint32_t base = sb + (c % NSTAGE) * STAGE;

        #pragma unroll
        for (int ks = 0; ks < 4; ks++) {
            const uint32_t kb = ks * 32;
            uint32_t ah[4][4];
            #pragma unroll
            for (int i = 0; i < 4; i++) {
                uint32_t off = swz((wm * 64 + i * 16 + arow) * 128 + kb + acol);
                ldsm_x4(ah[i], base + off);
            }
            #pragma unroll
            for (int j2 = 0; j2 < 4; j2++) {
                uint32_t off = swz((wn * 64 + j2 * 16 + brow) * 128 + kb + bcol);
                uint32_t th[4];
                ldsm_x4(th, base + A_TILE + off);
                const int j0 = j2 * 2, j1 = j2 * 2 + 1;
                #pragma unroll
                for (int i = 0; i < 4; i++) {
                    mma_f16(acc[i][j0], ah[i], &th[0]);
                    mma_f16(acc[i][j1], ah[i], &th[2]);
                }
            }
        }

        __syncthreads();
        if (c + NSTAGE < nchunk) {
            const size_t ko = (size_t)(c + NSTAGE) << 6;
            uint32_t st = sb + (c % NSTAGE) * STAGE;
            load_T_async(st, pA + ko, Dd, tid);
            load_T_async(st + A_TILE, pB + ko, Dd, tid);
        }
        CP_COMMIT();
    }

    const int m_base = by * TM_CTA + wm * 64;
    const int n_base = bxx * TN_CTA + wn * 64;
    const int rr = lane >> 2;
    const int cc = 2 * (lane & 3);

    #pragma unroll
    for (int i = 0; i < 4; i++) {
        #pragma unroll
        for (int j = 0; j < 8; j++) {
            const int col = n_base + j * 8 + cc;
            #pragma unroll
            for (int h = 0; h < 2; h++) {
                const int row = m_base + i * 16 + rr + h * 8;
                float v0 = acc[i][j][2 * h + 0] + __ldg(&bias[col]);
                float v1 = acc[i][j][2 * h + 1] + __ldg(&bias[col + 1]);
                if (wsel == 0) {
                    size_t o = (size_t)row * Dd + col;
                    *(__half2*)(qh + o) =
                        __halves2half2(__float2half_rn(v0), __float2half_rn(v1));
                } else if (wsel == 1) {
                    size_t o = (size_t)row * Dd + col;
                    *(__half2*)(kh + o) =
                        __halves2half2(__float2half_rn(v0), __float2half_rn(v1));
                } else {
                    const long z2 = row >> 11;
                    const long mloc = row & (Sq - 1);
                    size_t o0 = ((size_t)z2 * Dd + col) * Sq + mloc;
                    size_t o1 = ((size_t)z2 * Dd + col + 1) * Sq + mloc;
                    vt[o0] = __float2half_rn(v0);
                    vt[o1] = __float2half_rn(v1);
                }
            }
        }
    }
}

// ================= generic single-pass fp16 GEMM =================
// modes: 0 = fp32 out (+bias, *scale); 1 = fp16 out
__global__ __launch_bounds__(NTHR, 2)
void gemm_f16(const __half* __restrict__ Ah, const __half* __restrict__ Bh,
              int Kdim, long sAz, long sBz,
              const float* __restrict__ bias,
              float* __restrict__ outF, __half* __restrict__ outH,
              long sOz, int ldOut, float scale, int causal, int mode)
{
    const int bx = blockIdx.x, z = blockIdx.z;
    const int by = (causal == 2) ? ((int)gridDim.y - 1 - (int)blockIdx.y)
                                 : (int)blockIdx.y;
    if (causal == 1 && bx > by) return;           // tile-exact causal skip
    const int kend = (causal == 2) ? (by + 1) * 128 : Kdim;
    const int nchunk = kend >> 6;

    extern __shared__ __align__(16) char smem[];
    const uint32_t sb = smem_u32(smem);

    const int tid  = threadIdx.x;
    const int lane = tid & 31;
    const int wid  = tid >> 5;
    const int wm   = wid >> 1;
    const int wn   = wid & 1;

    const __half* pAh = Ah + (size_t)z * sAz + (size_t)by * TM_CTA * Kdim;
    const __half* pBh = Bh + (size_t)z * sBz + (size_t)bx * TN_CTA * Kdim;

    float acc[4][8][4] = {};

    #pragma unroll
    for (int p = 0; p < NSTAGE; p++) {
        if (p < nchunk) {
            const size_t ko = (size_t)p << 6;
            uint32_t st = sb + p * STAGE;
            load_T_async(st, pAh + ko, Kdim, tid);
            load_T_async(st + A_TILE, pBh + ko, Kdim, tid);
        }
        CP_COMMIT();
    }

    const uint32_t arow = (lane & 7) + ((lane & 8)  ? 8 : 0);
    const uint32_t acol = (lane & 16) ? 16u : 0u;
    const uint32_t brow = (lane & 7) + ((lane & 16) ? 8 : 0);
    const uint32_t bcol = (lane & 8)  ? 16u : 0u;

    for (int c = 0; c < nchunk; ++c) {
        CP_WAIT2();
        __syncthreads();
        const uint32_t base = sb + (c % NSTAGE) * STAGE;

        #pragma unroll
        for (int ks = 0; ks < 4; ks++) {
            const uint32_t kb = ks * 32;
            uint32_t ah[4][4];
            #pragma unroll
            for (int i = 0; i < 4; i++) {
                uint32_t off = swz((wm * 64 + i * 16 + arow) * 128 + kb + acol);
                ldsm_x4(ah[i], base + off);
            }
            #pragma unroll
            for (int j2 = 0; j2 < 4; j2++) {
                uint32_t off = swz((wn * 64 + j2 * 16 + brow) * 128 + kb + bcol);
                uint32_t th[4];
                ldsm_x4(th, base + A_TILE + off);
                const int j0 = j2 * 2, j1 = j2 * 2 + 1;
                #pragma unroll
                for (int i = 0; i < 4; i++) {
                    mma_f16(acc[i][j0], ah[i], &th[0]);
                    mma_f16(acc[i][j1], ah[i], &th[2]);
                }
            }
        }

        __syncthreads();
        if (c + NSTAGE < nchunk) {
            const size_t ko = (size_t)(c + NSTAGE) << 6;
            uint32_t st = sb + (c % NSTAGE) * STAGE;
            load_T_async(st, pAh + ko, Kdim, tid);
            load_T_async(st + A_TILE, pBh + ko, Kdim, tid);
        }
        CP_COMMIT();
    }

    const int m_base = by * TM_CTA + wm * 64;
    const int n_base = bx * TN_CTA + wn * 64;
    const int rr = lane >> 2;
    const int cc = 2 * (lane & 3);

    #pragma unroll
    for (int i = 0; i < 4; i++) {
        #pragma unroll
        for (int j = 0; j < 8; j++) {
            const int col = n_base + j * 8 + cc;
            #pragma unroll
            for (int h = 0; h < 2; h++) {
                const int row = m_base + i * 16 + rr + h * 8;
                float v0 = acc[i][j][2 * h + 0];
                float v1 = acc[i][j][2 * h + 1];
                if (mode == 0) {
                    v0 *= scale; v1 *= scale;
                    if (bias) { v0 += __ldg(&bias[col]); v1 += __ldg(&bias[col + 1]); }
                    float2 o = make_float2(v0, v1);
                    *(float2*)(outF + (size_t)z * sOz + (size_t)row * ldOut + col) = o;
                } else {
                    size_t o = (size_t)z * sOz + (size_t)row * ldOut + col;
                    *(__half2*)(outH + o) =
                        __halves2half2(__float2half_rn(v0), __float2half_rn(v1));
                }
            }
        }
    }
}

// ---------------- launch ----------------
extern "C" void kernel_launch(void* const* d_in, const int* in_sizes, int n_in,
                              void* d_out, int out_size)
{
    const float* x  = (const float*)d_in[0];
    const float* Wq = (const float*)d_in[1];
    const float* bq = (const float*)d_in[2];
    const float* Wk = (const float*)d_in[3];
    const float* bk = (const float*)d_in[4];
    const float* Wv = (const float*)d_in[5];
    const float* bv = (const float*)d_in[6];
    const float* Wo = (const float*)d_in[7];
    const float* bo = (const float*)d_in[8];
    float* out = (float*)d_out;

    __half *xr, *wqt, *wkt, *wvt, *wot, *qh, *kh, *vt, *phv, *aoh;
    float* Sp;
    cudaGetSymbolAddress((void**)&xr,  g_xr);
    cudaGetSymbolAddress((void**)&wqt, g_wqt);  cudaGetSymbolAddress((void**)&wkt, g_wkt);
    cudaGetSymbolAddress((void**)&wvt, g_wvt);  cudaGetSymbolAddress((void**)&wot, g_wot);
    cudaGetSymbolAddress((void**)&qh,  g_qh);
    cudaGetSymbolAddress((void**)&kh,  g_kh);
    cudaGetSymbolAddress((void**)&vt,  g_vt);
    cudaGetSymbolAddress((void**)&phv, g_ph);
    cudaGetSymbolAddress((void**)&aoh, g_aoh);
    cudaGetSymbolAddress((void**)&Sp,  g_S);

    cudaFuncSetAttribute(gemm_qkv, cudaFuncAttributeMaxDynamicSharedMemorySize, GEMM_SMEM);
    cudaFuncSetAttribute(gemm_f16, cudaFuncAttributeMaxDynamicSharedMemorySize, GEMM_SMEM);

    const float scale = 1.0f / 32.0f;

    // #1: round x to fp16
    round_kernel<<<2048, 256>>>(x, xr, (size_t)Mm * Dd);
    // #2: all four weight transposes in one launch
    dim3 tb(32, 8), tg4(Dd / 32, Dd / 32, 4);
    transpose4_kernel<<<tg4, tb>>>(Wq, wqt, Wk, wkt, Wv, wvt, Wo, wot);

    // #3: combined QKV projection
    dim3 gQKV(24, Mm / TM_CTA, 1);                // 24 x 64
    gemm_qkv<<<gQKV, NTHR, GEMM_SMEM>>>(xr, wqt, wkt, wvt, bq, bk, bv, qh, kh, vt);

    // #4: scores, per-batch 2048x2048, K=1024, tile-exact causal skip, *1/32
    dim3 gSc(Sq / TN_CTA, Sq / TM_CTA, Bn);       // 16 x 16 x 4
    gemm_f16<<<gSc, NTHR, GEMM_SMEM>>>(qh, kh, Dd,
        (long)Sq * Dd, (long)Sq * Dd, nullptr,
        Sp, nullptr, (long)Sq * Sq, Sq, scale, 1, 0);

    // #5: softmax
    softmax_causal<<<Mm, 256>>>(Sp, phv);

    // #6 (ncu capture slot): PV, K causally bounded, heavy tiles first
    dim3 gPV(Dd / TN_CTA, Sq / TM_CTA, Bn);       // 8 x 16 x 4
    gemm_f16<<<gPV, NTHR, GEMM_SMEM>>>(phv, vt, Sq,
        (long)Sq * Sq, (long)Dd * Sq, nullptr,
        nullptr, aoh, (long)Sq * Dd, Dd, 1.f, 2, 1);

    // #7: out projection, fp32 out + bias
    dim3 gProj(Dd / TN_CTA, Mm / TM_CTA, 1);      // 8 x 64
    gemm_f16<<<gProj, NTHR, GEMM_SMEM>>>(aoh, wot, Dd, 0, 0, bo,
        out, nullptr, 0, Dd, 1.f, 0, 0);
}

// round 11
// speedup vs baseline: 2.8743x; 1.0616x over previous
#include <cuda_runtime.h>
#include <cuda_fp16.h>
#include <cstdint>

// SingleSelfHeadAttention b=4, s=2048, d=1024, causal, fp32 I/O.
// R11: associativity swap out = P·(V·Wo); slim register-cached softmax;
//      6 launches. 128x128 tiles @128thr, 2 CTAs/SM, single-pass fp16 HMMA.

static constexpr int Bn = 4;
static constexpr int Sq = 2048;
static constexpr int Dd = 1024;
static constexpr int Mm = Bn * Sq;          // 8192

// ---------------- device scratch ----------------
__device__ __half g_xr [(size_t)Mm * Dd];
__device__ __half g_wqt[(size_t)Dd * Dd], g_wkt[(size_t)Dd * Dd];
__device__ __half g_wvt[(size_t)Dd * Dd], g_wot[(size_t)Dd * Dd];
__device__ __half g_qh[(size_t)Mm * Dd];
__device__ __half g_kh[(size_t)Mm * Dd];
__device__ __half g_vh[(size_t)Mm * Dd];
__device__ __half g_vwot[(size_t)Bn * Dd * Sq];   // (V·Wo)^T per batch [d'][s]
__device__ float  g_S [(size_t)Bn * Sq * Sq];
__device__ __half g_ph[(size_t)Bn * Sq * Sq];

// ---------------- PTX helpers ----------------
__device__ __forceinline__ uint32_t smem_u32(const void* p) {
    uint32_t a;
    asm("{ .reg .u64 t; cvta.to.shared.u64 t, %1; cvt.u32.u64 %0, t; }" : "=r"(a) : "l"(p));
    return a;
}
#define CP_ASYNC16(dst, src) \
    asm volatile("cp.async.cg.shared.global [%0], [%1], 16;" :: "r"(dst), "l"(src))
#define CP_COMMIT() asm volatile("cp.async.commit_group;" ::: "memory")
#define CP_WAIT2()  asm volatile("cp.async.wait_group 2;" ::: "memory")

__device__ __forceinline__ void ldsm_x4(uint32_t* r, uint32_t addr) {
    asm volatile("ldmatrix.sync.aligned.m8n8.x4.shared.b16 {%0,%1,%2,%3}, [%4];"
        : "=r"(r[0]), "=r"(r[1]), "=r"(r[2]), "=r"(r[3]) : "r"(addr));
}
__device__ __forceinline__ void mma_f16(float* c, const uint32_t* a, const uint32_t* b) {
    asm volatile("mma.sync.aligned.m16n8k16.row.col.f32.f16.f16.f32 "
        "{%0,%1,%2,%3}, {%4,%5,%6,%7}, {%8,%9}, {%0,%1,%2,%3};"
        : "+f"(c[0]), "+f"(c[1]), "+f"(c[2]), "+f"(c[3])
        : "r"(a[0]), "r"(a[1]), "r"(a[2]), "r"(a[3]), "r"(b[0]), "r"(b[1]));
}
__device__ __forceinline__ uint32_t swz(uint32_t off) {   // 128B-row XOR swizzle
    return off ^ ((off >> 3) & 0x70);
}

// ---------------- prep: weight transposes (z<4) + x rounding (z==4) --------
__global__ void prep_kernel(const float* __restrict__ x, __half* __restrict__ xr,
                            const float* __restrict__ W0, __half* __restrict__ T0,
                            const float* __restrict__ W1, __half* __restrict__ T1,
                            const float* __restrict__ W2, __half* __restrict__ T2,
                            const float* __restrict__ W3, __half* __restrict__ T3) {
    if (blockIdx.z == 4) {
        size_t i = ((size_t)(blockIdx.y * gridDim.x + blockIdx.x) * 256
                   + threadIdx.y * 32 + threadIdx.x);
        size_t stride = (size_t)gridDim.x * gridDim.y * 256;
        const size_t n = (size_t)Mm * Dd;
        for (; i < n; i += stride) xr[i] = __float2half_rn(x[i]);
        return;
    }
    const float* W = (blockIdx.z == 0) ? W0 : (blockIdx.z == 1) ? W1
                   : (blockIdx.z == 2) ? W2 : W3;
    __half* T = (blockIdx.z == 0) ? T0 : (blockIdx.z == 1) ? T1
              : (blockIdx.z == 2) ? T2 : T3;
    __shared__ float tile[32][33];
    int bx = blockIdx.x * 32, by = blockIdx.y * 32;
    int tx = threadIdx.x, ty = threadIdx.y;
    #pragma unroll
    for (int j = 0; j < 4; j++)
        tile[ty + 8 * j][tx] = W[(size_t)(by + ty + 8 * j) * Dd + bx + tx];
    __syncthreads();
    #pragma unroll
    for (int j = 0; j < 4; j++) {
        float v = tile[tx][ty + 8 * j];
        size_t o = (size_t)(bx + ty + 8 * j) * Dd + by + tx;
        T[o] = __float2half_rn(v);
    }
}

// causal softmax; exp values cached in registers; writes fp16 P only.
__global__ __launch_bounds__(256)
void softmax_causal(const float* __restrict__ Sm, __half* __restrict__ ph) {
    const int gq = blockIdx.x;
    const int q  = gq & (Sq - 1);
    const float* row = Sm + (size_t)gq * Sq;
    __half* hrow = ph + (size_t)gq * Sq;
    const int len = q + 1;
    const int tid = threadIdx.x;
    __shared__ float red[256];

    float m = -1e30f;
    for (int j = tid; j < len; j += 256) m = fmaxf(m, row[j]);
    red[tid] = m; __syncthreads();
    for (int s = 128; s > 0; s >>= 1) {
        if (tid < s) red[tid] = fmaxf(red[tid], red[tid + s]);
        __syncthreads();
    }
    m = red[0]; __syncthreads();

    float ev[8];
    float sum = 0.f;
    int c = 0;
    for (int j = tid; j < len; j += 256) {
        float e = __expf(row[j] - m);
        ev[c++] = e; sum += e;
    }
    red[tid] = sum; __syncthreads();
    for (int s = 128; s > 0; s >>= 1) {
        if (tid < s) red[tid] += red[tid + s];
        __syncthreads();
    }
    const float inv = 1.0f / red[0];

    c = 0;
    for (int j = tid; j < len; j += 256)
        hrow[j] = __float2half_rn(ev[c++] * inv);
    const int jend = ((q >> 7) + 1) << 7;
    const __half z = __float2half(0.f);
    for (int j = len + tid; j < jend; j += 256) hrow[j] = z;
}

// ---------------- GEMM config: 128x128 tile, 128 threads ----------------
#define TM_CTA 128
#define TN_CTA 128
#define NTHR   128
#define A_TILE (TM_CTA * 128)            // 16384 B (128 rows x 64 fp16)
#define STAGE  (2 * A_TILE)              // 32768 (A + B)
#define NSTAGE 3
#define GEMM_SMEM (NSTAGE * STAGE)       // 98304 -> 2 CTAs/SM

__device__ __forceinline__ void load_T_async(uint32_t dst, const __half* src,
                                             int ldK, int tid) {
    #pragma unroll
    for (int j = 0; j < 8; j++) {
        int s = tid + j * NTHR;
        int r = s >> 3, c = s & 7;
        CP_ASYNC16(dst + swz(r * 128 + c * 16), src + (size_t)r * ldK + c * 8);
    }
}

// ================= QKV combined single-pass GEMM =================
// grid.x in [0,24): wsel = x>>3 chooses {Q,K,V}; bxx = x&7 is the 128-col tile.
// All outputs row-major [8192, 1024] fp16 (+bias).
__global__ __launch_bounds__(NTHR, 2)
void gemm_qkv(const __half* __restrict__ xr,
              const __half* __restrict__ wq, const __half* __restrict__ wk,
              const __half* __restrict__ wv,
              const float* __restrict__ bq, const float* __restrict__ bk,
              const float* __restrict__ bv,
              __half* __restrict__ qh, __half* __restrict__ kh,
              __half* __restrict__ vh)
{
    const int bxx = blockIdx.x & 7;
    const int wsel = blockIdx.x >> 3;
    const int by = blockIdx.y;
    const __half* Bw  = (wsel == 0) ? wq : (wsel == 1) ? wk : wv;
    const float* bias = (wsel == 0) ? bq : (wsel == 1) ? bk : bv;
    __half* outp      = (wsel == 0) ? qh : (wsel == 1) ? kh : vh;

    extern __shared__ __align__(16) char smem[];
    const uint32_t sb = smem_u32(smem);

    const int tid  = threadIdx.x;
    const int lane = tid & 31;
    const int wid  = tid >> 5;
    const int wm   = wid >> 1;
    const int wn   = wid & 1;

    const __half* pA = xr + (size_t)by * TM_CTA * Dd;
    const __half* pB = Bw + (size_t)bxx * TN_CTA * Dd;

    float acc[4][8][4] = {};
    const int nchunk = Dd >> 6;                   // 16

    #pragma unroll
    for (int p = 0; p < NSTAGE; p++) {
        const size_t ko = (size_t)p << 6;
        uint32_t st = sb + p * STAGE;
        load_T_async(st, pA + ko, Dd, tid);
        load_T_async(st + A_TILE, pB + ko, Dd, tid);
        CP_COMMIT();
    }

    const uint32_t arow = (lane & 7) + ((lane & 8)  ? 8 : 0);
    const uint32_t acol = (lane & 16) ? 16u : 0u;
    const uint32_t brow = (lane & 7) + ((lane & 16) ? 8 : 0);
    const uint32_t bcol = (lane & 8)  ? 16u : 0u;

    for (int c = 0; c < nchunk; ++c) {
        CP_WAIT2();
        __syncthreads();
        const uint32_t base = sb + (c % NSTAGE) * STAGE;

        #pragma unroll
        for (int ks = 0; ks < 4; ks++) {
            const uint32_t kb = ks * 32;
            uint32_t ah[4][4];
            #pragma unroll
            for (int i = 0; i < 4; i++) {
                uint32_t off = swz((wm * 64 + i * 16 + arow) * 128 + kb + acol);
                ldsm_x4(ah[i], base + off);
            }
            #pragma unroll
            for (int j2 = 0; j2 < 4; j2++) {
                uint32_t off = swz((wn * 64 + j2 * 16 + brow) * 128 + kb + bcol);
                uint32_t th[4];
                ldsm_x4(th, base + A_TILE + off);
                const int j0 = j2 * 2, j1 = j2 * 2 + 1;
                #pragma unroll
                for (int i = 0; i < 4; i++) {
                    mma_f16(acc[i][j0], ah[i], &th[0]);
                    mma_f16(acc[i][j1], ah[i], &th[2]);
                }
            }
        }

        __syncthreads();
        if (c + NSTAGE < nchunk) {
            const size_t ko = (size_t)(c + NSTAGE) << 6;
            uint32_t st = sb + (c % NSTAGE) * STAGE;
            load_T_async(st, pA + ko, Dd, tid);
            load_T_async(st + A_TILE, pB + ko, Dd, tid);
        }
        CP_COMMIT();
    }

    const int m_base = by * TM_CTA + wm * 64;
    const int n_base = bxx * TN_CTA + wn * 64;
    const int rr = lane >> 2;
    const int cc = 2 * (lane & 3);

    #pragma unroll
    for (int i = 0; i < 4; i++) {
        #pragma unroll
        for (int j = 0; j < 8; j++) {
            const int col = n_base + j * 8 + cc;
            #pragma unroll
            for (int h = 0; h < 2; h++) {
                const int row = m_base + i * 16 + rr + h * 8;
                float v0 = acc[i][j][2 * h + 0] + __ldg(&bias[col]);
                float v1 = acc[i][j][2 * h + 1] + __ldg(&bias[col + 1]);
                size_t o = (size_t)row * Dd + col;
                *(__half2*)(outp + o) =
                    __halves2half2(__float2half_rn(v0), __float2half_rn(v1));
            }
        }
    }
}

// ================= generic single-pass fp16 GEMM =================
// modes: 0 = fp32 out (+bias, *scale); 1 = fp16 out
__global__ __launch_bounds__(NTHR, 2)
void gemm_f16(const __half* __restrict__ Ah, const __half* __restrict__ Bh,
              int Kdim, long sAz, long sBz,
              const float* __restrict__ bias,
              float* __restrict__ outF, __half* __restrict__ outH,
              long sOz, int ldOut, float scale, int causal, int mode)
{
    const int bx = blockIdx.x, z = blockIdx.z;
    const int by = (causal == 2) ? ((int)gridDim.y - 1 - (int)blockIdx.y)
                                 : (int)blockIdx.y;
    if (causal == 1 && bx > by) return;           // tile-exact causal skip
    const int kend = (causal == 2) ? (by + 1) * 128 : Kdim;
    const int nchunk = kend >> 6;

    extern __shared__ __align__(16) char smem[];
    const uint32_t sb = smem_u32(smem);

    const int tid  = threadIdx.x;
    const int lane = tid & 31;
    const int wid  = tid >> 5;
    const int wm   = wid >> 1;
    const int wn   = wid & 1;

    const __half* pAh = Ah + (size_t)z * sAz + (size_t)by * TM_CTA * Kdim;
    const __half* pBh = Bh + (size_t)z * sBz + (size_t)bx * TN_CTA * Kdim;

    float acc[4][8][4] = {};

    #pragma unroll
    for (int p = 0; p < NSTAGE; p++) {
        if (p < nchunk) {
            const size_t ko = (size_t)p << 6;
            uint32_t st = sb + p * STAGE;
            load_T_async(st, pAh + ko, Kdim, tid);
            load_T_async(st + A_TILE, pBh + ko, Kdim, tid);
        }
        CP_COMMIT();
    }

    const uint32_t arow = (lane & 7) + ((lane & 8)  ? 8 : 0);
    const uint32_t acol = (lane & 16) ? 16u : 0u;
    const uint32_t brow = (lane & 7) + ((lane & 16) ? 8 : 0);
    const uint32_t bcol = (lane & 8)  ? 16u : 0u;

    for (int c = 0; c < nchunk; ++c) {
        CP_WAIT2();
        __syncthreads();
        const uint32_t base = sb + (c % NSTAGE) * STAGE;

        #pragma unroll
        for (int ks = 0; ks < 4; ks++) {
            const uint32_t kb = ks * 32;
            uint32_t ah[4][4];
            #pragma unroll
            for (int i = 0; i < 4; i++) {
                uint32_t off = swz((wm * 64 + i * 16 + arow) * 128 + kb + acol);
                ldsm_x4(ah[i], base + off);
            }
            #pragma unroll
            for (int j2 = 0; j2 < 4; j2++) {
                uint32_t off = swz((wn * 64 + j2 * 16 + brow) * 128 + kb + bcol);
                uint32_t th[4];
                ldsm_x4(th, base + A_TILE + off);
                const int j0 = j2 * 2, j1 = j2 * 2 + 1;
                #pragma unroll
                for (int i = 0; i < 4; i++) {
                    mma_f16(acc[i][j0], ah[i], &th[0]);
                    mma_f16(acc[i][j1], ah[i], &th[2]);
                }
            }
        }

        __syncthreads();
        if (c + NSTAGE < nchunk) {
            const size_t ko = (size_t)(c + NSTAGE) << 6;
            uint32_t st = sb + (c % NSTAGE) * STAGE;
            load_T_async(st, pAh + ko, Kdim, tid);
            load_T_async(st + A_TILE, pBh + ko, Kdim, tid);
        }
        CP_COMMIT();
    }

    const int m_base = by * TM_CTA + wm * 64;
    const int n_base = bx * TN_CTA + wn * 64;
    const int rr = lane >> 2;
    const int cc = 2 * (lane & 3);

    #pragma unroll
    for (int i = 0; i < 4; i++) {
        #pragma unroll
        for (int j = 0; j < 8; j++) {
            const int col = n_base + j * 8 + cc;
            #pragma unroll
            for (int h = 0; h < 2; h++) {
                const int row = m_base + i * 16 + rr + h * 8;
                float v0 = acc[i][j][2 * h + 0];
                float v1 = acc[i][j][2 * h + 1];
                if (mode == 0) {
                    v0 *= scale; v1 *= scale;
                    if (bias) { v0 += __ldg(&bias[col]); v1 += __ldg(&bias[col + 1]); }
                    float2 o = make_float2(v0, v1);
                    *(float2*)(outF + (size_t)z * sOz + (size_t)row * ldOut + col) = o;
                } else {
                    size_t o = (size_t)z * sOz + (size_t)row * ldOut + col;
                    *(__half2*)(outH + o) =
                        __halves2half2(__float2half_rn(v0), __float2half_rn(v1));
                }
            }
        }
    }
}

// ---------------- launch ----------------
extern "C" void kernel_launch(void* const* d_in, const int* in_sizes, int n_in,
                              void* d_out, int out_size)
{
    const float* x  = (const float*)d_in[0];
    const float* Wq = (const float*)d_in[1];
    const float* bq = (const float*)d_in[2];
    const float* Wk = (const float*)d_in[3];
    const float* bk = (const float*)d_in[4];
    const float* Wv = (const float*)d_in[5];
    const float* bv = (const float*)d_in[6];
    const float* Wo = (const float*)d_in[7];
    const float* bo = (const float*)d_in[8];
    float* out = (float*)d_out;

    __half *xr, *wqt, *wkt, *wvt, *wot, *qh, *kh, *vh, *vwot, *phv;
    float* Sp;
    cudaGetSymbolAddress((void**)&xr,   g_xr);
    cudaGetSymbolAddress((void**)&wqt,  g_wqt);  cudaGetSymbolAddress((void**)&wkt, g_wkt);
    cudaGetSymbolAddress((void**)&wvt,  g_wvt);  cudaGetSymbolAddress((void**)&wot, g_wot);
    cudaGetSymbolAddress((void**)&qh,   g_qh);
    cudaGetSymbolAddress((void**)&kh,   g_kh);
    cudaGetSymbolAddress((void**)&vh,   g_vh);
    cudaGetSymbolAddress((void**)&vwot, g_vwot);
    cudaGetSymbolAddress((void**)&phv,  g_ph);
    cudaGetSymbolAddress((void**)&Sp,   g_S);

    cudaFuncSetAttribute(gemm_qkv, cudaFuncAttributeMaxDynamicSharedMemorySize, GEMM_SMEM);
    cudaFuncSetAttribute(gemm_f16, cudaFuncAttributeMaxDynamicSharedMemorySize, GEMM_SMEM);

    const float scale = 1.0f / 32.0f;

    // #1: prep — weight transposes (z<4) + x rounding (z==4)
    dim3 tb(32, 8), tgp(Dd / 32, Dd / 32, 5);
    prep_kernel<<<tgp, tb>>>(x, xr, Wq, wqt, Wk, wkt, Wv, wvt, Wo, wot);

    // #2: combined QKV projection (q, k, v all row-major fp16)
    dim3 gQKV(24, Mm / TM_CTA, 1);                // 24 x 64
    gemm_qkv<<<gQKV, NTHR, GEMM_SMEM>>>(xr, wqt, wkt, wvt, bq, bk, bv, qh, kh, vh);

    // #3: (V·Wo)^T per batch: C[d', s] = wot[d',:] · v[s,:]  (M=1024, N=2048, K=1024)
    dim3 gVW(Sq / TN_CTA, Dd / TM_CTA, Bn);       // 16 x 8 x 4
    gemm_f16<<<gVW, NTHR, GEMM_SMEM>>>(wot, vh, Dd,
        0, (long)Sq * Dd, nullptr,
        nullptr, vwot, (long)Dd * Sq, Sq, 1.f, 0, 1);

    // #4: scores, per-batch 2048x2048, K=1024, tile-exact causal skip, *1/32
    dim3 gSc(Sq / TN_CTA, Sq / TM_CTA, Bn);       // 16 x 16 x 4
    gemm_f16<<<gSc, NTHR, GEMM_SMEM>>>(qh, kh, Dd,
        (long)Sq * Dd, (long)Sq * Dd, nullptr,
        Sp, nullptr, (long)Sq * Sq, Sq, scale, 1, 0);

    // #5: softmax (register-cached, fp16 P out only)
    softmax_causal<<<Mm, 256>>>(Sp, phv);

    // #6 (ncu capture slot): out = P·(V·Wo)^T + bo, fp32, K causally bounded
    dim3 gPV(Dd / TN_CTA, Sq / TM_CTA, Bn);       // 8 x 16 x 4
    gemm_f16<<<gPV, NTHR, GEMM_SMEM>>>(phv, vwot, Sq,
        (long)Sq * Sq, (long)Dd * Sq, bo,
        out, nullptr, (long)Sq * Dd, Dd, 1.f, 2, 0);
}

// round 12
// speedup vs baseline: 2.8746x; 1.0001x over previous
#include <cuda_runtime.h>
#include <cuda_fp16.h>
#include <cstdint>

// SingleSelfHeadAttention b=4, s=2048, d=1024, causal, fp32 I/O.
// R12: single-barrier multistage cp.async pipeline (loads issued before MMAs);
//      scores+VWo merged into one launch. out = P·(V·Wo). Single-pass fp16 HMMA.

static constexpr int Bn = 4;
static constexpr int Sq = 2048;
static constexpr int Dd = 1024;
static constexpr int Mm = Bn * Sq;          // 8192

// ---------------- device scratch ----------------
__device__ __half g_xr [(size_t)Mm * Dd];
__device__ __half g_wqt[(size_t)Dd * Dd], g_wkt[(size_t)Dd * Dd];
__device__ __half g_wvt[(size_t)Dd * Dd], g_wot[(size_t)Dd * Dd];
__device__ __half g_qh[(size_t)Mm * Dd];
__device__ __half g_kh[(size_t)Mm * Dd];
__device__ __half g_vh[(size_t)Mm * Dd];
__device__ __half g_vwot[(size_t)Bn * Dd * Sq];   // (V·Wo)^T per batch [d'][s]
__device__ float  g_S [(size_t)Bn * Sq * Sq];
__device__ __half g_ph[(size_t)Bn * Sq * Sq];

// ---------------- PTX helpers ----------------
__device__ __forceinline__ uint32_t smem_u32(const void* p) {
    uint32_t a;
    asm("{ .reg .u64 t; cvta.to.shared.u64 t, %1; cvt.u32.u64 %0, t; }" : "=r"(a) : "l"(p));
    return a;
}
#define CP_ASYNC16(dst, src) \
    asm volatile("cp.async.cg.shared.global [%0], [%1], 16;" :: "r"(dst), "l"(src))
#define CP_COMMIT() asm volatile("cp.async.commit_group;" ::: "memory")
#define CP_WAIT1()  asm volatile("cp.async.wait_group 1;" ::: "memory")

__device__ __forceinline__ void ldsm_x4(uint32_t* r, uint32_t addr) {
    asm volatile("ldmatrix.sync.aligned.m8n8.x4.shared.b16 {%0,%1,%2,%3}, [%4];"
        : "=r"(r[0]), "=r"(r[1]), "=r"(r[2]), "=r"(r[3]) : "r"(addr));
}
__device__ __forceinline__ void mma_f16(float* c, const uint32_t* a, const uint32_t* b) {
    asm volatile("mma.sync.aligned.m16n8k16.row.col.f32.f16.f16.f32 "
        "{%0,%1,%2,%3}, {%4,%5,%6,%7}, {%8,%9}, {%0,%1,%2,%3};"
        : "+f"(c[0]), "+f"(c[1]), "+f"(c[2]), "+f"(c[3])
        : "r"(a[0]), "r"(a[1]), "r"(a[2]), "r"(a[3]), "r"(b[0]), "r"(b[1]));
}
__device__ __forceinline__ uint32_t swz(uint32_t off) {   // 128B-row XOR swizzle
    return off ^ ((off >> 3) & 0x70);
}

// ---------------- GEMM config: 128x128 tile, 128 threads ----------------
#define TM_CTA 128
#define TN_CTA 128
#define NTHR   128
#define A_TILE (TM_CTA * 128)            // 16384 B
#define STAGE  (2 * A_TILE)              // 32768
#define NSTAGE 3
#define GEMM_SMEM (NSTAGE * STAGE)       // 98304 -> 2 CTAs/SM

__device__ __forceinline__ void load_T_async(uint32_t dst, const __half* src,
                                             int ldK, int tid) {
    #pragma unroll
    for (int j = 0; j < 8; j++) {
        int s = tid + j * NTHR;
        int r = s >> 3, c = s & 7;
        CP_ASYNC16(dst + swz(r * 128 + c * 16), src + (size_t)r * ldK + c * 8);
    }
}

// Shared single-barrier multistage mainloop. acc[4][8][4] += A·B^T over nchunk*64 K.
__device__ __forceinline__ void mainloop(const __half* __restrict__ pA,
                                         const __half* __restrict__ pB,
                                         int ldA, int ldB, int nchunk,
                                         uint32_t sb, int tid, int lane,
                                         int wm, int wn, float acc[4][8][4])
{
    #pragma unroll
    for (int p = 0; p < 2; p++) {
        if (p < nchunk) {
            uint32_t st = sb + p * STAGE;
            load_T_async(st, pA + ((size_t)p << 6), ldA, tid);
            load_T_async(st + A_TILE, pB + ((size_t)p << 6), ldB, tid);
        }
        CP_COMMIT();
    }

    const uint32_t arow = (lane & 7) + ((lane & 8)  ? 8 : 0);
    const uint32_t acol = (lane & 16) ? 16u : 0u;
    const uint32_t brow = (lane & 7) + ((lane & 16) ? 8 : 0);
    const uint32_t bcol = (lane & 8)  ? 16u : 0u;

    for (int c = 0; c < nchunk; ++c) {
        CP_WAIT1();            // chunk c resident (c+1 may still be in flight)
        __syncthreads();       // all warps finished reading stage (c-1)%3

        // issue loads for chunk c+2 into stage (c+2)%3 == (c-1)%3 (safe now)
        if (c + 2 < nchunk) {
            uint32_t st = sb + ((c + 2) % NSTAGE) * STAGE;
            load_T_async(st, pA + ((size_t)(c + 2) << 6), ldA, tid);
            load_T_async(st + A_TILE, pB + ((size_t)(c + 2) << 6), ldB, tid);
        }
        CP_COMMIT();           // commit every iteration to keep FIFO counting exact

        const uint32_t base = sb + (c % NSTAGE) * STAGE;
        #pragma unroll
        for (int ks = 0; ks < 4; ks++) {
            const uint32_t kb = ks * 32;
            uint32_t ah[4][4];
            #pragma unroll
            for (int i = 0; i < 4; i++) {
                uint32_t off = swz((wm * 64 + i * 16 + arow) * 128 + kb + acol);
                ldsm_x4(ah[i], base + off);
            }
            #pragma unroll
            for (int j2 = 0; j2 < 4; j2++) {
                uint32_t off = swz((wn * 64 + j2 * 16 + brow) * 128 + kb + bcol);
                uint32_t th[4];
                ldsm_x4(th, base + A_TILE + off);
                const int j0 = j2 * 2, j1 = j2 * 2 + 1;
                #pragma unroll
                for (int i = 0; i < 4; i++) {
                    mma_f16(acc[i][j0], ah[i], &th[0]);
                    mma_f16(acc[i][j1], ah[i], &th[2]);
                }
            }
        }
    }
}

// ---------------- prep kernels ----------------
__global__ void round_kernel(const float* __restrict__ src,
                             __half* __restrict__ dst, size_t n) {
    size_t i = (size_t)blockIdx.x * blockDim.x + threadIdx.x;
    size_t stride = (size_t)gridDim.x * blockDim.x;
    for (; i < n; i += stride) dst[i] = __float2half_rn(src[i]);
}

__global__ void transpose4_kernel(const float* __restrict__ W0, __half* __restrict__ T0,
                                  const float* __restrict__ W1, __half* __restrict__ T1,
                                  const float* __restrict__ W2, __half* __restrict__ T2,
                                  const float* __restrict__ W3, __half* __restrict__ T3) {
    const float* W = (blockIdx.z == 0) ? W0 : (blockIdx.z == 1) ? W1
                   : (blockIdx.z == 2) ? W2 : W3;
    __half* T = (blockIdx.z == 0) ? T0 : (blockIdx.z == 1) ? T1
              : (blockIdx.z == 2) ? T2 : T3;
    __shared__ float tile[32][33];
    int bx = blockIdx.x * 32, by = blockIdx.y * 32;
    int tx = threadIdx.x, ty = threadIdx.y;
    #pragma unroll
    for (int j = 0; j < 4; j++)
        tile[ty + 8 * j][tx] = W[(size_t)(by + ty + 8 * j) * Dd + bx + tx];
    __syncthreads();
    #pragma unroll
    for (int j = 0; j < 4; j++) {
        float v = tile[tx][ty + 8 * j];
        size_t o = (size_t)(bx + ty + 8 * j) * Dd + by + tx;
        T[o] = __float2half_rn(v);
    }
}

// causal softmax; exp values cached in registers; writes fp16 P only.
__global__ __launch_bounds__(256)
void softmax_causal(const float* __restrict__ Sm, __half* __restrict__ ph) {
    const int gq = blockIdx.x;
    const int q  = gq & (Sq - 1);
    const float* row = Sm + (size_t)gq * Sq;
    __half* hrow = ph + (size_t)gq * Sq;
    const int len = q + 1;
    const int tid = threadIdx.x;
    __shared__ float red[256];

    float m = -1e30f;
    for (int j = tid; j < len; j += 256) m = fmaxf(m, row[j]);
    red[tid] = m; __syncthreads();
    for (int s = 128; s > 0; s >>= 1) {
        if (tid < s) red[tid] = fmaxf(red[tid], red[tid + s]);
        __syncthreads();
    }
    m = red[0]; __syncthreads();

    float ev[8];
    float sum = 0.f;
    int c = 0;
    for (int j = tid; j < len; j += 256) {
        float e = __expf(row[j] - m);
        ev[c++] = e; sum += e;
    }
    red[tid] = sum; __syncthreads();
    for (int s = 128; s > 0; s >>= 1) {
        if (tid < s) red[tid] += red[tid + s];
        __syncthreads();
    }
    const float inv = 1.0f / red[0];

    c = 0;
    for (int j = tid; j < len; j += 256)
        hrow[j] = __float2half_rn(ev[c++] * inv);
    const int jend = ((q >> 7) + 1) << 7;
    const __half z = __float2half(0.f);
    for (int j = len + tid; j < jend; j += 256) hrow[j] = z;
}

// ================= QKV combined single-pass GEMM =================
__global__ __launch_bounds__(NTHR, 2)
void gemm_qkv(const __half* __restrict__ xr,
              const __half* __restrict__ wq, const __half* __restrict__ wk,
              const __half* __restrict__ wv,
              const float* __restrict__ bq, const float* __restrict__ bk,
              const float* __restrict__ bv,
              __half* __restrict__ qh, __half* __restrict__ kh,
              __half* __restrict__ vh)
{
    const int bxx = blockIdx.x & 7;
    const int wsel = blockIdx.x >> 3;
    const int by = blockIdx.y;
    const __half* Bw  = (wsel == 0) ? wq : (wsel == 1) ? wk : wv;
    const float* bias = (wsel == 0) ? bq : (wsel == 1) ? bk : bv;
    __half* outp      = (wsel == 0) ? qh : (wsel == 1) ? kh : vh;

    extern __shared__ __align__(16) char smem[];
    const uint32_t sb = smem_u32(smem);
    const int tid  = threadIdx.x;
    const int lane = tid & 31;
    const int wid  = tid >> 5;
    const int wm   = wid >> 1;
    const int wn   = wid & 1;

    float acc[4][8][4] = {};
    mainloop(xr + (size_t)by * TM_CTA * Dd, Bw + (size_t)bxx * TN_CTA * Dd,
             Dd, Dd, Dd >> 6, sb, tid, lane, wm, wn, acc);

    const int m_base = by * TM_CTA + wm * 64;
    const int n_base = bxx * TN_CTA + wn * 64;
    const int rr = lane >> 2;
    const int cc = 2 * (lane & 3);

    #pragma unroll
    for (int i = 0; i < 4; i++) {
        #pragma unroll
        for (int j = 0; j < 8; j++) {
            const int col = n_base + j * 8 + cc;
            #pragma unroll
            for (int h = 0; h < 2; h++) {
                const int row = m_base + i * 16 + rr + h * 8;
                float v0 = acc[i][j][2 * h + 0] + __ldg(&bias[col]);
                float v1 = acc[i][j][2 * h + 1] + __ldg(&bias[col + 1]);
                size_t o = (size_t)row * Dd + col;
                *(__half2*)(outp + o) =
                    __halves2half2(__float2half_rn(v0), __float2half_rn(v1));
            }
        }
    }
}

// ================= merged scores + (V·Wo)^T GEMM =================
// grid (16, 24, Bn). by<16: scores S = q·k^T * scale (causal tile skip).
//                    by>=16: vwot[z][d'][s] = wot · v^T (row tile = by-16).
__global__ __launch_bounds__(NTHR, 2)
void gemm_scvw(const __half* __restrict__ qh, const __half* __restrict__ kh,
               const __half* __restrict__ wot, const __half* __restrict__ vh,
               float* __restrict__ Sp, __half* __restrict__ vwot, float scale)
{
    const int bx = blockIdx.x, by = blockIdx.y, z = blockIdx.z;
    const bool is_sc = (by < 16);
    if (is_sc && bx > by) return;                 // causal tile skip

    extern __shared__ __align__(16) char smem[];
    const uint32_t sb = smem_u32(smem);
    const int tid  = threadIdx.x;
    const int lane = tid & 31;
    const int wid  = tid >> 5;
    const int wm   = wid >> 1;
    const int wn   = wid & 1;

    const __half* pA;
    const __half* pB;
    if (is_sc) {
        pA = qh + (size_t)z * Sq * Dd + (size_t)by * TM_CTA * Dd;
        pB = kh + (size_t)z * Sq * Dd + (size_t)bx * TN_CTA * Dd;
    } else {
        pA = wot + (size_t)(by - 16) * TM_CTA * Dd;
        pB = vh + (size_t)z * Sq * Dd + (size_t)bx * TN_CTA * Dd;
    }

    float acc[4][8][4] = {};
    mainloop(pA, pB, Dd, Dd, Dd >> 6, sb, tid, lane, wm, wn, acc);

    const int rr = lane >> 2;
    const int cc = 2 * (lane & 3);
    const int n_base = bx * TN_CTA + wn * 64;

    if (is_sc) {
        const int m_base = by * TM_CTA + wm * 64;
        float* outp = Sp + (size_t)z * Sq * Sq;
        #pragma unroll
        for (int i = 0; i < 4; i++)
            #pragma unroll
            for (int j = 0; j < 8; j++) {
                const int col = n_base + j * 8 + cc;
                #pragma unroll
                for (int h = 0; h < 2; h++) {
                    const int row = m_base + i * 16 + rr + h * 8;
                    float2 o = make_float2(acc[i][j][2 * h] * scale,
                                           acc[i][j][2 * h + 1] * scale);
                    *(float2*)(outp + (size_t)row * Sq + col) = o;
                }
            }
    } else {
        const int m_base = (by - 16) * TM_CTA + wm * 64;
        __half* outp = vwot + (size_t)z * Dd * Sq;
        #pragma unroll
        for (int i = 0; i < 4; i++)
            #pragma unroll
            for (int j = 0; j < 8; j++) {
                const int col = n_base + j * 8 + cc;
                #pragma unroll
                for (int h = 0; h < 2; h++) {
                    const int row = m_base + i * 16 + rr + h * 8;
                    size_t o = (size_t)row * Sq + col;
                    *(__half2*)(outp + o) = __halves2half2(
                        __float2half_rn(acc[i][j][2 * h]),
                        __float2half_rn(acc[i][j][2 * h + 1]));
                }
            }
    }
}

// ================= PV GEMM: out = P · (V·Wo)^T + bo (fp32) =================
__global__ __launch_bounds__(NTHR, 2)
void gemm_pv(const __half* __restrict__ ph, const __half* __restrict__ vwot,
             const float* __restrict__ bo, float* __restrict__ out)
{
    const int bx = blockIdx.x, z = blockIdx.z;
    const int by = (int)gridDim.y - 1 - (int)blockIdx.y;   // heavy tiles first
    const int nchunk = ((by + 1) * 128) >> 6;              // causal K bound

    extern __shared__ __align__(16) char smem[];
    const uint32_t sb = smem_u32(smem);
    const int tid  = threadIdx.x;
    const int lane = tid & 31;
    const int wid  = tid >> 5;
    const int wm   = wid >> 1;
    const int wn   = wid & 1;

    float acc[4][8][4] = {};
    mainloop(ph + (size_t)z * Sq * Sq + (size_t)by * TM_CTA * Sq,
             vwot + (size_t)z * Dd * Sq + (size_t)bx * TN_CTA * Sq,
             Sq, Sq, nchunk, sb, tid, lane, wm, wn, acc);

    const int m_base = by * TM_CTA + wm * 64;
    const int n_base = bx * TN_CTA + wn * 64;
    const int rr = lane >> 2;
    const int cc = 2 * (lane & 3);
    float* outp = out + (size_t)z * Sq * Dd;

    #pragma unroll
    for (int i = 0; i < 4; i++)
        #pragma unroll
        for (int j = 0; j < 8; j++) {
            const int col = n_base + j * 8 + cc;
            #pragma unroll
            for (int h = 0; h < 2; h++) {
                const int row = m_base + i * 16 + rr + h * 8;
                float2 o = make_float2(acc[i][j][2 * h]     + __ldg(&bo[col]),
                                       acc[i][j][2 * h + 1] + __ldg(&bo[col + 1]));
                *(float2*)(outp + (size_t)row * Dd + col) = o;
            }
        }
}

// ---------------- launch ----------------
extern "C" void kernel_launch(void* const* d_in, const int* in_sizes, int n_in,
                              void* d_out, int out_size)
{
    const float* x  = (const float*)d_in[0];
    const float* Wq = (const float*)d_in[1];
    const float* bq = (const float*)d_in[2];
    const float* Wk = (const float*)d_in[3];
    const float* bk = (const float*)d_in[4];
    const float* Wv = (const float*)d_in[5];
    const float* bv = (const float*)d_in[6];
    const float* Wo = (const float*)d_in[7];
    const float* bo = (const float*)d_in[8];
    float* out = (float*)d_out;

    __half *xr, *wqt, *wkt, *wvt, *wot, *qh, *kh, *vh, *vwot, *phv;
    float* Sp;
    cudaGetSymbolAddress((void**)&xr,   g_xr);
    cudaGetSymbolAddress((void**)&wqt,  g_wqt);  cudaGetSymbolAddress((void**)&wkt, g_wkt);
    cudaGetSymbolAddress((void**)&wvt,  g_wvt);  cudaGetSymbolAddress((void**)&wot, g_wot);
    cudaGetSymbolAddress((void**)&qh,   g_qh);
    cudaGetSymbolAddress((void**)&kh,   g_kh);
    cudaGetSymbolAddress((void**)&vh,   g_vh);
    cudaGetSymbolAddress((void**)&vwot, g_vwot);
    cudaGetSymbolAddress((void**)&phv,  g_ph);
    cudaGetSymbolAddress((void**)&Sp,   g_S);

    cudaFuncSetAttribute(gemm_qkv,  cudaFuncAttributeMaxDynamicSharedMemorySize, GEMM_SMEM);
    cudaFuncSetAttribute(gemm_scvw, cudaFuncAttributeMaxDynamicSharedMemorySize, GEMM_SMEM);
    cudaFuncSetAttribute(gemm_pv,   cudaFuncAttributeMaxDynamicSharedMemorySize, GEMM_SMEM);

    const float scale = 1.0f / 32.0f;

    // #1: round x to fp16
    round_kernel<<<2048, 256>>>(x, xr, (size_t)Mm * Dd);

    // #2: all four weight transposes
    dim3 tb(32, 8), tg4(Dd / 32, Dd / 32, 4);
    transpose4_kernel<<<tg4, tb>>>(Wq, wqt, Wk, wkt, Wv, wvt, Wo, wot);

    // #3: combined QKV projection
    dim3 gQKV(24, Mm / TM_CTA, 1);
    gemm_qkv<<<gQKV, NTHR, GEMM_SMEM>>>(xr, wqt, wkt, wvt, bq, bk, bv, qh, kh, vh);

    // #4 (ncu capture slot): merged scores + VWo
    dim3 gSV(Sq / TN_CTA, 16 + 8, Bn);            // 16 x 24 x 4
    gemm_scvw<<<gSV, NTHR, GEMM_SMEM>>>(qh, kh, wot, vh, Sp, vwot, scale);

    // #5: softmax
    softmax_causal<<<Mm, 256>>>(Sp, phv);

    // #6: out = P·(V·Wo)^T + bo, fp32, K causally bounded
    dim3 gPV(Dd / TN_CTA, Sq / TM_CTA, Bn);       // 8 x 16 x 4
    gemm_pv<<<gPV, NTHR, GEMM_SMEM>>>(phv, vwot, bo, out);
}

// round 13
// speedup vs baseline: 2.9470x; 1.0252x over previous
#include <cuda_runtime.h>
#include <cuda_fp16.h>
#include <cstdint>

// SingleSelfHeadAttention b=4, s=2048, d=1024, causal, fp32 I/O.
// R13: single-read register-cached softmax; merged prep launch; softmax in
//      the ncu capture slot. GEMMs unchanged from R12 (68% tensor = crossbar wall).

static constexpr int Bn = 4;
static constexpr int Sq = 2048;
static constexpr int Dd = 1024;
static constexpr int Mm = Bn * Sq;          // 8192

// ---------------- device scratch ----------------
__device__ __half g_xr [(size_t)Mm * Dd];
__device__ __half g_wqt[(size_t)Dd * Dd], g_wkt[(size_t)Dd * Dd];
__device__ __half g_wvt[(size_t)Dd * Dd], g_wot[(size_t)Dd * Dd];
__device__ __half g_qh[(size_t)Mm * Dd];
__device__ __half g_kh[(size_t)Mm * Dd];
__device__ __half g_vh[(size_t)Mm * Dd];
__device__ __half g_vwot[(size_t)Bn * Dd * Sq];   // (V·Wo)^T per batch [d'][s]
__device__ float  g_S [(size_t)Bn * Sq * Sq];
__device__ __half g_ph[(size_t)Bn * Sq * Sq];

// ---------------- PTX helpers ----------------
__device__ __forceinline__ uint32_t smem_u32(const void* p) {
    uint32_t a;
    asm("{ .reg .u64 t; cvta.to.shared.u64 t, %1; cvt.u32.u64 %0, t; }" : "=r"(a) : "l"(p));
    return a;
}
#define CP_ASYNC16(dst, src) \
    asm volatile("cp.async.cg.shared.global [%0], [%1], 16;" :: "r"(dst), "l"(src))
#define CP_COMMIT() asm volatile("cp.async.commit_group;" ::: "memory")
#define CP_WAIT1()  asm volatile("cp.async.wait_group 1;" ::: "memory")

__device__ __forceinline__ void ldsm_x4(uint32_t* r, uint32_t addr) {
    asm volatile("ldmatrix.sync.aligned.m8n8.x4.shared.b16 {%0,%1,%2,%3}, [%4];"
        : "=r"(r[0]), "=r"(r[1]), "=r"(r[2]), "=r"(r[3]) : "r"(addr));
}
__device__ __forceinline__ void mma_f16(float* c, const uint32_t* a, const uint32_t* b) {
    asm volatile("mma.sync.aligned.m16n8k16.row.col.f32.f16.f16.f32 "
        "{%0,%1,%2,%3}, {%4,%5,%6,%7}, {%8,%9}, {%0,%1,%2,%3};"
        : "+f"(c[0]), "+f"(c[1]), "+f"(c[2]), "+f"(c[3])
        : "r"(a[0]), "r"(a[1]), "r"(a[2]), "r"(a[3]), "r"(b[0]), "r"(b[1]));
}
__device__ __forceinline__ uint32_t swz(uint32_t off) {   // 128B-row XOR swizzle
    return off ^ ((off >> 3) & 0x70);
}

// ---------------- GEMM config: 128x128 tile, 128 threads ----------------
#define TM_CTA 128
#define TN_CTA 128
#define NTHR   128
#define A_TILE (TM_CTA * 128)            // 16384 B
#define STAGE  (2 * A_TILE)              // 32768
#define NSTAGE 3
#define GEMM_SMEM (NSTAGE * STAGE)       // 98304 -> 2 CTAs/SM

__device__ __forceinline__ void load_T_async(uint32_t dst, const __half* src,
                                             int ldK, int tid) {
    #pragma unroll
    for (int j = 0; j < 8; j++) {
        int s = tid + j * NTHR;
        int r = s >> 3, c = s & 7;
        CP_ASYNC16(dst + swz(r * 128 + c * 16), src + (size_t)r * ldK + c * 8);
    }
}

// Shared single-barrier multistage mainloop. acc[4][8][4] += A·B^T over nchunk*64 K.
__device__ __forceinline__ void mainloop(const __half* __restrict__ pA,
                                         const __half* __restrict__ pB,
                                         int ldA, int ldB, int nchunk,
                                         uint32_t sb, int tid, int lane,
                                         int wm, int wn, float acc[4][8][4])
{
    #pragma unroll
    for (int p = 0; p < 2; p++) {
        if (p < nchunk) {
            uint32_t st = sb + p * STAGE;
            load_T_async(st, pA + ((size_t)p << 6), ldA, tid);
            load_T_async(st + A_TILE, pB + ((size_t)p << 6), ldB, tid);
        }
        CP_COMMIT();
    }

    const uint32_t arow = (lane & 7) + ((lane & 8)  ? 8 : 0);
    const uint32_t acol = (lane & 16) ? 16u : 0u;
    const uint32_t brow = (lane & 7) + ((lane & 16) ? 8 : 0);
    const uint32_t bcol = (lane & 8)  ? 16u : 0u;

    for (int c = 0; c < nchunk; ++c) {
        CP_WAIT1();            // chunk c resident
        __syncthreads();       // stage (c-1)%3 reads complete

        if (c + 2 < nchunk) {  // prefetch chunk c+2 into stage (c+2)%3
            uint32_t st = sb + ((c + 2) % NSTAGE) * STAGE;
            load_T_async(st, pA + ((size_t)(c + 2) << 6), ldA, tid);
            load_T_async(st + A_TILE, pB + ((size_t)(c + 2) << 6), ldB, tid);
        }
        CP_COMMIT();

        const uint32_t base = sb + (c % NSTAGE) * STAGE;
        #pragma unroll
        for (int ks = 0; ks < 4; ks++) {
            const uint32_t kb = ks * 32;
            uint32_t ah[4][4];
            #pragma unroll
            for (int i = 0; i < 4; i++) {
                uint32_t off = swz((wm * 64 + i * 16 + arow) * 128 + kb + acol);
                ldsm_x4(ah[i], base + off);
            }
            #pragma unroll
            for (int j2 = 0; j2 < 4; j2++) {
                uint32_t off = swz((wn * 64 + j2 * 16 + brow) * 128 + kb + bcol);
                uint32_t th[4];
                ldsm_x4(th, base + A_TILE + off);
                const int j0 = j2 * 2, j1 = j2 * 2 + 1;
                #pragma unroll
                for (int i = 0; i < 4; i++) {
                    mma_f16(acc[i][j0], ah[i], &th[0]);
                    mma_f16(acc[i][j1], ah[i], &th[2]);
                }
            }
        }
    }
}

// ---------------- prep: weight transposes (z<4) + x rounding (z==4) --------
__global__ void prep_kernel(const float* __restrict__ x, __half* __restrict__ xr,
                            const float* __restrict__ W0, __half* __restrict__ T0,
                            const float* __restrict__ W1, __half* __restrict__ T1,
                            const float* __restrict__ W2, __half* __restrict__ T2,
                            const float* __restrict__ W3, __half* __restrict__ T3) {
    if (blockIdx.z == 4) {
        size_t i = ((size_t)(blockIdx.y * gridDim.x + blockIdx.x) * 256
                   + threadIdx.y * 32 + threadIdx.x);
        size_t stride = (size_t)gridDim.x * gridDim.y * 256;
        const size_t n = (size_t)Mm * Dd;
        for (; i < n; i += stride) xr[i] = __float2half_rn(x[i]);
        return;
    }
    const float* W = (blockIdx.z == 0) ? W0 : (blockIdx.z == 1) ? W1
                   : (blockIdx.z == 2) ? W2 : W3;
    __half* T = (blockIdx.z == 0) ? T0 : (blockIdx.z == 1) ? T1
              : (blockIdx.z == 2) ? T2 : T3;
    __shared__ float tile[32][33];
    int bx = blockIdx.x * 32, by = blockIdx.y * 32;
    int tx = threadIdx.x, ty = threadIdx.y;
    #pragma unroll
    for (int j = 0; j < 4; j++)
        tile[ty + 8 * j][tx] = W[(size_t)(by + ty + 8 * j) * Dd + bx + tx];
    __syncthreads();
    #pragma unroll
    for (int j = 0; j < 4; j++) {
        float v = tile[tx][ty + 8 * j];
        size_t o = (size_t)(bx + ty + 8 * j) * Dd + by + tx;
        T[o] = __float2half_rn(v);
    }
}

// single-read causal softmax: row cached in registers across all three phases
__global__ __launch_bounds__(256)
void softmax_causal(const float* __restrict__ Sm, __half* __restrict__ ph) {
    const int gq = blockIdx.x;
    const int q  = gq & (Sq - 1);
    const float* row = Sm + (size_t)gq * Sq;
    __half* hrow = ph + (size_t)gq * Sq;
    const int len = q + 1;
    const int tid = threadIdx.x;
    __shared__ float red[256];

    float v[8];
    int cnt = 0;
    float m = -1e30f;
    for (int j = tid; j < len; j += 256) {
        float s = row[j];
        v[cnt++] = s;
        m = fmaxf(m, s);
    }
    red[tid] = m; __syncthreads();
    for (int s = 128; s > 0; s >>= 1) {
        if (tid < s) red[tid] = fmaxf(red[tid], red[tid + s]);
        __syncthreads();
    }
    m = red[0]; __syncthreads();

    float sum = 0.f;
    #pragma unroll
    for (int k = 0; k < 8; k++) {
        if (k < cnt) {
            float e = __expf(v[k] - m);
            v[k] = e; sum += e;
        }
    }
    red[tid] = sum; __syncthreads();
    for (int s = 128; s > 0; s >>= 1) {
        if (tid < s) red[tid] += red[tid + s];
        __syncthreads();
    }
    const float inv = 1.0f / red[0];

    cnt = 0;
    for (int j = tid; j < len; j += 256)
        hrow[j] = __float2half_rn(v[cnt++] * inv);
    const int jend = ((q >> 7) + 1) << 7;
    const __half z = __float2half(0.f);
    for (int j = len + tid; j < jend; j += 256) hrow[j] = z;
}

// ================= QKV combined single-pass GEMM =================
__global__ __launch_bounds__(NTHR, 2)
void gemm_qkv(const __half* __restrict__ xr,
              const __half* __restrict__ wq, const __half* __restrict__ wk,
              const __half* __restrict__ wv,
              const float* __restrict__ bq, const float* __restrict__ bk,
              const float* __restrict__ bv,
              __half* __restrict__ qh, __half* __restrict__ kh,
              __half* __restrict__ vh)
{
    const int bxx = blockIdx.x & 7;
    const int wsel = blockIdx.x >> 3;
    const int by = blockIdx.y;
    const __half* Bw  = (wsel == 0) ? wq : (wsel == 1) ? wk : wv;
    const float* bias = (wsel == 0) ? bq : (wsel == 1) ? bk : bv;
    __half* outp      = (wsel == 0) ? qh : (wsel == 1) ? kh : vh;

    extern __shared__ __align__(16) char smem[];
    const uint32_t sb = smem_u32(smem);
    const int tid  = threadIdx.x;
    const int lane = tid & 31;
    const int wid  = tid >> 5;
    const int wm   = wid >> 1;
    const int wn   = wid & 1;

    float acc[4][8][4] = {};
    mainloop(xr + (size_t)by * TM_CTA * Dd, Bw + (size_t)bxx * TN_CTA * Dd,
             Dd, Dd, Dd >> 6, sb, tid, lane, wm, wn, acc);

    const int m_base = by * TM_CTA + wm * 64;
    const int n_base = bxx * TN_CTA + wn * 64;
    const int rr = lane >> 2;
    const int cc = 2 * (lane & 3);

    #pragma unroll
    for (int j = 0; j < 8; j++) {
        const int col = n_base + j * 8 + cc;
        const float b0 = __ldg(&bias[col]);
        const float b1 = __ldg(&bias[col + 1]);
        #pragma unroll
        for (int i = 0; i < 4; i++) {
            #pragma unroll
            for (int h = 0; h < 2; h++) {
                const int row = m_base + i * 16 + rr + h * 8;
                float v0 = acc[i][j][2 * h + 0] + b0;
                float v1 = acc[i][j][2 * h + 1] + b1;
                size_t o = (size_t)row * Dd + col;
                *(__half2*)(outp + o) =
                    __halves2half2(__float2half_rn(v0), __float2half_rn(v1));
            }
        }
    }
}

// ================= merged scores + (V·Wo)^T GEMM =================
__global__ __launch_bounds__(NTHR, 2)
void gemm_scvw(const __half* __restrict__ qh, const __half* __restrict__ kh,
               const __half* __restrict__ wot, const __half* __restrict__ vh,
               float* __restrict__ Sp, __half* __restrict__ vwot, float scale)
{
    const int bx = blockIdx.x, by = blockIdx.y, z = blockIdx.z;
    const bool is_sc = (by < 16);
    if (is_sc && bx > by) return;                 // causal tile skip

    extern __shared__ __align__(16) char smem[];
    const uint32_t sb = smem_u32(smem);
    const int tid  = threadIdx.x;
    const int lane = tid & 31;
    const int wid  = tid >> 5;
    const int wm   = wid >> 1;
    const int wn   = wid & 1;

    const __half* pA;
    const __half* pB;
    if (is_sc) {
        pA = qh + (size_t)z * Sq * Dd + (size_t)by * TM_CTA * Dd;
        pB = kh + (size_t)z * Sq * Dd + (size_t)bx * TN_CTA * Dd;
    } else {
        pA = wot + (size_t)(by - 16) * TM_CTA * Dd;
        pB = vh + (size_t)z * Sq * Dd + (size_t)bx * TN_CTA * Dd;
    }

    float acc[4][8][4] = {};
    mainloop(pA, pB, Dd, Dd, Dd >> 6, sb, tid, lane, wm, wn, acc);

    const int rr = lane >> 2;
    const int cc = 2 * (lane & 3);
    const int n_base = bx * TN_CTA + wn * 64;

    if (is_sc) {
        const int m_base = by * TM_CTA + wm * 64;
        float* outp = Sp + (size_t)z * Sq * Sq;
        #pragma unroll
        for (int i = 0; i < 4; i++)
            #pragma unroll
            for (int j = 0; j < 8; j++) {
                const int col = n_base + j * 8 + cc;
                #pragma unroll
                for (int h = 0; h < 2; h++) {
                    const int row = m_base + i * 16 + rr + h * 8;
                    float2 o = make_float2(acc[i][j][2 * h] * scale,
                                           acc[i][j][2 * h + 1] * scale);
                    *(float2*)(outp + (size_t)row * Sq + col) = o;
                }
            }
    } else {
        const int m_base = (by - 16) * TM_CTA + wm * 64;
        __half* outp = vwot + (size_t)z * Dd * Sq;
        #pragma unroll
        for (int i = 0; i < 4; i++)
            #pragma unroll
            for (int j = 0; j < 8; j++) {
                const int col = n_base + j * 8 + cc;
                #pragma unroll
                for (int h = 0; h < 2; h++) {
                    const int row = m_base + i * 16 + rr + h * 8;
                    size_t o = (size_t)row * Sq + col;
                    *(__half2*)(outp + o) = __halves2half2(
                        __float2half_rn(acc[i][j][2 * h]),
                        __float2half_rn(acc[i][j][2 * h + 1]));
                }
            }
    }
}

// ================= PV GEMM: out = P · (V·Wo)^T + bo (fp32) =================
__global__ __launch_bounds__(NTHR, 2)
void gemm_pv(const __half* __restrict__ ph, const __half* __restrict__ vwot,
             const float* __restrict__ bo, float* __restrict__ out)
{
    const int bx = blockIdx.x, z = blockIdx.z;
    const int by = (int)gridDim.y - 1 - (int)blockIdx.y;   // heavy tiles first
    const int nchunk = ((by + 1) * 128) >> 6;              // causal K bound

    extern __shared__ __align__(16) char smem[];
    const uint32_t sb = smem_u32(smem);
    const int tid  = threadIdx.x;
    const int lane = tid & 31;
    const int wid  = tid >> 5;
    const int wm   = wid >> 1;
    const int wn   = wid & 1;

    float acc[4][8][4] = {};
    mainloop(ph + (size_t)z * Sq * Sq + (size_t)by * TM_CTA * Sq,
             vwot + (size_t)z * Dd * Sq + (size_t)bx * TN_CTA * Sq,
             Sq, Sq, nchunk, sb, tid, lane, wm, wn, acc);

    const int m_base = by * TM_CTA + wm * 64;
    const int n_base = bx * TN_CTA + wn * 64;
    const int rr = lane >> 2;
    const int cc = 2 * (lane & 3);
    float* outp = out + (size_t)z * Sq * Dd;

    #pragma unroll
    for (int j = 0; j < 8; j++) {
        const int col = n_base + j * 8 + cc;
        const float b0 = __ldg(&bo[col]);
        const float b1 = __ldg(&bo[col + 1]);
        #pragma unroll
        for (int i = 0; i < 4; i++) {
            #pragma unroll
            for (int h = 0; h < 2; h++) {
                const int row = m_base + i * 16 + rr + h * 8;
                float2 o = make_float2(acc[i][j][2 * h] + b0,
                                       acc[i][j][2 * h + 1] + b1);
                *(float2*)(outp + (size_t)row * Dd + col) = o;
            }
        }
    }
}

// ---------------- launch ----------------
extern "C" void kernel_launch(void* const* d_in, const int* in_sizes, int n_in,
                              void* d_out, int out_size)
{
    const float* x  = (const float*)d_in[0];
    const float* Wq = (const float*)d_in[1];
    const float* bq = (const float*)d_in[2];
    const float* Wk = (const float*)d_in[3];
    const float* bk = (const float*)d_in[4];
    const float* Wv = (const float*)d_in[5];
    const float* bv = (const float*)d_in[6];
    const float* Wo = (const float*)d_in[7];
    const float* bo = (const float*)d_in[8];
    float* out = (float*)d_out;

    __half *xr, *wqt, *wkt, *wvt, *wot, *qh, *kh, *vh, *vwot, *phv;
    float* Sp;
    cudaGetSymbolAddress((void**)&xr,   g_xr);
    cudaGetSymbolAddress((void**)&wqt,  g_wqt);  cudaGetSymbolAddress((void**)&wkt, g_wkt);
    cudaGetSymbolAddress((void**)&wvt,  g_wvt);  cudaGetSymbolAddress((void**)&wot, g_wot);
    cudaGetSymbolAddress((void**)&qh,   g_qh);
    cudaGetSymbolAddress((void**)&kh,   g_kh);
    cudaGetSymbolAddress((void**)&vh,   g_vh);
    cudaGetSymbolAddress((void**)&vwot, g_vwot);
    cudaGetSymbolAddress((void**)&phv,  g_ph);
    cudaGetSymbolAddress((void**)&Sp,   g_S);

    cudaFuncSetAttribute(gemm_qkv,  cudaFuncAttributeMaxDynamicSharedMemorySize, GEMM_SMEM);
    cudaFuncSetAttribute(gemm_scvw, cudaFuncAttributeMaxDynamicSharedMemorySize, GEMM_SMEM);
    cudaFuncSetAttribute(gemm_pv,   cudaFuncAttributeMaxDynamicSharedMemorySize, GEMM_SMEM);

    const float scale = 1.0f / 32.0f;

    // #1: prep — weight transposes (z<4) + x rounding (z==4)
    dim3 tb(32, 8), tgp(Dd / 32, Dd / 32, 5);
    prep_kernel<<<tgp, tb>>>(x, xr, Wq, wqt, Wk, wkt, Wv, wvt, Wo, wot);

    // #2: combined QKV projection
    dim3 gQKV(24, Mm / TM_CTA, 1);
    gemm_qkv<<<gQKV, NTHR, GEMM_SMEM>>>(xr, wqt, wkt, wvt, bq, bk, bv, qh, kh, vh);

    // #3: merged scores + VWo
    dim3 gSV(Sq / TN_CTA, 16 + 8, Bn);            // 16 x 24 x 4
    gemm_scvw<<<gSV, NTHR, GEMM_SMEM>>>(qh, kh, wot, vh, Sp, vwot, scale);

    // #4 (ncu capture slot): single-read softmax
    softmax_causal<<<Mm, 256>>>(Sp, phv);

    // #5: out = P·(V·Wo)^T + bo, fp32, K causally bounded
    dim3 gPV(Dd / TN_CTA, Sq / TM_CTA, Bn);       // 8 x 16 x 4
    gemm_pv<<<gPV, NTHR, GEMM_SMEM>>>(phv, vwot, bo, out);
}

// round 14
// speedup vs baseline: 3.0600x; 1.0383x over previous
#include <cuda_runtime.h>
#include <cuda_fp16.h>
#include <cstdint>

// SingleSelfHeadAttention b=4, s=2048, d=1024, causal, fp32 I/O.
// R14: float4 + shuffle-reduction softmax (was ALU-bound at 31us).
//      GEMMs unchanged: 128x128 @128thr, 2 CTA/SM, single-pass fp16 HMMA
//      at the SMEM-crossbar wall (68% tensor).

static constexpr int Bn = 4;
static constexpr int Sq = 2048;
static constexpr int Dd = 1024;
static constexpr int Mm = Bn * Sq;          // 8192

// ---------------- device scratch ----------------
__device__ __half g_xr [(size_t)Mm * Dd];
__device__ __half g_wqt[(size_t)Dd * Dd], g_wkt[(size_t)Dd * Dd];
__device__ __half g_wvt[(size_t)Dd * Dd], g_wot[(size_t)Dd * Dd];
__device__ __half g_qh[(size_t)Mm * Dd];
__device__ __half g_kh[(size_t)Mm * Dd];
__device__ __half g_vh[(size_t)Mm * Dd];
__device__ __half g_vwot[(size_t)Bn * Dd * Sq];   // (V·Wo)^T per batch [d'][s]
__device__ float  g_S [(size_t)Bn * Sq * Sq];
__device__ __half g_ph[(size_t)Bn * Sq * Sq];

// ---------------- PTX helpers ----------------
__device__ __forceinline__ uint32_t smem_u32(const void* p) {
    uint32_t a;
    asm("{ .reg .u64 t; cvta.to.shared.u64 t, %1; cvt.u32.u64 %0, t; }" : "=r"(a) : "l"(p));
    return a;
}
#define CP_ASYNC16(dst, src) \
    asm volatile("cp.async.cg.shared.global [%0], [%1], 16;" :: "r"(dst), "l"(src))
#define CP_COMMIT() asm volatile("cp.async.commit_group;" ::: "memory")
#define CP_WAIT1()  asm volatile("cp.async.wait_group 1;" ::: "memory")

__device__ __forceinline__ void ldsm_x4(uint32_t* r, uint32_t addr) {
    asm volatile("ldmatrix.sync.aligned.m8n8.x4.shared.b16 {%0,%1,%2,%3}, [%4];"
        : "=r"(r[0]), "=r"(r[1]), "=r"(r[2]), "=r"(r[3]) : "r"(addr));
}
__device__ __forceinline__ void mma_f16(float* c, const uint32_t* a, const uint32_t* b) {
    asm volatile("mma.sync.aligned.m16n8k16.row.col.f32.f16.f16.f32 "
        "{%0,%1,%2,%3}, {%4,%5,%6,%7}, {%8,%9}, {%0,%1,%2,%3};"
        : "+f"(c[0]), "+f"(c[1]), "+f"(c[2]), "+f"(c[3])
        : "r"(a[0]), "r"(a[1]), "r"(a[2]), "r"(a[3]), "r"(b[0]), "r"(b[1]));
}
__device__ __forceinline__ uint32_t swz(uint32_t off) {   // 128B-row XOR swizzle
    return off ^ ((off >> 3) & 0x70);
}

// ---------------- GEMM config: 128x128 tile, 128 threads ----------------
#define TM_CTA 128
#define TN_CTA 128
#define NTHR   128
#define A_TILE (TM_CTA * 128)            // 16384 B
#define STAGE  (2 * A_TILE)              // 32768
#define NSTAGE 3
#define GEMM_SMEM (NSTAGE * STAGE)       // 98304 -> 2 CTAs/SM

__device__ __forceinline__ void load_T_async(uint32_t dst, const __half* src,
                                             int ldK, int tid) {
    #pragma unroll
    for (int j = 0; j < 8; j++) {
        int s = tid + j * NTHR;
        int r = s >> 3, c = s & 7;
        CP_ASYNC16(dst + swz(r * 128 + c * 16), src + (size_t)r * ldK + c * 8);
    }
}

// Shared single-barrier multistage mainloop. acc[4][8][4] += A·B^T over nchunk*64 K.
__device__ __forceinline__ void mainloop(const __half* __restrict__ pA,
                                         const __half* __restrict__ pB,
                                         int ldA, int ldB, int nchunk,
                                         uint32_t sb, int tid, int lane,
                                         int wm, int wn, float acc[4][8][4])
{
    #pragma unroll
    for (int p = 0; p < 2; p++) {
        if (p < nchunk) {
            uint32_t st = sb + p * STAGE;
            load_T_async(st, pA + ((size_t)p << 6), ldA, tid);
            load_T_async(st + A_TILE, pB + ((size_t)p << 6), ldB, tid);
        }
        CP_COMMIT();
    }

    const uint32_t arow = (lane & 7) + ((lane & 8)  ? 8 : 0);
    const uint32_t acol = (lane & 16) ? 16u : 0u;
    const uint32_t brow = (lane & 7) + ((lane & 16) ? 8 : 0);
    const uint32_t bcol = (lane & 8)  ? 16u : 0u;

    for (int c = 0; c < nchunk; ++c) {
        CP_WAIT1();            // chunk c resident
        __syncthreads();       // stage (c-1)%3 reads complete

        if (c + 2 < nchunk) {  // prefetch chunk c+2 into stage (c+2)%3
            uint32_t st = sb + ((c + 2) % NSTAGE) * STAGE;
            load_T_async(st, pA + ((size_t)(c + 2) << 6), ldA, tid);
            load_T_async(st + A_TILE, pB + ((size_t)(c + 2) << 6), ldB, tid);
        }
        CP_COMMIT();

        const uint32_t base = sb + (c % NSTAGE) * STAGE;
        #pragma unroll
        for (int ks = 0; ks < 4; ks++) {
            const uint32_t kb = ks * 32;
            uint32_t ah[4][4];
            #pragma unroll
            for (int i = 0; i < 4; i++) {
                uint32_t off = swz((wm * 64 + i * 16 + arow) * 128 + kb + acol);
                ldsm_x4(ah[i], base + off);
            }
            #pragma unroll
            for (int j2 = 0; j2 < 4; j2++) {
                uint32_t off = swz((wn * 64 + j2 * 16 + brow) * 128 + kb + bcol);
                uint32_t th[4];
                ldsm_x4(th, base + A_TILE + off);
                const int j0 = j2 * 2, j1 = j2 * 2 + 1;
                #pragma unroll
                for (int i = 0; i < 4; i++) {
                    mma_f16(acc[i][j0], ah[i], &th[0]);
                    mma_f16(acc[i][j1], ah[i], &th[2]);
                }
            }
        }
    }
}

// ---------------- prep: weight transposes (z<4) + x rounding (z==4) --------
__global__ void prep_kernel(const float* __restrict__ x, __half* __restrict__ xr,
                            const float* __restrict__ W0, __half* __restrict__ T0,
                            const float* __restrict__ W1, __half* __restrict__ T1,
                            const float* __restrict__ W2, __half* __restrict__ T2,
                            const float* __restrict__ W3, __half* __restrict__ T3) {
    if (blockIdx.z == 4) {
        size_t i = ((size_t)(blockIdx.y * gridDim.x + blockIdx.x) * 256
                   + threadIdx.y * 32 + threadIdx.x);
        size_t stride = (size_t)gridDim.x * gridDim.y * 256;
        const size_t n = (size_t)Mm * Dd;
        for (; i < n; i += stride) xr[i] = __float2half_rn(x[i]);
        return;
    }
    const float* W = (blockIdx.z == 0) ? W0 : (blockIdx.z == 1) ? W1
                   : (blockIdx.z == 2) ? W2 : W3;
    __half* T = (blockIdx.z == 0) ? T0 : (blockIdx.z == 1) ? T1
              : (blockIdx.z == 2) ? T2 : T3;
    __shared__ float tile[32][33];
    int bx = blockIdx.x * 32, by = blockIdx.y * 32;
    int tx = threadIdx.x, ty = threadIdx.y;
    #pragma unroll
    for (int j = 0; j < 4; j++)
        tile[ty + 8 * j][tx] = W[(size_t)(by + ty + 8 * j) * Dd + bx + tx];
    __syncthreads();
    #pragma unroll
    for (int j = 0; j < 4; j++) {
        float v = tile[tx][ty + 8 * j];
        size_t o = (size_t)(bx + ty + 8 * j) * Dd + by + tx;
        T[o] = __float2half_rn(v);
    }
}

// float4 + shuffle-reduction causal softmax. One block of 256 per row.
__global__ __launch_bounds__(256)
void softmax_causal(const float* __restrict__ Sm, __half* __restrict__ ph) {
    const int gq = blockIdx.x;
    const int q  = gq & (Sq - 1);
    const float4* row4 = (const float4*)(Sm + (size_t)gq * Sq);
    __half2* hrow2 = (__half2*)(ph + (size_t)gq * Sq);
    const int len  = q + 1;
    const int jend = ((q >> 7) + 1) << 7;         // 128-multiple pad bound
    const int tid  = threadIdx.x;
    const int lane = tid & 31;
    const int wrp  = tid >> 5;
    __shared__ float redm[8], reds[8];

    float4 v[2];
    float m = -1e30f;
    #pragma unroll
    for (int g = 0; g < 2; g++) {
        const int j4 = tid + g * 256;
        const int col = j4 << 2;
        if (col < len) {
            float4 t = row4[j4];
            m = fmaxf(m, t.x);
            if (col + 1 < len) m = fmaxf(m, t.y);
            if (col + 2 < len) m = fmaxf(m, t.z);
            if (col + 3 < len) m = fmaxf(m, t.w);
            v[g] = t;
        } else {
            v[g] = make_float4(0.f, 0.f, 0.f, 0.f);
        }
    }
    #pragma unroll
    for (int o = 16; o > 0; o >>= 1)
        m = fmaxf(m, __shfl_xor_sync(0xffffffffu, m, o));
    if (lane == 0) redm[wrp] = m;
    __syncthreads();
    if (wrp == 0) {
        float t = (lane < 8) ? redm[lane] : -1e30f;
        #pragma unroll
        for (int o = 4; o > 0; o >>= 1)
            t = fmaxf(t, __shfl_xor_sync(0xffffffffu, t, o));
        if (lane == 0) redm[0] = t;
    }
    __syncthreads();
    m = redm[0];

    float sum = 0.f;
    #pragma unroll
    for (int g = 0; g < 2; g++) {
        const int col = (tid + g * 256) << 2;
        if (col < len) {
            float4 t = v[g];
            float4 e;
            e.x = __expf(t.x - m);
            e.y = (col + 1 < len) ? __expf(t.y - m) : 0.f;
            e.z = (col + 2 < len) ? __expf(t.z - m) : 0.f;
            e.w = (col + 3 < len) ? __expf(t.w - m) : 0.f;
            sum += e.x + e.y + e.z + e.w;
            v[g] = e;
        }
    }
    #pragma unroll
    for (int o = 16; o > 0; o >>= 1)
        sum += __shfl_xor_sync(0xffffffffu, sum, o);
    if (lane == 0) reds[wrp] = sum;
    __syncthreads();
    if (wrp == 0) {
        float t = (lane < 8) ? reds[lane] : 0.f;
        #pragma unroll
        for (int o = 4; o > 0; o >>= 1)
            t += __shfl_xor_sync(0xffffffffu, t, o);
        if (lane == 0) reds[0] = t;
    }
    __syncthreads();
    const float inv = 1.0f / reds[0];

    #pragma unroll
    for (int g = 0; g < 2; g++) {
        const int j4 = tid + g * 256;
        const int col = j4 << 2;
        if (col < jend) {                          // covers data + zero pad
            float4 e = v[g];
            __half2 a = __halves2half2(__float2half_rn(e.x * inv),
                                       __float2half_rn(e.y * inv));
            __half2 b = __halves2half2(__float2half_rn(e.z * inv),
                                       __float2half_rn(e.w * inv));
            hrow2[j4 * 2]     = a;
            hrow2[j4 * 2 + 1] = b;
        }
    }
}

// ================= QKV combined single-pass GEMM =================
__global__ __launch_bounds__(NTHR, 2)
void gemm_qkv(const __half* __restrict__ xr,
              const __half* __restrict__ wq, const __half* __restrict__ wk,
              const __half* __restrict__ wv,
              const float* __restrict__ bq, const float* __restrict__ bk,
              const float* __restrict__ bv,
              __half* __restrict__ qh, __half* __restrict__ kh,
              __half* __restrict__ vh)
{
    const int bxx = blockIdx.x & 7;
    const int wsel = blockIdx.x >> 3;
    const int by = blockIdx.y;
    const __half* Bw  = (wsel == 0) ? wq : (wsel == 1) ? wk : wv;
    const float* bias = (wsel == 0) ? bq : (wsel == 1) ? bk : bv;
    __half* outp      = (wsel == 0) ? qh : (wsel == 1) ? kh : vh;

    extern __shared__ __align__(16) char smem[];
    const uint32_t sb = smem_u32(smem);
    const int tid  = threadIdx.x;
    const int lane = tid & 31;
    const int wid  = tid >> 5;
    const int wm   = wid >> 1;
    const int wn   = wid & 1;

    float acc[4][8][4] = {};
    mainloop(xr + (size_t)by * TM_CTA * Dd, Bw + (size_t)bxx * TN_CTA * Dd,
             Dd, Dd, Dd >> 6, sb, tid, lane, wm, wn, acc);

    const int m_base = by * TM_CTA + wm * 64;
    const int n_base = bxx * TN_CTA + wn * 64;
    const int rr = lane >> 2;
    const int cc = 2 * (lane & 3);

    #pragma unroll
    for (int j = 0; j < 8; j++) {
        const int col = n_base + j * 8 + cc;
        const float b0 = __ldg(&bias[col]);
        const float b1 = __ldg(&bias[col + 1]);
        #pragma unroll
        for (int i = 0; i < 4; i++) {
            #pragma unroll
            for (int h = 0; h < 2; h++) {
                const int row = m_base + i * 16 + rr + h * 8;
                float v0 = acc[i][j][2 * h + 0] + b0;
                float v1 = acc[i][j][2 * h + 1] + b1;
                size_t o = (size_t)row * Dd + col;
                *(__half2*)(outp + o) =
                    __halves2half2(__float2half_rn(v0), __float2half_rn(v1));
            }
        }
    }
}

// ================= merged scores + (V·Wo)^T GEMM =================
__global__ __launch_bounds__(NTHR, 2)
void gemm_scvw(const __half* __restrict__ qh, const __half* __restrict__ kh,
               const __half* __restrict__ wot, const __half* __restrict__ vh,
               float* __restrict__ Sp, __half* __restrict__ vwot, float scale)
{
    const int bx = blockIdx.x, by = blockIdx.y, z = blockIdx.z;
    const bool is_sc = (by < 16);
    if (is_sc && bx > by) return;                 // causal tile skip

    extern __shared__ __align__(16) char smem[];
    const uint32_t sb = smem_u32(smem);
    const int tid  = threadIdx.x;
    const int lane = tid & 31;
    const int wid  = tid >> 5;
    const int wm   = wid >> 1;
    const int wn   = wid & 1;

    const __half* pA;
    const __half* pB;
    if (is_sc) {
        pA = qh + (size_t)z * Sq * Dd + (size_t)by * TM_CTA * Dd;
        pB = kh + (size_t)z * Sq * Dd + (size_t)bx * TN_CTA * Dd;
    } else {
        pA = wot + (size_t)(by - 16) * TM_CTA * Dd;
        pB = vh + (size_t)z * Sq * Dd + (size_t)bx * TN_CTA * Dd;
    }

    float acc[4][8][4] = {};
    mainloop(pA, pB, Dd, Dd, Dd >> 6, sb, tid, lane, wm, wn, acc);

    const int rr = lane >> 2;
    const int cc = 2 * (lane & 3);
    const int n_base = bx * TN_CTA + wn * 64;

    if (is_sc) {
        const int m_base = by * TM_CTA + wm * 64;
        float* outp = Sp + (size_t)z * Sq * Sq;
        #pragma unroll
        for (int i = 0; i < 4; i++)
            #pragma unroll
            for (int j = 0; j < 8; j++) {
                const int col = n_base + j * 8 + cc;
                #pragma unroll
                for (int h = 0; h < 2; h++) {
                    const int row = m_base + i * 16 + rr + h * 8;
                    float2 o = make_float2(acc[i][j][2 * h] * scale,
                                           acc[i][j][2 * h + 1] * scale);
                    *(float2*)(outp + (size_t)row * Sq + col) = o;
                }
            }
    } else {
        const int m_base = (by - 16) * TM_CTA + wm * 64;
        __half* outp = vwot + (size_t)z * Dd * Sq;
        #pragma unroll
        for (int i = 0; i < 4; i++)
            #pragma unroll
            for (int j = 0; j < 8; j++) {
                const int col = n_base + j * 8 + cc;
                #pragma unroll
                for (int h = 0; h < 2; h++) {
                    const int row = m_base + i * 16 + rr + h * 8;
                    size_t o = (size_t)row * Sq + col;
                    *(__half2*)(outp + o) = __halves2half2(
                        __float2half_rn(acc[i][j][2 * h]),
                        __float2half_rn(acc[i][j][2 * h + 1]));
                }
            }
    }
}

// ================= PV GEMM: out = P · (V·Wo)^T + bo (fp32) =================
__global__ __launch_bounds__(NTHR, 2)
void gemm_pv(const __half* __restrict__ ph, const __half* __restrict__ vwot,
             const float* __restrict__ bo, float* __restrict__ out)
{
    const int bx = blockIdx.x, z = blockIdx.z;
    const int by = (int)gridDim.y - 1 - (int)blockIdx.y;   // heavy tiles first
    const int nchunk = ((by + 1) * 128) >> 6;              // causal K bound

    extern __shared__ __align__(16) char smem[];
    const uint32_t sb = smem_u32(smem);
    const int tid  = threadIdx.x;
    const int lane = tid & 31;
    const int wid  = tid >> 5;
    const int wm   = wid >> 1;
    const int wn   = wid & 1;

    float acc[4][8][4] = {};
    mainloop(ph + (size_t)z * Sq * Sq + (size_t)by * TM_CTA * Sq,
             vwot + (size_t)z * Dd * Sq + (size_t)bx * TN_CTA * Sq,
             Sq, Sq, nchunk, sb, tid, lane, wm, wn, acc);

    const int m_base = by * TM_CTA + wm * 64;
    const int n_base = bx * TN_CTA + wn * 64;
    const int rr = lane >> 2;
    const int cc = 2 * (lane & 3);
    float* outp = out + (size_t)z * Sq * Dd;

    #pragma unroll
    for (int j = 0; j < 8; j++) {
        const int col = n_base + j * 8 + cc;
        const float b0 = __ldg(&bo[col]);
        const float b1 = __ldg(&bo[col + 1]);
        #pragma unroll
        for (int i = 0; i < 4; i++) {
            #pragma unroll
            for (int h = 0; h < 2; h++) {
                const int row = m_base + i * 16 + rr + h * 8;
                float2 o = make_float2(acc[i][j][2 * h] + b0,
                                       acc[i][j][2 * h + 1] + b1);
                *(float2*)(outp + (size_t)row * Dd + col) = o;
            }
        }
    }
}

// ---------------- launch ----------------
extern "C" void kernel_launch(void* const* d_in, const int* in_sizes, int n_in,
                              void* d_out, int out_size)
{
    const float* x  = (const float*)d_in[0];
    const float* Wq = (const float*)d_in[1];
    const float* bq = (const float*)d_in[2];
    const float* Wk = (const float*)d_in[3];
    const float* bk = (const float*)d_in[4];
    const float* Wv = (const float*)d_in[5];
    const float* bv = (const float*)d_in[6];
    const float* Wo = (const float*)d_in[7];
    const float* bo = (const float*)d_in[8];
    float* out = (float*)d_out;

    __half *xr, *wqt, *wkt, *wvt, *wot, *qh, *kh, *vh, *vwot, *phv;
    float* Sp;
    cudaGetSymbolAddress((void**)&xr,   g_xr);
    cudaGetSymbolAddress((void**)&wqt,  g_wqt);  cudaGetSymbolAddress((void**)&wkt, g_wkt);
    cudaGetSymbolAddress((void**)&wvt,  g_wvt);  cudaGetSymbolAddress((void**)&wot, g_wot);
    cudaGetSymbolAddress((void**)&qh,   g_qh);
    cudaGetSymbolAddress((void**)&kh,   g_kh);
    cudaGetSymbolAddress((void**)&vh,   g_vh);
    cudaGetSymbolAddress((void**)&vwot, g_vwot);
    cudaGetSymbolAddress((void**)&phv,  g_ph);
    cudaGetSymbolAddress((void**)&Sp,   g_S);

    cudaFuncSetAttribute(gemm_qkv,  cudaFuncAttributeMaxDynamicSharedMemorySize, GEMM_SMEM);
    cudaFuncSetAttribute(gemm_scvw, cudaFuncAttributeMaxDynamicSharedMemorySize, GEMM_SMEM);
    cudaFuncSetAttribute(gemm_pv,   cudaFuncAttributeMaxDynamicSharedMemorySize, GEMM_SMEM);

    const float scale = 1.0f / 32.0f;

    // #1: prep — weight transposes (z<4) + x rounding (z==4)
    dim3 tb(32, 8), tgp(Dd / 32, Dd / 32, 5);
    prep_kernel<<<tgp, tb>>>(x, xr, Wq, wqt, Wk, wkt, Wv, wvt, Wo, wot);

    // #2: combined QKV projection
    dim3 gQKV(24, Mm / TM_CTA, 1);
    gemm_qkv<<<gQKV, NTHR, GEMM_SMEM>>>(xr, wqt, wkt, wvt, bq, bk, bv, qh, kh, vh);

    // #3: merged scores + VWo
    dim3 gSV(Sq / TN_CTA, 16 + 8, Bn);            // 16 x 24 x 4
    gemm_scvw<<<gSV, NTHR, GEMM_SMEM>>>(qh, kh, wot, vh, Sp, vwot, scale);

    // #4 (ncu capture slot): float4 + shuffle softmax
    softmax_causal<<<Mm, 256>>>(Sp, phv);

    // #5: out = P·(V·Wo)^T + bo, fp32, K causally bounded
    dim3 gPV(Dd / TN_CTA, Sq / TM_CTA, Bn);       // 8 x 16 x 4
    gemm_pv<<<gPV, NTHR, GEMM_SMEM>>>(phv, vwot, bo, out);
}